// round 1
// baseline (speedup 1.0000x reference)
#include <cuda_runtime.h>

// Problem constants
#define BATCH 16
#define CH    256
#define CQ    32
#define WW    2048

// Scratch (device globals: allocation-free per harness rules)
__device__ float g_q[(size_t)BATCH * CQ * WW];          //  4 MB
__device__ float g_k[(size_t)BATCH * CQ * WW];          //  4 MB
__device__ float g_v[(size_t)BATCH * CH * WW];          // 32 MB
__device__ float g_s[(size_t)BATCH * WW * WW];          // 256 MB

// ---------------------------------------------------------------------------
// Generic register-tiled fp32 GEMM.
//   OPA==0: a(m,k) = A[m*lda + k]      OPA==1: a(m,k) = A[k*lda + m]
//   OPB==0: b(k,n) = B[k*ldb + n]      OPB==1: b(k,n) = B[n*ldb + k]
//   C[m*ldc + n] = sum_k a*b (+ bias[m]) ; EPI: C = gamma[0]*acc + Xres
// Batched via blockIdx.z with strides sA/sB/sC (sC also strides Xres).
// All dims assumed multiples of the tile sizes (true for this problem).
// ---------------------------------------------------------------------------
template<int BM,int BN,int BK,int TM,int TN,int OPA,int OPB,bool BIAS,bool EPI>
__global__ __launch_bounds__((BM/TM)*(BN/TN))
void sgemm_k(const float* __restrict__ A, const float* __restrict__ B,
             const float* __restrict__ bias,
             const float* __restrict__ Xres, const float* __restrict__ gamma,
             float* __restrict__ C,
             int M, int N, int K, int lda, int ldb, int ldc,
             long sA, long sB, long sC)
{
    constexpr int THREADS = (BM/TM) * (BN/TN);
    __shared__ float As[BK][BM + 4];
    __shared__ float Bs[BK][BN + 4];

    const int bz = blockIdx.z;
    A += (long)bz * sA;
    B += (long)bz * sB;
    float* Cb = C + (long)bz * sC;
    const float* Xb = Xres ? (Xres + (long)bz * sC) : nullptr;

    const int m0 = blockIdx.y * BM;
    const int n0 = blockIdx.x * BN;
    const int tid = threadIdx.x;
    const int tx = tid % (BN / TN);
    const int ty = tid / (BN / TN);

    float acc[TM][TN] = {};

    for (int k0 = 0; k0 < K; k0 += BK) {
        // ---- load A tile into As[kk][m] ----
        if constexpr (OPA == 0) {
            #pragma unroll
            for (int idx = tid; idx < BM * BK; idx += THREADS) {
                int m = idx / BK, kk = idx % BK;
                As[kk][m] = A[(long)(m0 + m) * lda + k0 + kk];
            }
        } else {
            #pragma unroll
            for (int idx = tid; idx < BM * BK; idx += THREADS) {
                int kk = idx / BM, m = idx % BM;
                As[kk][m] = A[(long)(k0 + kk) * lda + m0 + m];
            }
        }
        // ---- load B tile into Bs[kk][n] ----
        if constexpr (OPB == 0) {
            #pragma unroll
            for (int idx = tid; idx < BK * BN; idx += THREADS) {
                int kk = idx / BN, n = idx % BN;
                Bs[kk][n] = B[(long)(k0 + kk) * ldb + n0 + n];
            }
        } else {
            #pragma unroll
            for (int idx = tid; idx < BK * BN; idx += THREADS) {
                int n = idx / BK, kk = idx % BK;
                Bs[kk][n] = B[(long)(n0 + n) * ldb + k0 + kk];
            }
        }
        __syncthreads();

        #pragma unroll
        for (int kk = 0; kk < BK; kk++) {
            float ar[TM], br[TN];
            #pragma unroll
            for (int i = 0; i < TM; i += 4) {
                float4 t = *(const float4*)&As[kk][ty * TM + i];
                ar[i] = t.x; ar[i+1] = t.y; ar[i+2] = t.z; ar[i+3] = t.w;
            }
            #pragma unroll
            for (int j = 0; j < TN; j += 4) {
                float4 t = *(const float4*)&Bs[kk][tx * TN + j];
                br[j] = t.x; br[j+1] = t.y; br[j+2] = t.z; br[j+3] = t.w;
            }
            #pragma unroll
            for (int i = 0; i < TM; i++)
                #pragma unroll
                for (int j = 0; j < TN; j++)
                    acc[i][j] += ar[i] * br[j];
        }
        __syncthreads();
    }

    // ---- epilogue ----
    float g = 0.f;
    if constexpr (EPI) g = gamma[0];

    #pragma unroll
    for (int i = 0; i < TM; i++) {
        int m = m0 + ty * TM + i;
        float bb = 0.f;
        if constexpr (BIAS) bb = bias[m];
        #pragma unroll
        for (int j0 = 0; j0 < TN; j0 += 4) {
            int n = n0 + tx * TN + j0;
            long off = (long)m * ldc + n;
            float4 r;
            r.x = acc[i][j0+0] + bb;
            r.y = acc[i][j0+1] + bb;
            r.z = acc[i][j0+2] + bb;
            r.w = acc[i][j0+3] + bb;
            if constexpr (EPI) {
                float4 xv = *(const float4*)&Xb[off];
                r.x = g * r.x + xv.x;
                r.y = g * r.y + xv.y;
                r.z = g * r.z + xv.z;
                r.w = g * r.w + xv.w;
            }
            *(float4*)&Cb[off] = r;
        }
    }
}

// ---------------------------------------------------------------------------
// Row softmax over N=2048, one block of 256 threads per row. In-place.
// ---------------------------------------------------------------------------
__global__ __launch_bounds__(256)
void softmax2048(float* __restrict__ S)
{
    const int N = 2048;
    float* p = S + (size_t)blockIdx.x * N;
    const int tid = threadIdx.x;

    float v[8];
    float m = __int_as_float(0xff800000);  // -inf
    #pragma unroll
    for (int i = 0; i < 8; i++) {
        v[i] = p[tid + 256 * i];
        m = fmaxf(m, v[i]);
    }
    #pragma unroll
    for (int o = 16; o; o >>= 1) m = fmaxf(m, __shfl_xor_sync(0xffffffffu, m, o));

    __shared__ float smax[8];
    __shared__ float ssum[8];
    if ((tid & 31) == 0) smax[tid >> 5] = m;
    __syncthreads();
    float mm = smax[0];
    #pragma unroll
    for (int i = 1; i < 8; i++) mm = fmaxf(mm, smax[i]);

    float s = 0.f;
    #pragma unroll
    for (int i = 0; i < 8; i++) {
        v[i] = __expf(v[i] - mm);
        s += v[i];
    }
    #pragma unroll
    for (int o = 16; o; o >>= 1) s += __shfl_xor_sync(0xffffffffu, s, o);
    if ((tid & 31) == 0) ssum[tid >> 5] = s;
    __syncthreads();
    float tot = 0.f;
    #pragma unroll
    for (int i = 0; i < 8; i++) tot += ssum[i];

    float inv = 1.0f / tot;
    #pragma unroll
    for (int i = 0; i < 8; i++) p[tid + 256 * i] = v[i] * inv;
}

// ---------------------------------------------------------------------------
extern "C" void kernel_launch(void* const* d_in, const int* in_sizes, int n_in,
                              void* d_out, int out_size)
{
    const float* x     = (const float*)d_in[0];
    const float* wq    = (const float*)d_in[1];
    const float* bq    = (const float*)d_in[2];
    const float* wk    = (const float*)d_in[3];
    const float* bk    = (const float*)d_in[4];
    const float* wv    = (const float*)d_in[5];
    const float* bv    = (const float*)d_in[6];
    const float* gamma = (const float*)d_in[7];
    float* out = (float*)d_out;

    float *q, *k, *v, *s;
    cudaGetSymbolAddress((void**)&q, g_q);
    cudaGetSymbolAddress((void**)&k, g_k);
    cudaGetSymbolAddress((void**)&v, g_v);
    cudaGetSymbolAddress((void**)&s, g_s);

    const long xStride = (long)CH * WW;     // per-batch x / v / out stride
    const long qStride = (long)CQ * WW;     // per-batch q / k stride
    const long sStride = (long)WW * WW;     // per-batch scores stride

    // q = wq @ x + bq   [32 x 2048] per batch
    sgemm_k<32,128,16,4,8, 0,0, true,false><<<dim3(WW/128, 1, BATCH), 128>>>(
        wq, x, bq, nullptr, nullptr, q,
        CQ, WW, CH, CH, WW, WW, 0, xStride, qStride);

    // k = wk @ x + bk
    sgemm_k<32,128,16,4,8, 0,0, true,false><<<dim3(WW/128, 1, BATCH), 128>>>(
        wk, x, bk, nullptr, nullptr, k,
        CQ, WW, CH, CH, WW, WW, 0, xStride, qStride);

    // v = wv @ x + bv   [256 x 2048] per batch
    sgemm_k<128,128,16,8,8, 0,0, true,false><<<dim3(WW/128, CH/128, BATCH), 256>>>(
        wv, x, bv, nullptr, nullptr, v,
        CH, WW, CH, CH, WW, WW, 0, xStride, xStride);

    // scores = q^T @ k  [2048 x 2048] per batch  (K = 32)
    sgemm_k<128,128,16,8,8, 1,0, false,false><<<dim3(WW/128, WW/128, BATCH), 256>>>(
        q, k, nullptr, nullptr, nullptr, s,
        WW, WW, CQ, WW, WW, WW, qStride, qStride, sStride);

    // softmax over last dim, in place
    softmax2048<<<BATCH * WW, 256>>>(s);

    // out = gamma * (v @ attn^T) + x   [256 x 2048] per batch  (K = 2048)
    sgemm_k<128,128,16,8,8, 0,1, false,true><<<dim3(WW/128, CH/128, BATCH), 256>>>(
        v, s, nullptr, x, gamma, out,
        CH, WW, WW, WW, WW, WW, xStride, sStride, xStride);
}

// round 3
// speedup vs baseline: 2.0134x; 2.0134x over previous
#include <cuda_runtime.h>
#include <cuda_bf16.h>
#include <cstdint>

// Problem constants
#define BATCH 16
#define CH    256
#define CQ    32
#define WW    2048

// Scratch (device globals: allocation-free per harness rules)
__device__ float g_q[(size_t)BATCH * CQ * WW];                    //  4 MB
__device__ float g_k[(size_t)BATCH * CQ * WW];                    //  4 MB
__device__ float g_v[(size_t)BATCH * CH * WW];                    // 32 MB
__device__ float g_s[(size_t)BATCH * WW * WW];                    // 256 MB
__device__ __nv_bfloat16 g_vh[(size_t)BATCH * CH * WW];           // 16 MB
__device__ __nv_bfloat16 g_vl[(size_t)BATCH * CH * WW];           // 16 MB
__device__ __nv_bfloat16 g_ah[(size_t)BATCH * WW * WW];           // 128 MB
__device__ __nv_bfloat16 g_al[(size_t)BATCH * WW * WW];           // 128 MB

// ---------------------------------------------------------------------------
// mma.sync / ldmatrix helpers (sm_80+ ISA, compiles from compute_100 PTX)
// ---------------------------------------------------------------------------
__device__ __forceinline__ uint32_t smem_u32(const void* p) {
    uint32_t a;
    asm("{ .reg .u64 t; cvta.to.shared.u64 t, %1; cvt.u32.u64 %0, t; }" : "=r"(a) : "l"(p));
    return a;
}

__device__ __forceinline__ void ldsm_x4(uint32_t& r0, uint32_t& r1, uint32_t& r2, uint32_t& r3,
                                        uint32_t addr) {
    asm volatile("ldmatrix.sync.aligned.m8n8.x4.shared.b16 {%0,%1,%2,%3}, [%4];"
                 : "=r"(r0), "=r"(r1), "=r"(r2), "=r"(r3) : "r"(addr));
}

__device__ __forceinline__ void mma_bf16(float* c, const uint32_t* a, const uint32_t* b) {
    asm volatile(
        "mma.sync.aligned.m16n8k16.row.col.f32.bf16.bf16.f32 "
        "{%0,%1,%2,%3}, {%4,%5,%6,%7}, {%8,%9}, {%0,%1,%2,%3};"
        : "+f"(c[0]), "+f"(c[1]), "+f"(c[2]), "+f"(c[3])
        : "r"(a[0]), "r"(a[1]), "r"(a[2]), "r"(a[3]), "r"(b[0]), "r"(b[1]));
}

// ---------------------------------------------------------------------------
// Generic register-tiled fp32 GEMM (q/k/v projections and scores).
// ---------------------------------------------------------------------------
template<int BM,int BN,int BK,int TM,int TN,int OPA,int OPB,bool BIAS>
__global__ __launch_bounds__((BM/TM)*(BN/TN))
void sgemm_k(const float* __restrict__ A, const float* __restrict__ B,
             const float* __restrict__ bias, float* __restrict__ C,
             int M, int N, int K, int lda, int ldb, int ldc,
             long sA, long sB, long sC)
{
    constexpr int THREADS = (BM/TM) * (BN/TN);
    __shared__ float As[BK][BM + 4];
    __shared__ float Bs[BK][BN + 4];

    const int bz = blockIdx.z;
    A += (long)bz * sA;
    B += (long)bz * sB;
    float* Cb = C + (long)bz * sC;

    const int m0 = blockIdx.y * BM;
    const int n0 = blockIdx.x * BN;
    const int tid = threadIdx.x;
    const int tx = tid % (BN / TN);
    const int ty = tid / (BN / TN);

    float acc[TM][TN] = {};

    for (int k0 = 0; k0 < K; k0 += BK) {
        if constexpr (OPA == 0) {
            #pragma unroll
            for (int idx = tid; idx < BM * BK; idx += THREADS) {
                int m = idx / BK, kk = idx % BK;
                As[kk][m] = A[(long)(m0 + m) * lda + k0 + kk];
            }
        } else {
            #pragma unroll
            for (int idx = tid; idx < BM * BK; idx += THREADS) {
                int kk = idx / BM, m = idx % BM;
                As[kk][m] = A[(long)(k0 + kk) * lda + m0 + m];
            }
        }
        if constexpr (OPB == 0) {
            #pragma unroll
            for (int idx = tid; idx < BK * BN; idx += THREADS) {
                int kk = idx / BN, n = idx % BN;
                Bs[kk][n] = B[(long)(k0 + kk) * ldb + n0 + n];
            }
        } else {
            #pragma unroll
            for (int idx = tid; idx < BK * BN; idx += THREADS) {
                int n = idx / BK, kk = idx % BK;
                Bs[kk][n] = B[(long)(n0 + n) * ldb + k0 + kk];
            }
        }
        __syncthreads();

        #pragma unroll
        for (int kk = 0; kk < BK; kk++) {
            float ar[TM], br[TN];
            #pragma unroll
            for (int i = 0; i < TM; i += 4) {
                float4 t = *(const float4*)&As[kk][ty * TM + i];
                ar[i] = t.x; ar[i+1] = t.y; ar[i+2] = t.z; ar[i+3] = t.w;
            }
            #pragma unroll
            for (int j = 0; j < TN; j += 4) {
                float4 t = *(const float4*)&Bs[kk][tx * TN + j];
                br[j] = t.x; br[j+1] = t.y; br[j+2] = t.z; br[j+3] = t.w;
            }
            #pragma unroll
            for (int i = 0; i < TM; i++)
                #pragma unroll
                for (int j = 0; j < TN; j++)
                    acc[i][j] += ar[i] * br[j];
        }
        __syncthreads();
    }

    #pragma unroll
    for (int i = 0; i < TM; i++) {
        int m = m0 + ty * TM + i;
        float bb = 0.f;
        if constexpr (BIAS) bb = bias[m];
        #pragma unroll
        for (int j0 = 0; j0 < TN; j0 += 4) {
            int n = n0 + tx * TN + j0;
            long off = (long)m * ldc + n;
            float4 r;
            r.x = acc[i][j0+0] + bb;
            r.y = acc[i][j0+1] + bb;
            r.z = acc[i][j0+2] + bb;
            r.w = acc[i][j0+3] + bb;
            *(float4*)&Cb[off] = r;
        }
    }
}

// ---------------------------------------------------------------------------
// Split fp32 array into bf16 hi/lo
// ---------------------------------------------------------------------------
__global__ __launch_bounds__(256)
void split_bf16(const float* __restrict__ src, __nv_bfloat16* __restrict__ hi,
                __nv_bfloat16* __restrict__ lo, size_t n4)
{
    size_t i = (size_t)blockIdx.x * blockDim.x + threadIdx.x;
    if (i >= n4) return;
    float4 v = ((const float4*)src)[i];
    __nv_bfloat16 h0 = __float2bfloat16(v.x), h1 = __float2bfloat16(v.y);
    __nv_bfloat16 h2 = __float2bfloat16(v.z), h3 = __float2bfloat16(v.w);
    __nv_bfloat162 H0{h0, h1}, H1{h2, h3};
    __nv_bfloat162 L0{__float2bfloat16(v.x - __bfloat162float(h0)),
                      __float2bfloat16(v.y - __bfloat162float(h1))};
    __nv_bfloat162 L1{__float2bfloat16(v.z - __bfloat162float(h2)),
                      __float2bfloat16(v.w - __bfloat162float(h3))};
    ((__nv_bfloat162*)hi)[2*i]   = H0;
    ((__nv_bfloat162*)hi)[2*i+1] = H1;
    ((__nv_bfloat162*)lo)[2*i]   = L0;
    ((__nv_bfloat162*)lo)[2*i+1] = L1;
}

// ---------------------------------------------------------------------------
// Row softmax over N=2048; emits bf16 hi/lo attn
// ---------------------------------------------------------------------------
__global__ __launch_bounds__(256)
void softmax2048_split(const float* __restrict__ S, __nv_bfloat16* __restrict__ AH,
                       __nv_bfloat16* __restrict__ AL)
{
    const int N = 2048;
    const float* p = S + (size_t)blockIdx.x * N;
    __nv_bfloat16* ph = AH + (size_t)blockIdx.x * N;
    __nv_bfloat16* pl = AL + (size_t)blockIdx.x * N;
    const int tid = threadIdx.x;

    float v[8];
    float m = __int_as_float(0xff800000);
    #pragma unroll
    for (int i = 0; i < 8; i++) {
        v[i] = p[tid + 256 * i];
        m = fmaxf(m, v[i]);
    }
    #pragma unroll
    for (int o = 16; o; o >>= 1) m = fmaxf(m, __shfl_xor_sync(0xffffffffu, m, o));

    __shared__ float smax[8];
    __shared__ float ssum[8];
    if ((tid & 31) == 0) smax[tid >> 5] = m;
    __syncthreads();
    float mm = smax[0];
    #pragma unroll
    for (int i = 1; i < 8; i++) mm = fmaxf(mm, smax[i]);

    float s = 0.f;
    #pragma unroll
    for (int i = 0; i < 8; i++) {
        v[i] = __expf(v[i] - mm);
        s += v[i];
    }
    #pragma unroll
    for (int o = 16; o; o >>= 1) s += __shfl_xor_sync(0xffffffffu, s, o);
    if ((tid & 31) == 0) ssum[tid >> 5] = s;
    __syncthreads();
    float tot = 0.f;
    #pragma unroll
    for (int i = 0; i < 8; i++) tot += ssum[i];

    float inv = 1.0f / tot;
    #pragma unroll
    for (int i = 0; i < 8; i++) {
        float a = v[i] * inv;
        __nv_bfloat16 h = __float2bfloat16(a);
        __nv_bfloat16 l = __float2bfloat16(a - __bfloat162float(h));
        ph[tid + 256 * i] = h;
        pl[tid + 256 * i] = l;
    }
}

// ---------------------------------------------------------------------------
// mma.sync bf16 split-precision GEMM:  out = gamma * (V @ attn^T) + x
// CTA: 128 channels x 128 positions, K=2048 in chunks of 64.
// 8 warps in 2(m) x 4(n) grid; warp tile 64x32 via m16n8k16.
// Terms: Vh*Ah + Vl*Ah + Vh*Al  (Vl*Al ~ 2^-16, dropped)
// ---------------------------------------------------------------------------
#define BKC 64
#define PITCH 72            // bf16 elements per smem row (64 + 8 pad)
#define TILE_ELEMS (128 * PITCH)

__global__ __launch_bounds__(256)
void attn_out_mma(const __nv_bfloat16* __restrict__ VH, const __nv_bfloat16* __restrict__ VL,
                  const __nv_bfloat16* __restrict__ AH, const __nv_bfloat16* __restrict__ AL,
                  const float* __restrict__ X, const float* __restrict__ gamma,
                  float* __restrict__ OUT)
{
    extern __shared__ __nv_bfloat16 sm[];
    __nv_bfloat16* sVH = sm;
    __nv_bfloat16* sVL = sm + TILE_ELEMS;
    __nv_bfloat16* sAH = sm + 2 * TILE_ELEMS;
    __nv_bfloat16* sAL = sm + 3 * TILE_ELEMS;

    const int tid  = threadIdx.x;
    const int wid  = tid >> 5;
    const int lane = tid & 31;
    const int b    = blockIdx.z;
    const int my   = blockIdx.y;           // m half: channels my*128..
    const int n0b  = blockIdx.x * 128;     // position tile base

    const __nv_bfloat16* vh = VH + (size_t)b * CH * WW + (size_t)my * 128 * WW;
    const __nv_bfloat16* vl = VL + (size_t)b * CH * WW + (size_t)my * 128 * WW;
    const __nv_bfloat16* ah = AH + (size_t)b * WW * WW + (size_t)n0b * WW;
    const __nv_bfloat16* al = AL + (size_t)b * WW * WW + (size_t)n0b * WW;
    const float* xb = X   + (size_t)b * CH * WW;
    float* ob       = OUT + (size_t)b * CH * WW;

    const int mw = wid & 1;    // warp m tile (64)
    const int nw = wid >> 1;   // warp n tile (32)

    const uint32_t sVHa = smem_u32(sVH);
    const uint32_t sVLa = smem_u32(sVL);
    const uint32_t sAHa = smem_u32(sAH);
    const uint32_t sALa = smem_u32(sAL);

    float acc[4][4][4] = {};   // [m16 tile][n8 tile][frag]

    const int mi   = lane >> 3;   // ldmatrix matrix index
    const int row8 = lane & 7;

    for (int kc = 0; kc < WW / BKC; kc++) {
        const int k0 = kc * BKC;
        // ---- stage tiles: 4 tiles x 128 rows x 64 bf16, uint4 per 8 elems ----
        #pragma unroll
        for (int i = 0; i < 4; i++) {
            int u = tid + 256 * i;          // 0..1023
            int r = u >> 3, c8 = (u & 7) * 8;
            size_t go = (size_t)r * WW + k0 + c8;
            uint32_t so = r * PITCH + c8;
            *(uint4*)(sVH + so) = *(const uint4*)(vh + go);
            *(uint4*)(sVL + so) = *(const uint4*)(vl + go);
            *(uint4*)(sAH + so) = *(const uint4*)(ah + go);
            *(uint4*)(sAL + so) = *(const uint4*)(al + go);
        }
        __syncthreads();

        #pragma unroll
        for (int kk = 0; kk < 4; kk++) {
            const int ks = kk * 16;
            // B frags (attn hi/lo): 2 x ldmatrix.x4 each, covering n32 x k16
            uint32_t bh[8], bl[8];
            #pragma unroll
            for (int q = 0; q < 2; q++) {
                uint32_t off = (uint32_t)((nw * 32 + q * 16 + (mi >> 1) * 8 + row8) * PITCH
                                          + ks + (mi & 1) * 8) * 2;
                ldsm_x4(bh[q*4+0], bh[q*4+1], bh[q*4+2], bh[q*4+3], sAHa + off);
                ldsm_x4(bl[q*4+0], bl[q*4+1], bl[q*4+2], bl[q*4+3], sALa + off);
            }
            // A frags hi (V hi): 4 x ldmatrix.x4, m16 x k16 each
            uint32_t a[4][4];
            #pragma unroll
            for (int t = 0; t < 4; t++) {
                uint32_t off = (uint32_t)((mw * 64 + t * 16 + (mi & 1) * 8 + row8) * PITCH
                                          + ks + (mi >> 1) * 8) * 2;
                ldsm_x4(a[t][0], a[t][1], a[t][2], a[t][3], sVHa + off);
            }
            // term Vh*Ah and Vh*Al
            #pragma unroll
            for (int t = 0; t < 4; t++)
                #pragma unroll
                for (int g = 0; g < 4; g++) {
                    mma_bf16(acc[t][g], a[t], &bh[g * 2]);
                    mma_bf16(acc[t][g], a[t], &bl[g * 2]);
                }
            // A frags lo (V lo), term Vl*Ah
            #pragma unroll
            for (int t = 0; t < 4; t++) {
                uint32_t off = (uint32_t)((mw * 64 + t * 16 + (mi & 1) * 8 + row8) * PITCH
                                          + ks + (mi >> 1) * 8) * 2;
                ldsm_x4(a[t][0], a[t][1], a[t][2], a[t][3], sVLa + off);
            }
            #pragma unroll
            for (int t = 0; t < 4; t++)
                #pragma unroll
                for (int g = 0; g < 4; g++)
                    mma_bf16(acc[t][g], a[t], &bh[g * 2]);
        }
        __syncthreads();
    }

    // ---- epilogue: out = gamma * acc + x ----
    const float g = gamma[0];
    #pragma unroll
    for (int t = 0; t < 4; t++) {
        const int c0 = my * 128 + mw * 64 + t * 16 + (lane >> 2);
        #pragma unroll
        for (int gg = 0; gg < 4; gg++) {
            const int i0 = n0b + nw * 32 + gg * 8 + (lane & 3) * 2;
            {
                size_t o = (size_t)c0 * WW + i0;
                float2 xv = *(const float2*)(xb + o);
                float2 r;
                r.x = g * acc[t][gg][0] + xv.x;
                r.y = g * acc[t][gg][1] + xv.y;
                *(float2*)(ob + o) = r;
            }
            {
                size_t o = (size_t)(c0 + 8) * WW + i0;
                float2 xv = *(const float2*)(xb + o);
                float2 r;
                r.x = g * acc[t][gg][2] + xv.x;
                r.y = g * acc[t][gg][3] + xv.y;
                *(float2*)(ob + o) = r;
            }
        }
    }
}

// ---------------------------------------------------------------------------
extern "C" void kernel_launch(void* const* d_in, const int* in_sizes, int n_in,
                              void* d_out, int out_size)
{
    const float* x     = (const float*)d_in[0];
    const float* wq    = (const float*)d_in[1];
    const float* bq    = (const float*)d_in[2];
    const float* wk    = (const float*)d_in[3];
    const float* bk    = (const float*)d_in[4];
    const float* wv    = (const float*)d_in[5];
    const float* bv    = (const float*)d_in[6];
    const float* gamma = (const float*)d_in[7];
    float* out = (float*)d_out;

    float *q, *k, *v, *s;
    __nv_bfloat16 *vh, *vl, *ah, *al;
    cudaGetSymbolAddress((void**)&q, g_q);
    cudaGetSymbolAddress((void**)&k, g_k);
    cudaGetSymbolAddress((void**)&v, g_v);
    cudaGetSymbolAddress((void**)&s, g_s);
    cudaGetSymbolAddress((void**)&vh, g_vh);
    cudaGetSymbolAddress((void**)&vl, g_vl);
    cudaGetSymbolAddress((void**)&ah, g_ah);
    cudaGetSymbolAddress((void**)&al, g_al);

    const long xStride = (long)CH * WW;
    const long qStride = (long)CQ * WW;
    const long sStride = (long)WW * WW;

    // q = wq @ x + bq   [32 x 2048] per batch
    sgemm_k<32,128,16,4,8, 0,0, true><<<dim3(WW/128, 1, BATCH), 128>>>(
        wq, x, bq, q, CQ, WW, CH, CH, WW, WW, 0, xStride, qStride);

    // k = wk @ x + bk
    sgemm_k<32,128,16,4,8, 0,0, true><<<dim3(WW/128, 1, BATCH), 128>>>(
        wk, x, bk, k, CQ, WW, CH, CH, WW, WW, 0, xStride, qStride);

    // v = wv @ x + bv   [256 x 2048] per batch
    sgemm_k<128,128,16,8,8, 0,0, true><<<dim3(WW/128, CH/128, BATCH), 256>>>(
        wv, x, bv, v, CH, WW, CH, CH, WW, WW, 0, xStride, xStride);

    // split V -> bf16 hi/lo
    {
        size_t n4 = (size_t)BATCH * CH * WW / 4;
        split_bf16<<<(unsigned)((n4 + 255) / 256), 256>>>(v, vh, vl, n4);
    }

    // scores = q^T @ k  [2048 x 2048] per batch  (K = 32)
    sgemm_k<128,128,16,8,8, 1,0, false><<<dim3(WW/128, WW/128, BATCH), 256>>>(
        q, k, nullptr, s, WW, WW, CQ, WW, WW, WW, qStride, qStride, sStride);

    // softmax + bf16 hi/lo split of attn
    softmax2048_split<<<BATCH * WW, 256>>>(s, ah, al);

    // out = gamma * (V @ attn^T) + x  via mma.sync
    static bool attr_set = false;
    if (!attr_set) {
        cudaFuncSetAttribute(attn_out_mma, cudaFuncAttributeMaxDynamicSharedMemorySize,
                             4 * TILE_ELEMS * (int)sizeof(__nv_bfloat16));
        attr_set = true;
    }
    attn_out_mma<<<dim3(WW/128, CH/128, BATCH), 256, 4 * TILE_ELEMS * sizeof(__nv_bfloat16)>>>(
        vh, vl, ah, al, x, gamma, out);
}

// round 4
// speedup vs baseline: 2.8694x; 1.4251x over previous
#include <cuda_runtime.h>
#include <cuda_bf16.h>
#include <cstdint>

// Problem constants
#define BATCH 16
#define CH    256
#define CQ    32
#define WW    2048

// ---------------------------------------------------------------------------
// Scratch (device globals: allocation-free per harness rules)
// ---------------------------------------------------------------------------
__device__ float g_s[(size_t)BATCH * WW * WW];                    // 256 MB scores fp32
__device__ __nv_bfloat16 g_vh[(size_t)BATCH * CH * WW];           // V hi
__device__ __nv_bfloat16 g_vl[(size_t)BATCH * CH * WW];           // V lo
__device__ __nv_bfloat16 g_ah[(size_t)BATCH * WW * WW];           // attn hi
__device__ __nv_bfloat16 g_al[(size_t)BATCH * WW * WW];           // attn lo
__device__ __nv_bfloat16 g_xth[(size_t)BATCH * WW * CH];          // x^T hi [b][i][c]
__device__ __nv_bfloat16 g_xtl[(size_t)BATCH * WW * CH];          // x^T lo
__device__ __nv_bfloat16 g_qth[(size_t)BATCH * WW * CQ];          // q^T hi [b][i][d]
__device__ __nv_bfloat16 g_qtl[(size_t)BATCH * WW * CQ];
__device__ __nv_bfloat16 g_kth[(size_t)BATCH * WW * CQ];
__device__ __nv_bfloat16 g_ktl[(size_t)BATCH * WW * CQ];
__device__ __nv_bfloat16 g_wqh[CQ * CH], g_wql[CQ * CH];
__device__ __nv_bfloat16 g_wkh[CQ * CH], g_wkl[CQ * CH];
__device__ __nv_bfloat16 g_wvh[CH * CH], g_wvl[CH * CH];

// ---------------------------------------------------------------------------
// Helpers
// ---------------------------------------------------------------------------
__device__ __forceinline__ uint32_t smem_u32(const void* p) {
    uint32_t a;
    asm("{ .reg .u64 t; cvta.to.shared.u64 t, %1; cvt.u32.u64 %0, t; }" : "=r"(a) : "l"(p));
    return a;
}
__device__ __forceinline__ void ldsm_x4(uint32_t& r0, uint32_t& r1, uint32_t& r2, uint32_t& r3,
                                        uint32_t addr) {
    asm volatile("ldmatrix.sync.aligned.m8n8.x4.shared.b16 {%0,%1,%2,%3}, [%4];"
                 : "=r"(r0), "=r"(r1), "=r"(r2), "=r"(r3) : "r"(addr));
}
__device__ __forceinline__ void mma_bf16(float* c, const uint32_t* a, const uint32_t* b) {
    asm volatile(
        "mma.sync.aligned.m16n8k16.row.col.f32.bf16.bf16.f32 "
        "{%0,%1,%2,%3}, {%4,%5,%6,%7}, {%8,%9}, {%0,%1,%2,%3};"
        : "+f"(c[0]), "+f"(c[1]), "+f"(c[2]), "+f"(c[3])
        : "r"(a[0]), "r"(a[1]), "r"(a[2]), "r"(a[3]), "r"(b[0]), "r"(b[1]));
}
__device__ __forceinline__ void cp16(uint32_t dst, const void* src) {
    asm volatile("cp.async.ca.shared.global [%0], [%1], 16;" :: "r"(dst), "l"(src));
}
__device__ __forceinline__ void bsplit(float v, __nv_bfloat16& h, __nv_bfloat16& l) {
    h = __float2bfloat16(v);
    l = __float2bfloat16(v - __bfloat162float(h));
}

// ---------------------------------------------------------------------------
// Tiny: split fp32 -> bf16 hi/lo (weights)
// ---------------------------------------------------------------------------
__global__ __launch_bounds__(256)
void split_flat(const float* __restrict__ s, __nv_bfloat16* __restrict__ h,
                __nv_bfloat16* __restrict__ l)
{
    int i = blockIdx.x * 256 + threadIdx.x;
    __nv_bfloat16 hh, ll;
    bsplit(s[i], hh, ll);
    h[i] = hh; l[i] = ll;
}

// ---------------------------------------------------------------------------
// x [b][c][i] fp32 -> xT hi/lo [b][i][c] bf16 (32x32 smem tiles)
// ---------------------------------------------------------------------------
__global__ __launch_bounds__(256)
void transpose_split_x(const float* __restrict__ X, __nv_bfloat16* __restrict__ XTH,
                       __nv_bfloat16* __restrict__ XTL)
{
    __shared__ float t[32][33];
    const int b = blockIdx.z;
    const int i0 = blockIdx.x * 32, c0 = blockIdx.y * 32;
    const int tx = threadIdx.x & 31, ty = threadIdx.x >> 5;
    const float* xb = X + (size_t)b * CH * WW;
    #pragma unroll
    for (int r = 0; r < 4; r++)
        t[ty + r * 8][tx] = xb[(size_t)(c0 + ty + r * 8) * WW + i0 + tx];
    __syncthreads();
    __nv_bfloat16* oh = XTH + (size_t)b * WW * CH;
    __nv_bfloat16* ol = XTL + (size_t)b * WW * CH;
    #pragma unroll
    for (int r = 0; r < 4; r++) {
        int i = ty + r * 8;
        __nv_bfloat16 h, l;
        bsplit(t[tx][i], h, l);
        oh[(size_t)(i0 + i) * CH + c0 + tx] = h;
        ol[(size_t)(i0 + i) * CH + c0 + tx] = l;
    }
}

// ---------------------------------------------------------------------------
// Q/K projection (mma.sync, 3-term split): qT[b][i][d] = (wq @ x)^T + bq
// CTA: M=32 (d), N=128 (i). blockIdx.y: 0=Q, 1=K.
// ---------------------------------------------------------------------------
__global__ __launch_bounds__(256)
void proj_qk(const __nv_bfloat16* __restrict__ WHQ, const __nv_bfloat16* __restrict__ WLQ,
             const __nv_bfloat16* __restrict__ WHK, const __nv_bfloat16* __restrict__ WLK,
             const float* __restrict__ BQ, const float* __restrict__ BK_,
             const __nv_bfloat16* __restrict__ XTH, const __nv_bfloat16* __restrict__ XTL,
             __nv_bfloat16* __restrict__ QTH, __nv_bfloat16* __restrict__ QTL,
             __nv_bfloat16* __restrict__ KTH, __nv_bfloat16* __restrict__ KTL)
{
    __shared__ __nv_bfloat16 sAh[32][40], sAl[32][40], sBh[128][40], sBl[128][40];
    __shared__ float sc[129][33];
    const int tid = threadIdx.x, wid = tid >> 5, lane = tid & 31;
    const int b = blockIdx.z;
    const int n0 = blockIdx.x * 128;
    const bool isK = blockIdx.y == 1;
    const __nv_bfloat16* wh = isK ? WHK : WHQ;
    const __nv_bfloat16* wl = isK ? WLK : WLQ;
    const float* bias = isK ? BK_ : BQ;
    __nv_bfloat16* OH = (isK ? KTH : QTH) + (size_t)b * WW * CQ;
    __nv_bfloat16* OL = (isK ? KTL : QTL) + (size_t)b * WW * CQ;
    const __nv_bfloat16* xh = XTH + (size_t)b * WW * CH;
    const __nv_bfloat16* xl = XTL + (size_t)b * WW * CH;

    const int mw = wid & 1, nw = wid >> 1;
    const int mi = lane >> 3, row8 = lane & 7;
    const uint32_t aAh = smem_u32(sAh), aAl = smem_u32(sAl);
    const uint32_t aBh = smem_u32(sBh), aBl = smem_u32(sBl);

    float acc[4][4] = {};

    for (int kc = 0; kc < 8; kc++) {
        const int k0 = kc * 32;
        if (tid < 128) {
            int r = tid >> 2, c8 = (tid & 3) * 8;
            *(uint4*)&sAh[r][c8] = *(const uint4*)(wh + (size_t)r * CH + k0 + c8);
            *(uint4*)&sAl[r][c8] = *(const uint4*)(wl + (size_t)r * CH + k0 + c8);
        }
        #pragma unroll
        for (int i2 = 0; i2 < 2; i2++) {
            int u = tid + 256 * i2;
            int r = u >> 2, c8 = (u & 3) * 8;
            *(uint4*)&sBh[r][c8] = *(const uint4*)(xh + (size_t)(n0 + r) * CH + k0 + c8);
            *(uint4*)&sBl[r][c8] = *(const uint4*)(xl + (size_t)(n0 + r) * CH + k0 + c8);
        }
        __syncthreads();
        #pragma unroll
        for (int kk = 0; kk < 2; kk++) {
            const int ks = kk * 16;
            uint32_t bh[8], bl[8];
            #pragma unroll
            for (int q = 0; q < 2; q++) {
                uint32_t off = (uint32_t)((nw * 32 + q * 16 + (mi >> 1) * 8 + row8) * 40
                                          + ks + (mi & 1) * 8) * 2;
                ldsm_x4(bh[q*4+0], bh[q*4+1], bh[q*4+2], bh[q*4+3], aBh + off);
                ldsm_x4(bl[q*4+0], bl[q*4+1], bl[q*4+2], bl[q*4+3], aBl + off);
            }
            uint32_t a4[4];
            const uint32_t offA = (uint32_t)((mw * 16 + (mi & 1) * 8 + row8) * 40
                                             + ks + (mi >> 1) * 8) * 2;
            ldsm_x4(a4[0], a4[1], a4[2], a4[3], aAh + offA);
            #pragma unroll
            for (int g = 0; g < 4; g++) {
                mma_bf16(acc[g], a4, &bh[g * 2]);
                mma_bf16(acc[g], a4, &bl[g * 2]);
            }
            ldsm_x4(a4[0], a4[1], a4[2], a4[3], aAl + offA);
            #pragma unroll
            for (int g = 0; g < 4; g++)
                mma_bf16(acc[g], a4, &bh[g * 2]);
        }
        __syncthreads();
    }
    // transpose via smem bounce (+bias), then split & write qT rows
    const int m = mw * 16 + (lane >> 2);
    #pragma unroll
    for (int g = 0; g < 4; g++) {
        int n = nw * 32 + g * 8 + (lane & 3) * 2;
        sc[n][m]       = acc[g][0] + bias[m];
        sc[n + 1][m]   = acc[g][1] + bias[m];
        sc[n][m + 8]   = acc[g][2] + bias[m + 8];
        sc[n + 1][m + 8] = acc[g][3] + bias[m + 8];
    }
    __syncthreads();
    const int n = tid >> 1, half = (tid & 1) * 16;
    #pragma unroll
    for (int j = 0; j < 16; j++) {
        __nv_bfloat16 h, l;
        bsplit(sc[n][half + j], h, l);
        OH[(size_t)(n0 + n) * CQ + half + j] = h;
        OL[(size_t)(n0 + n) * CQ + half + j] = l;
    }
}

// ---------------------------------------------------------------------------
// V projection (mma.sync, 3-term split): vh/vl[b][o][i] = wv @ x + bv
// CTA: M=128 (o half via blockIdx.y), N=128 (i).
// ---------------------------------------------------------------------------
__global__ __launch_bounds__(256)
void proj_v(const __nv_bfloat16* __restrict__ WVH, const __nv_bfloat16* __restrict__ WVL,
            const float* __restrict__ BV,
            const __nv_bfloat16* __restrict__ XTH, const __nv_bfloat16* __restrict__ XTL,
            __nv_bfloat16* __restrict__ VH, __nv_bfloat16* __restrict__ VL)
{
    __shared__ __nv_bfloat16 sAh[128][40], sAl[128][40], sBh[128][40], sBl[128][40];
    const int tid = threadIdx.x, wid = tid >> 5, lane = tid & 31;
    const int b = blockIdx.z, my = blockIdx.y;
    const int n0 = blockIdx.x * 128;
    const __nv_bfloat16* xh = XTH + (size_t)b * WW * CH;
    const __nv_bfloat16* xl = XTL + (size_t)b * WW * CH;
    __nv_bfloat16* vh = VH + (size_t)b * CH * WW;
    __nv_bfloat16* vl = VL + (size_t)b * CH * WW;
    const int mw = wid & 1, nw = wid >> 1, mi = lane >> 3, row8 = lane & 7;
    const uint32_t aAh = smem_u32(sAh), aAl = smem_u32(sAl);
    const uint32_t aBh = smem_u32(sBh), aBl = smem_u32(sBl);

    float acc[4][4][4] = {};

    for (int kc = 0; kc < 8; kc++) {
        const int k0 = kc * 32;
        #pragma unroll
        for (int i2 = 0; i2 < 2; i2++) {
            int u = tid + 256 * i2;
            int r = u >> 2, c8 = (u & 3) * 8;
            *(uint4*)&sAh[r][c8] = *(const uint4*)(WVH + (size_t)(my * 128 + r) * CH + k0 + c8);
            *(uint4*)&sAl[r][c8] = *(const uint4*)(WVL + (size_t)(my * 128 + r) * CH + k0 + c8);
            *(uint4*)&sBh[r][c8] = *(const uint4*)(xh + (size_t)(n0 + r) * CH + k0 + c8);
            *(uint4*)&sBl[r][c8] = *(const uint4*)(xl + (size_t)(n0 + r) * CH + k0 + c8);
        }
        __syncthreads();
        #pragma unroll
        for (int kk = 0; kk < 2; kk++) {
            const int ks = kk * 16;
            uint32_t bh[8], bl[8];
            #pragma unroll
            for (int q = 0; q < 2; q++) {
                uint32_t off = (uint32_t)((nw * 32 + q * 16 + (mi >> 1) * 8 + row8) * 40
                                          + ks + (mi & 1) * 8) * 2;
                ldsm_x4(bh[q*4+0], bh[q*4+1], bh[q*4+2], bh[q*4+3], aBh + off);
                ldsm_x4(bl[q*4+0], bl[q*4+1], bl[q*4+2], bl[q*4+3], aBl + off);
            }
            uint32_t a[4][4];
            #pragma unroll
            for (int t = 0; t < 4; t++) {
                uint32_t off = (uint32_t)((mw * 64 + t * 16 + (mi & 1) * 8 + row8) * 40
                                          + ks + (mi >> 1) * 8) * 2;
                ldsm_x4(a[t][0], a[t][1], a[t][2], a[t][3], aAh + off);
            }
            #pragma unroll
            for (int t = 0; t < 4; t++)
                #pragma unroll
                for (int g = 0; g < 4; g++) {
                    mma_bf16(acc[t][g], a[t], &bh[g * 2]);
                    mma_bf16(acc[t][g], a[t], &bl[g * 2]);
                }
            #pragma unroll
            for (int t = 0; t < 4; t++) {
                uint32_t off = (uint32_t)((mw * 64 + t * 16 + (mi & 1) * 8 + row8) * 40
                                          + ks + (mi >> 1) * 8) * 2;
                ldsm_x4(a[t][0], a[t][1], a[t][2], a[t][3], aAl + off);
            }
            #pragma unroll
            for (int t = 0; t < 4; t++)
                #pragma unroll
                for (int g = 0; g < 4; g++)
                    mma_bf16(acc[t][g], a[t], &bh[g * 2]);
        }
        __syncthreads();
    }
    // epilogue: + bias, split hi/lo, write [o][i]
    #pragma unroll
    for (int t = 0; t < 4; t++) {
        const int o = my * 128 + mw * 64 + t * 16 + (lane >> 2);
        const float b0 = BV[o], b8 = BV[o + 8];
        #pragma unroll
        for (int g = 0; g < 4; g++) {
            const int n = n0 + nw * 32 + g * 8 + (lane & 3) * 2;
            __nv_bfloat16 h0, l0, h1, l1;
            bsplit(acc[t][g][0] + b0, h0, l0);
            bsplit(acc[t][g][1] + b0, h1, l1);
            *(__nv_bfloat162*)&vh[(size_t)o * WW + n] = __nv_bfloat162{h0, h1};
            *(__nv_bfloat162*)&vl[(size_t)o * WW + n] = __nv_bfloat162{l0, l1};
            bsplit(acc[t][g][2] + b8, h0, l0);
            bsplit(acc[t][g][3] + b8, h1, l1);
            *(__nv_bfloat162*)&vh[(size_t)(o + 8) * WW + n] = __nv_bfloat162{h0, h1};
            *(__nv_bfloat162*)&vl[(size_t)(o + 8) * WW + n] = __nv_bfloat162{l0, l1};
        }
    }
}

// ---------------------------------------------------------------------------
// Scores (mma.sync, 3-term split): s[b][i][j] = sum_d qT[i][d] kT[j][d]
// CTA: 128 (i) x 128 (j). K = 32, single chunk.
// ---------------------------------------------------------------------------
__global__ __launch_bounds__(256)
void scores_mma(const __nv_bfloat16* __restrict__ QTH, const __nv_bfloat16* __restrict__ QTL,
                const __nv_bfloat16* __restrict__ KTH, const __nv_bfloat16* __restrict__ KTL,
                float* __restrict__ S)
{
    __shared__ __nv_bfloat16 sQh[128][40], sQl[128][40], sKh[128][40], sKl[128][40];
    const int tid = threadIdx.x, wid = tid >> 5, lane = tid & 31;
    const int b = blockIdx.z;
    const int i0 = blockIdx.y * 128, j0 = blockIdx.x * 128;
    const __nv_bfloat16* qh = QTH + (size_t)b * WW * CQ;
    const __nv_bfloat16* ql = QTL + (size_t)b * WW * CQ;
    const __nv_bfloat16* kh = KTH + (size_t)b * WW * CQ;
    const __nv_bfloat16* kl = KTL + (size_t)b * WW * CQ;
    float* s = S + (size_t)b * WW * WW;
    const int mw = wid & 1, nw = wid >> 1, mi = lane >> 3, row8 = lane & 7;
    const uint32_t aQh = smem_u32(sQh), aQl = smem_u32(sQl);
    const uint32_t aKh = smem_u32(sKh), aKl = smem_u32(sKl);

    #pragma unroll
    for (int i2 = 0; i2 < 2; i2++) {
        int u = tid + 256 * i2;
        int r = u >> 2, c8 = (u & 3) * 8;
        *(uint4*)&sQh[r][c8] = *(const uint4*)(qh + (size_t)(i0 + r) * CQ + c8);
        *(uint4*)&sQl[r][c8] = *(const uint4*)(ql + (size_t)(i0 + r) * CQ + c8);
        *(uint4*)&sKh[r][c8] = *(const uint4*)(kh + (size_t)(j0 + r) * CQ + c8);
        *(uint4*)&sKl[r][c8] = *(const uint4*)(kl + (size_t)(j0 + r) * CQ + c8);
    }
    __syncthreads();

    float acc[4][4][4] = {};
    #pragma unroll
    for (int kk = 0; kk < 2; kk++) {
        const int ks = kk * 16;
        uint32_t bh[8], bl[8];
        #pragma unroll
        for (int q = 0; q < 2; q++) {
            uint32_t off = (uint32_t)((nw * 32 + q * 16 + (mi >> 1) * 8 + row8) * 40
                                      + ks + (mi & 1) * 8) * 2;
            ldsm_x4(bh[q*4+0], bh[q*4+1], bh[q*4+2], bh[q*4+3], aKh + off);
            ldsm_x4(bl[q*4+0], bl[q*4+1], bl[q*4+2], bl[q*4+3], aKl + off);
        }
        uint32_t a[4][4];
        #pragma unroll
        for (int t = 0; t < 4; t++) {
            uint32_t off = (uint32_t)((mw * 64 + t * 16 + (mi & 1) * 8 + row8) * 40
                                      + ks + (mi >> 1) * 8) * 2;
            ldsm_x4(a[t][0], a[t][1], a[t][2], a[t][3], aQh + off);
        }
        #pragma unroll
        for (int t = 0; t < 4; t++)
            #pragma unroll
            for (int g = 0; g < 4; g++) {
                mma_bf16(acc[t][g], a[t], &bh[g * 2]);
                mma_bf16(acc[t][g], a[t], &bl[g * 2]);
            }
        #pragma unroll
        for (int t = 0; t < 4; t++) {
            uint32_t off = (uint32_t)((mw * 64 + t * 16 + (mi & 1) * 8 + row8) * 40
                                      + ks + (mi >> 1) * 8) * 2;
            ldsm_x4(a[t][0], a[t][1], a[t][2], a[t][3], aQl + off);
        }
        #pragma unroll
        for (int t = 0; t < 4; t++)
            #pragma unroll
            for (int g = 0; g < 4; g++)
                mma_bf16(acc[t][g], a[t], &bh[g * 2]);
    }

    #pragma unroll
    for (int t = 0; t < 4; t++) {
        const int i = i0 + mw * 64 + t * 16 + (lane >> 2);
        #pragma unroll
        for (int g = 0; g < 4; g++) {
            const int j = j0 + nw * 32 + g * 8 + (lane & 3) * 2;
            *(float2*)&s[(size_t)i * WW + j] = float2{acc[t][g][0], acc[t][g][1]};
            *(float2*)&s[(size_t)(i + 8) * WW + j] = float2{acc[t][g][2], acc[t][g][3]};
        }
    }
}

// ---------------------------------------------------------------------------
// Row softmax over N=2048; emits bf16 hi/lo attn
// ---------------------------------------------------------------------------
__global__ __launch_bounds__(256)
void softmax2048_split(const float* __restrict__ S, __nv_bfloat16* __restrict__ AH,
                       __nv_bfloat16* __restrict__ AL)
{
    const int N = 2048;
    const float* p = S + (size_t)blockIdx.x * N;
    __nv_bfloat16* ph = AH + (size_t)blockIdx.x * N;
    __nv_bfloat16* pl = AL + (size_t)blockIdx.x * N;
    const int tid = threadIdx.x;

    float v[8];
    float m = __int_as_float(0xff800000);
    #pragma unroll
    for (int i = 0; i < 8; i++) {
        v[i] = p[tid + 256 * i];
        m = fmaxf(m, v[i]);
    }
    #pragma unroll
    for (int o = 16; o; o >>= 1) m = fmaxf(m, __shfl_xor_sync(0xffffffffu, m, o));

    __shared__ float smax[8];
    __shared__ float ssum[8];
    if ((tid & 31) == 0) smax[tid >> 5] = m;
    __syncthreads();
    float mm = smax[0];
    #pragma unroll
    for (int i = 1; i < 8; i++) mm = fmaxf(mm, smax[i]);

    float s = 0.f;
    #pragma unroll
    for (int i = 0; i < 8; i++) {
        v[i] = __expf(v[i] - mm);
        s += v[i];
    }
    #pragma unroll
    for (int o = 16; o; o >>= 1) s += __shfl_xor_sync(0xffffffffu, s, o);
    if ((tid & 31) == 0) ssum[tid >> 5] = s;
    __syncthreads();
    float tot = 0.f;
    #pragma unroll
    for (int i = 0; i < 8; i++) tot += ssum[i];

    float inv = 1.0f / tot;
    #pragma unroll
    for (int i = 0; i < 8; i++) {
        float a = v[i] * inv;
        __nv_bfloat16 h, l;
        bsplit(a, h, l);
        ph[tid + 256 * i] = h;
        pl[tid + 256 * i] = l;
    }
}

// ---------------------------------------------------------------------------
// out = gamma * (V @ attn^T) + x via mma.sync, cp.async double-buffered.
// CTA: 128 channels x 128 positions, K=2048 in chunks of 64, 2 stages.
// ---------------------------------------------------------------------------
#define OPITCH 72
#define OTILE_B (128 * OPITCH * 2)      // 18432 bytes per tile
#define OSTAGE_B (4 * OTILE_B)          // 73728 bytes per stage
#define OSMEM (2 * OSTAGE_B)            // 147456 bytes total

__global__ __launch_bounds__(256)
void attn_out_mma(const __nv_bfloat16* __restrict__ VH, const __nv_bfloat16* __restrict__ VL,
                  const __nv_bfloat16* __restrict__ AH, const __nv_bfloat16* __restrict__ AL,
                  const float* __restrict__ X, const float* __restrict__ gamma,
                  float* __restrict__ OUT)
{
    extern __shared__ char smem[];
    const uint32_t sbase = smem_u32(smem);
    const int tid = threadIdx.x, wid = tid >> 5, lane = tid & 31;
    const int b = blockIdx.z, my = blockIdx.y, n0b = blockIdx.x * 128;

    const __nv_bfloat16* vh = VH + (size_t)b * CH * WW + (size_t)my * 128 * WW;
    const __nv_bfloat16* vl = VL + (size_t)b * CH * WW + (size_t)my * 128 * WW;
    const __nv_bfloat16* ah = AH + (size_t)b * WW * WW + (size_t)n0b * WW;
    const __nv_bfloat16* al = AL + (size_t)b * WW * WW + (size_t)n0b * WW;
    const float* xb = X + (size_t)b * CH * WW;
    float* ob = OUT + (size_t)b * CH * WW;

    const int mw = wid & 1, nw = wid >> 1, mi = lane >> 3, row8 = lane & 7;

    float acc[4][4][4] = {};

    auto stage = [&](int kc, int s) {
        const int k0 = kc * 64;
        const uint32_t sb = sbase + s * OSTAGE_B;
        #pragma unroll
        for (int i2 = 0; i2 < 4; i2++) {
            int u = tid + 256 * i2;
            int r = u >> 3, c8 = (u & 7) * 8;
            size_t go = (size_t)r * WW + k0 + c8;
            uint32_t so = (uint32_t)(r * OPITCH + c8) * 2;
            cp16(sb + so, vh + go);
            cp16(sb + OTILE_B + so, vl + go);
            cp16(sb + 2 * OTILE_B + so, ah + go);
            cp16(sb + 3 * OTILE_B + so, al + go);
        }
    };

    stage(0, 0);
    asm volatile("cp.async.commit_group;");

    for (int kc = 0; kc < 32; kc++) {
        const int s = kc & 1;
        if (kc < 31) {
            stage(kc + 1, s ^ 1);
            asm volatile("cp.async.commit_group;");
            asm volatile("cp.async.wait_group 1;");
        } else {
            asm volatile("cp.async.wait_group 0;");
        }
        __syncthreads();

        const uint32_t aVH = sbase + s * OSTAGE_B;
        const uint32_t aVL = aVH + OTILE_B;
        const uint32_t aAH = aVH + 2 * OTILE_B;
        const uint32_t aAL = aVH + 3 * OTILE_B;

        #pragma unroll
        for (int kk = 0; kk < 4; kk++) {
            const int ks = kk * 16;
            uint32_t bh[8], bl[8];
            #pragma unroll
            for (int q = 0; q < 2; q++) {
                uint32_t off = (uint32_t)((nw * 32 + q * 16 + (mi >> 1) * 8 + row8) * OPITCH
                                          + ks + (mi & 1) * 8) * 2;
                ldsm_x4(bh[q*4+0], bh[q*4+1], bh[q*4+2], bh[q*4+3], aAH + off);
                ldsm_x4(bl[q*4+0], bl[q*4+1], bl[q*4+2], bl[q*4+3], aAL + off);
            }
            uint32_t a[4][4];
            #pragma unroll
            for (int t = 0; t < 4; t++) {
                uint32_t off = (uint32_t)((mw * 64 + t * 16 + (mi & 1) * 8 + row8) * OPITCH
                                          + ks + (mi >> 1) * 8) * 2;
                ldsm_x4(a[t][0], a[t][1], a[t][2], a[t][3], aVH + off);
            }
            #pragma unroll
            for (int t = 0; t < 4; t++)
                #pragma unroll
                for (int g = 0; g < 4; g++) {
                    mma_bf16(acc[t][g], a[t], &bh[g * 2]);
                    mma_bf16(acc[t][g], a[t], &bl[g * 2]);
                }
            #pragma unroll
            for (int t = 0; t < 4; t++) {
                uint32_t off = (uint32_t)((mw * 64 + t * 16 + (mi & 1) * 8 + row8) * OPITCH
                                          + ks + (mi >> 1) * 8) * 2;
                ldsm_x4(a[t][0], a[t][1], a[t][2], a[t][3], aVL + off);
            }
            #pragma unroll
            for (int t = 0; t < 4; t++)
                #pragma unroll
                for (int g = 0; g < 4; g++)
                    mma_bf16(acc[t][g], a[t], &bh[g * 2]);
        }
        __syncthreads();
    }

    // epilogue: out = gamma * acc + x
    const float g = gamma[0];
    #pragma unroll
    for (int t = 0; t < 4; t++) {
        const int c0 = my * 128 + mw * 64 + t * 16 + (lane >> 2);
        #pragma unroll
        for (int gg = 0; gg < 4; gg++) {
            const int i0 = n0b + nw * 32 + gg * 8 + (lane & 3) * 2;
            {
                size_t o = (size_t)c0 * WW + i0;
                float2 xv = *(const float2*)(xb + o);
                float2 r;
                r.x = g * acc[t][gg][0] + xv.x;
                r.y = g * acc[t][gg][1] + xv.y;
                *(float2*)(ob + o) = r;
            }
            {
                size_t o = (size_t)(c0 + 8) * WW + i0;
                float2 xv = *(const float2*)(xb + o);
                float2 r;
                r.x = g * acc[t][gg][2] + xv.x;
                r.y = g * acc[t][gg][3] + xv.y;
                *(float2*)(ob + o) = r;
            }
        }
    }
}

// ---------------------------------------------------------------------------
extern "C" void kernel_launch(void* const* d_in, const int* in_sizes, int n_in,
                              void* d_out, int out_size)
{
    const float* x     = (const float*)d_in[0];
    const float* wq    = (const float*)d_in[1];
    const float* bq    = (const float*)d_in[2];
    const float* wk    = (const float*)d_in[3];
    const float* bk    = (const float*)d_in[4];
    const float* wv    = (const float*)d_in[5];
    const float* bv    = (const float*)d_in[6];
    const float* gamma = (const float*)d_in[7];
    float* out = (float*)d_out;

    float* s;
    __nv_bfloat16 *vh, *vl, *ah, *al, *xth, *xtl, *qth, *qtl, *kth, *ktl;
    __nv_bfloat16 *wqh, *wql, *wkh, *wkl, *wvh, *wvl;
    cudaGetSymbolAddress((void**)&s, g_s);
    cudaGetSymbolAddress((void**)&vh, g_vh);
    cudaGetSymbolAddress((void**)&vl, g_vl);
    cudaGetSymbolAddress((void**)&ah, g_ah);
    cudaGetSymbolAddress((void**)&al, g_al);
    cudaGetSymbolAddress((void**)&xth, g_xth);
    cudaGetSymbolAddress((void**)&xtl, g_xtl);
    cudaGetSymbolAddress((void**)&qth, g_qth);
    cudaGetSymbolAddress((void**)&qtl, g_qtl);
    cudaGetSymbolAddress((void**)&kth, g_kth);
    cudaGetSymbolAddress((void**)&ktl, g_ktl);
    cudaGetSymbolAddress((void**)&wqh, g_wqh);
    cudaGetSymbolAddress((void**)&wql, g_wql);
    cudaGetSymbolAddress((void**)&wkh, g_wkh);
    cudaGetSymbolAddress((void**)&wkl, g_wkl);
    cudaGetSymbolAddress((void**)&wvh, g_wvh);
    cudaGetSymbolAddress((void**)&wvl, g_wvl);

    // 1. split weights
    split_flat<<<CQ * CH / 256, 256>>>(wq, wqh, wql);
    split_flat<<<CQ * CH / 256, 256>>>(wk, wkh, wkl);
    split_flat<<<CH * CH / 256, 256>>>(wv, wvh, wvl);

    // 2. transpose + split x
    transpose_split_x<<<dim3(WW / 32, CH / 32, BATCH), 256>>>(x, xth, xtl);

    // 3. q/k projections (transposed output)
    proj_qk<<<dim3(WW / 128, 2, BATCH), 256>>>(wqh, wql, wkh, wkl, bq, bk,
                                               xth, xtl, qth, qtl, kth, ktl);

    // 4. v projection (emits bf16 hi/lo directly)
    proj_v<<<dim3(WW / 128, CH / 128, BATCH), 256>>>(wvh, wvl, bv, xth, xtl, vh, vl);

    // 5. scores
    scores_mma<<<dim3(WW / 128, WW / 128, BATCH), 256>>>(qth, qtl, kth, ktl, s);

    // 6. softmax + split
    softmax2048_split<<<BATCH * WW, 256>>>(s, ah, al);

    // 7. out = gamma * (V @ attn^T) + x
    cudaFuncSetAttribute(attn_out_mma, cudaFuncAttributeMaxDynamicSharedMemorySize, OSMEM);
    attn_out_mma<<<dim3(WW / 128, CH / 128, BATCH), 256, OSMEM>>>(
        vh, vl, ah, al, x, gamma, out);
}

// round 5
// speedup vs baseline: 2.9670x; 1.0340x over previous
#include <cuda_runtime.h>
#include <cuda_bf16.h>
#include <cstdint>

// Problem constants
#define BATCH 16
#define CH    256
#define CQ    32
#define WW    2048

// ---------------------------------------------------------------------------
// Scratch (device globals: allocation-free per harness rules)
// ---------------------------------------------------------------------------
__device__ __nv_bfloat16 g_vh[(size_t)BATCH * CH * WW];           // V hi [b][c][j]
__device__ __nv_bfloat16 g_vl[(size_t)BATCH * CH * WW];           // V lo
__device__ __nv_bfloat16 g_xth[(size_t)BATCH * WW * CH];          // x^T hi [b][i][c]
__device__ __nv_bfloat16 g_xtl[(size_t)BATCH * WW * CH];          // x^T lo
__device__ __nv_bfloat16 g_qth[(size_t)BATCH * WW * CQ];          // q^T hi [b][i][d]
__device__ __nv_bfloat16 g_qtl[(size_t)BATCH * WW * CQ];
__device__ __nv_bfloat16 g_kth[(size_t)BATCH * WW * CQ];
__device__ __nv_bfloat16 g_ktl[(size_t)BATCH * WW * CQ];
__device__ __nv_bfloat16 g_wqh[CQ * CH], g_wql[CQ * CH];
__device__ __nv_bfloat16 g_wkh[CQ * CH], g_wkl[CQ * CH];
__device__ __nv_bfloat16 g_wvh[CH * CH], g_wvl[CH * CH];

// ---------------------------------------------------------------------------
// Helpers
// ---------------------------------------------------------------------------
__device__ __forceinline__ uint32_t smem_u32(const void* p) {
    uint32_t a;
    asm("{ .reg .u64 t; cvta.to.shared.u64 t, %1; cvt.u32.u64 %0, t; }" : "=r"(a) : "l"(p));
    return a;
}
__device__ __forceinline__ void ldsm_x4(uint32_t& r0, uint32_t& r1, uint32_t& r2, uint32_t& r3,
                                        uint32_t addr) {
    asm volatile("ldmatrix.sync.aligned.m8n8.x4.shared.b16 {%0,%1,%2,%3}, [%4];"
                 : "=r"(r0), "=r"(r1), "=r"(r2), "=r"(r3) : "r"(addr));
}
__device__ __forceinline__ void mma_bf16(float* c, const uint32_t* a, const uint32_t* b) {
    asm volatile(
        "mma.sync.aligned.m16n8k16.row.col.f32.bf16.bf16.f32 "
        "{%0,%1,%2,%3}, {%4,%5,%6,%7}, {%8,%9}, {%0,%1,%2,%3};"
        : "+f"(c[0]), "+f"(c[1]), "+f"(c[2]), "+f"(c[3])
        : "r"(a[0]), "r"(a[1]), "r"(a[2]), "r"(a[3]), "r"(b[0]), "r"(b[1]));
}
__device__ __forceinline__ void cp16(uint32_t dst, const void* src) {
    asm volatile("cp.async.ca.shared.global [%0], [%1], 16;" :: "r"(dst), "l"(src));
}
__device__ __forceinline__ void bsplit(float v, __nv_bfloat16& h, __nv_bfloat16& l) {
    h = __float2bfloat16(v);
    l = __float2bfloat16(v - __bfloat162float(h));
}
__device__ __forceinline__ uint32_t packbf2(float x, float y) {
    __nv_bfloat162 t = __floats2bfloat162_rn(x, y);
    return *(uint32_t*)&t;
}

// ---------------------------------------------------------------------------
// Split fp32 -> bf16 hi/lo (weights)
// ---------------------------------------------------------------------------
__global__ __launch_bounds__(256)
void split_flat(const float* __restrict__ s, __nv_bfloat16* __restrict__ h,
                __nv_bfloat16* __restrict__ l)
{
    int i = blockIdx.x * 256 + threadIdx.x;
    __nv_bfloat16 hh, ll;
    bsplit(s[i], hh, ll);
    h[i] = hh; l[i] = ll;
}

// ---------------------------------------------------------------------------
// x [b][c][i] fp32 -> xT hi/lo [b][i][c] bf16 (32x32 smem tiles)
// ---------------------------------------------------------------------------
__global__ __launch_bounds__(256)
void transpose_split_x(const float* __restrict__ X, __nv_bfloat16* __restrict__ XTH,
                       __nv_bfloat16* __restrict__ XTL)
{
    __shared__ float t[32][33];
    const int b = blockIdx.z;
    const int i0 = blockIdx.x * 32, c0 = blockIdx.y * 32;
    const int tx = threadIdx.x & 31, ty = threadIdx.x >> 5;
    const float* xb = X + (size_t)b * CH * WW;
    #pragma unroll
    for (int r = 0; r < 4; r++)
        t[ty + r * 8][tx] = xb[(size_t)(c0 + ty + r * 8) * WW + i0 + tx];
    __syncthreads();
    __nv_bfloat16* oh = XTH + (size_t)b * WW * CH;
    __nv_bfloat16* ol = XTL + (size_t)b * WW * CH;
    #pragma unroll
    for (int r = 0; r < 4; r++) {
        int i = ty + r * 8;
        __nv_bfloat16 h, l;
        bsplit(t[tx][i], h, l);
        oh[(size_t)(i0 + i) * CH + c0 + tx] = h;
        ol[(size_t)(i0 + i) * CH + c0 + tx] = l;
    }
}

// ---------------------------------------------------------------------------
// Q/K projection (mma.sync, 3-term split): qT[b][i][d] = (wq @ x)^T + bq
// ---------------------------------------------------------------------------
__global__ __launch_bounds__(256)
void proj_qk(const __nv_bfloat16* __restrict__ WHQ, const __nv_bfloat16* __restrict__ WLQ,
             const __nv_bfloat16* __restrict__ WHK, const __nv_bfloat16* __restrict__ WLK,
             const float* __restrict__ BQ, const float* __restrict__ BK_,
             const __nv_bfloat16* __restrict__ XTH, const __nv_bfloat16* __restrict__ XTL,
             __nv_bfloat16* __restrict__ QTH, __nv_bfloat16* __restrict__ QTL,
             __nv_bfloat16* __restrict__ KTH, __nv_bfloat16* __restrict__ KTL)
{
    __shared__ __nv_bfloat16 sAh[32][40], sAl[32][40], sBh[128][40], sBl[128][40];
    __shared__ float sc[129][33];
    const int tid = threadIdx.x, wid = tid >> 5, lane = tid & 31;
    const int b = blockIdx.z;
    const int n0 = blockIdx.x * 128;
    const bool isK = blockIdx.y == 1;
    const __nv_bfloat16* wh = isK ? WHK : WHQ;
    const __nv_bfloat16* wl = isK ? WLK : WLQ;
    const float* bias = isK ? BK_ : BQ;
    __nv_bfloat16* OH = (isK ? KTH : QTH) + (size_t)b * WW * CQ;
    __nv_bfloat16* OL = (isK ? KTL : QTL) + (size_t)b * WW * CQ;
    const __nv_bfloat16* xh = XTH + (size_t)b * WW * CH;
    const __nv_bfloat16* xl = XTL + (size_t)b * WW * CH;

    const int mw = wid & 1, nw = wid >> 1;
    const int mi = lane >> 3, row8 = lane & 7;
    const uint32_t aAh = smem_u32(sAh), aAl = smem_u32(sAl);
    const uint32_t aBh = smem_u32(sBh), aBl = smem_u32(sBl);

    float acc[4][4] = {};

    for (int kc = 0; kc < 8; kc++) {
        const int k0 = kc * 32;
        if (tid < 128) {
            int r = tid >> 2, c8 = (tid & 3) * 8;
            *(uint4*)&sAh[r][c8] = *(const uint4*)(wh + (size_t)r * CH + k0 + c8);
            *(uint4*)&sAl[r][c8] = *(const uint4*)(wl + (size_t)r * CH + k0 + c8);
        }
        #pragma unroll
        for (int i2 = 0; i2 < 2; i2++) {
            int u = tid + 256 * i2;
            int r = u >> 2, c8 = (u & 3) * 8;
            *(uint4*)&sBh[r][c8] = *(const uint4*)(xh + (size_t)(n0 + r) * CH + k0 + c8);
            *(uint4*)&sBl[r][c8] = *(const uint4*)(xl + (size_t)(n0 + r) * CH + k0 + c8);
        }
        __syncthreads();
        #pragma unroll
        for (int kk = 0; kk < 2; kk++) {
            const int ks = kk * 16;
            uint32_t bh[8], bl[8];
            #pragma unroll
            for (int q = 0; q < 2; q++) {
                uint32_t off = (uint32_t)((nw * 32 + q * 16 + (mi >> 1) * 8 + row8) * 40
                                          + ks + (mi & 1) * 8) * 2;
                ldsm_x4(bh[q*4+0], bh[q*4+1], bh[q*4+2], bh[q*4+3], aBh + off);
                ldsm_x4(bl[q*4+0], bl[q*4+1], bl[q*4+2], bl[q*4+3], aBl + off);
            }
            uint32_t a4[4];
            const uint32_t offA = (uint32_t)((mw * 16 + (mi & 1) * 8 + row8) * 40
                                             + ks + (mi >> 1) * 8) * 2;
            ldsm_x4(a4[0], a4[1], a4[2], a4[3], aAh + offA);
            #pragma unroll
            for (int g = 0; g < 4; g++) {
                mma_bf16(acc[g], a4, &bh[g * 2]);
                mma_bf16(acc[g], a4, &bl[g * 2]);
            }
            ldsm_x4(a4[0], a4[1], a4[2], a4[3], aAl + offA);
            #pragma unroll
            for (int g = 0; g < 4; g++)
                mma_bf16(acc[g], a4, &bh[g * 2]);
        }
        __syncthreads();
    }
    const int m = mw * 16 + (lane >> 2);
    #pragma unroll
    for (int g = 0; g < 4; g++) {
        int n = nw * 32 + g * 8 + (lane & 3) * 2;
        sc[n][m]         = acc[g][0] + bias[m];
        sc[n + 1][m]     = acc[g][1] + bias[m];
        sc[n][m + 8]     = acc[g][2] + bias[m + 8];
        sc[n + 1][m + 8] = acc[g][3] + bias[m + 8];
    }
    __syncthreads();
    const int n = tid >> 1, half = (tid & 1) * 16;
    #pragma unroll
    for (int j = 0; j < 16; j++) {
        __nv_bfloat16 h, l;
        bsplit(sc[n][half + j], h, l);
        OH[(size_t)(n0 + n) * CQ + half + j] = h;
        OL[(size_t)(n0 + n) * CQ + half + j] = l;
    }
}

// ---------------------------------------------------------------------------
// V projection (mma.sync, 3-term split): vh/vl[b][o][i] = wv @ x + bv
// ---------------------------------------------------------------------------
__global__ __launch_bounds__(256)
void proj_v(const __nv_bfloat16* __restrict__ WVH, const __nv_bfloat16* __restrict__ WVL,
            const float* __restrict__ BV,
            const __nv_bfloat16* __restrict__ XTH, const __nv_bfloat16* __restrict__ XTL,
            __nv_bfloat16* __restrict__ VH, __nv_bfloat16* __restrict__ VL)
{
    __shared__ __nv_bfloat16 sAh[128][40], sAl[128][40], sBh[128][40], sBl[128][40];
    const int tid = threadIdx.x, wid = tid >> 5, lane = tid & 31;
    const int b = blockIdx.z, my = blockIdx.y;
    const int n0 = blockIdx.x * 128;
    const __nv_bfloat16* xh = XTH + (size_t)b * WW * CH;
    const __nv_bfloat16* xl = XTL + (size_t)b * WW * CH;
    __nv_bfloat16* vh = VH + (size_t)b * CH * WW;
    __nv_bfloat16* vl = VL + (size_t)b * CH * WW;
    const int mw = wid & 1, nw = wid >> 1, mi = lane >> 3, row8 = lane & 7;
    const uint32_t aAh = smem_u32(sAh), aAl = smem_u32(sAl);
    const uint32_t aBh = smem_u32(sBh), aBl = smem_u32(sBl);

    float acc[4][4][4] = {};

    for (int kc = 0; kc < 8; kc++) {
        const int k0 = kc * 32;
        #pragma unroll
        for (int i2 = 0; i2 < 2; i2++) {
            int u = tid + 256 * i2;
            int r = u >> 2, c8 = (u & 3) * 8;
            *(uint4*)&sAh[r][c8] = *(const uint4*)(WVH + (size_t)(my * 128 + r) * CH + k0 + c8);
            *(uint4*)&sAl[r][c8] = *(const uint4*)(WVL + (size_t)(my * 128 + r) * CH + k0 + c8);
            *(uint4*)&sBh[r][c8] = *(const uint4*)(xh + (size_t)(n0 + r) * CH + k0 + c8);
            *(uint4*)&sBl[r][c8] = *(const uint4*)(xl + (size_t)(n0 + r) * CH + k0 + c8);
        }
        __syncthreads();
        #pragma unroll
        for (int kk = 0; kk < 2; kk++) {
            const int ks = kk * 16;
            uint32_t bh[8], bl[8];
            #pragma unroll
            for (int q = 0; q < 2; q++) {
                uint32_t off = (uint32_t)((nw * 32 + q * 16 + (mi >> 1) * 8 + row8) * 40
                                          + ks + (mi & 1) * 8) * 2;
                ldsm_x4(bh[q*4+0], bh[q*4+1], bh[q*4+2], bh[q*4+3], aBh + off);
                ldsm_x4(bl[q*4+0], bl[q*4+1], bl[q*4+2], bl[q*4+3], aBl + off);
            }
            uint32_t a[4][4];
            #pragma unroll
            for (int t = 0; t < 4; t++) {
                uint32_t off = (uint32_t)((mw * 64 + t * 16 + (mi & 1) * 8 + row8) * 40
                                          + ks + (mi >> 1) * 8) * 2;
                ldsm_x4(a[t][0], a[t][1], a[t][2], a[t][3], aAh + off);
            }
            #pragma unroll
            for (int t = 0; t < 4; t++)
                #pragma unroll
                for (int g = 0; g < 4; g++) {
                    mma_bf16(acc[t][g], a[t], &bh[g * 2]);
                    mma_bf16(acc[t][g], a[t], &bl[g * 2]);
                }
            #pragma unroll
            for (int t = 0; t < 4; t++) {
                uint32_t off = (uint32_t)((mw * 64 + t * 16 + (mi & 1) * 8 + row8) * 40
                                          + ks + (mi >> 1) * 8) * 2;
                ldsm_x4(a[t][0], a[t][1], a[t][2], a[t][3], aAl + off);
            }
            #pragma unroll
            for (int t = 0; t < 4; t++)
                #pragma unroll
                for (int g = 0; g < 4; g++)
                    mma_bf16(acc[t][g], a[t], &bh[g * 2]);
        }
        __syncthreads();
    }
    #pragma unroll
    for (int t = 0; t < 4; t++) {
        const int o = my * 128 + mw * 64 + t * 16 + (lane >> 2);
        const float b0 = BV[o], b8 = BV[o + 8];
        #pragma unroll
        for (int g = 0; g < 4; g++) {
            const int n = n0 + nw * 32 + g * 8 + (lane & 3) * 2;
            __nv_bfloat16 h0, l0, h1, l1;
            bsplit(acc[t][g][0] + b0, h0, l0);
            bsplit(acc[t][g][1] + b0, h1, l1);
            *(__nv_bfloat162*)&vh[(size_t)o * WW + n] = __nv_bfloat162{h0, h1};
            *(__nv_bfloat162*)&vl[(size_t)o * WW + n] = __nv_bfloat162{l0, l1};
            bsplit(acc[t][g][2] + b8, h0, l0);
            bsplit(acc[t][g][3] + b8, h1, l1);
            *(__nv_bfloat162*)&vh[(size_t)(o + 8) * WW + n] = __nv_bfloat162{h0, h1};
            *(__nv_bfloat162*)&vl[(size_t)(o + 8) * WW + n] = __nv_bfloat162{l0, l1};
        }
    }
}

// ---------------------------------------------------------------------------
// Fused flash attention: scores + softmax + PV + gamma/residual epilogue.
// CTA = (i-tile 128, channel-half 128, batch). 8 warps; warp owns 16 i-rows.
// K loop over 16 j-tiles of 128, cp.async double-buffered K^T and V tiles.
// ---------------------------------------------------------------------------
#define F_KL    10240
#define F_V     20480
#define F_VL    34816
#define F_STAGE 90112
#define F_Q     180224
#define F_QL    10240
#define F_SMEM  200704

__global__ __launch_bounds__(256, 1)
void fused_attn(const __nv_bfloat16* __restrict__ QTH, const __nv_bfloat16* __restrict__ QTL,
                const __nv_bfloat16* __restrict__ KTH, const __nv_bfloat16* __restrict__ KTL,
                const __nv_bfloat16* __restrict__ VH, const __nv_bfloat16* __restrict__ VL,
                const float* __restrict__ X, const float* __restrict__ gamma,
                float* __restrict__ OUT)
{
    extern __shared__ char smem[];
    const uint32_t sbase = smem_u32(smem);
    const int tid = threadIdx.x, wid = tid >> 5, lane = tid & 31;
    const int mi = lane >> 3, row8 = lane & 7;
    const int i0 = blockIdx.x * 128;
    const int c0 = blockIdx.y * 128;
    const int b  = blockIdx.z;

    const __nv_bfloat16* qhg = QTH + (size_t)b * WW * CQ;
    const __nv_bfloat16* qlg = QTL + (size_t)b * WW * CQ;
    const __nv_bfloat16* khg = KTH + (size_t)b * WW * CQ;
    const __nv_bfloat16* klg = KTL + (size_t)b * WW * CQ;
    const __nv_bfloat16* vhg = VH + (size_t)b * CH * WW + (size_t)c0 * WW;
    const __nv_bfloat16* vlg = VL + (size_t)b * CH * WW + (size_t)c0 * WW;
    const float* xb = X + (size_t)b * CH * WW;
    float* ob = OUT + (size_t)b * CH * WW;

    auto stage = [&](int jt, int st) {
        const int j0 = jt * 128;
        const uint32_t sb = sbase + st * F_STAGE;
        #pragma unroll
        for (int it = 0; it < 2; it++) {
            int u = tid + 256 * it;              // 0..511
            int r = u >> 2, c8 = (u & 3) * 8;
            size_t go = (size_t)(j0 + r) * CQ + c8;
            uint32_t so = (uint32_t)(r * 40 + c8) * 2;
            cp16(sb + so, khg + go);
            cp16(sb + F_KL + so, klg + go);
        }
        #pragma unroll
        for (int it = 0; it < 8; it++) {
            int u = tid + 256 * it;              // 0..2047
            int r = u >> 4, c8 = (u & 15) * 8;
            size_t go = (size_t)r * WW + j0 + c8;
            uint32_t so = (uint32_t)(r * 136 + c8) * 2;
            cp16(sb + F_V + so, vhg + go);
            cp16(sb + F_V + F_VL + so, vlg + go);
        }
    };

    stage(0, 0);
    asm volatile("cp.async.commit_group;");

    // load q tile (plain stores)
    #pragma unroll
    for (int it = 0; it < 2; it++) {
        int u = tid + 256 * it;
        int r = u >> 2, c8 = (u & 3) * 8;
        uint32_t so = (uint32_t)(r * 40 + c8) * 2;
        *(uint4*)(smem + F_Q + so) = *(const uint4*)(qhg + (size_t)(i0 + r) * CQ + c8);
        *(uint4*)(smem + F_Q + F_QL + so) = *(const uint4*)(qlg + (size_t)(i0 + r) * CQ + c8);
    }
    __syncthreads();

    // preload q fragments (loop-invariant): rows wid*16..+15, k=0..31
    uint32_t qah[8], qal[8];
    #pragma unroll
    for (int kk = 0; kk < 2; kk++) {
        uint32_t off = (uint32_t)((wid * 16 + (mi & 1) * 8 + row8) * 40
                                  + kk * 16 + (mi >> 1) * 8) * 2;
        ldsm_x4(qah[kk*4+0], qah[kk*4+1], qah[kk*4+2], qah[kk*4+3], sbase + F_Q + off);
        ldsm_x4(qal[kk*4+0], qal[kk*4+1], qal[kk*4+2], qal[kk*4+3], sbase + F_Q + F_QL + off);
    }

    float s_[16][4];
    float o_[16][4] = {};
    float m0 = -1e30f, m1 = -1e30f, l0 = 0.f, l1 = 0.f;

    for (int jt = 0; jt < 16; jt++) {
        const int st = jt & 1;
        if (jt < 15) {
            stage(jt + 1, st ^ 1);
            asm volatile("cp.async.commit_group;");
            asm volatile("cp.async.wait_group 1;");
        } else {
            asm volatile("cp.async.wait_group 0;");
        }
        __syncthreads();

        // ---- scores: S = q k^T (3-term split), warp rows = wid*16..+15 ----
        #pragma unroll
        for (int nt = 0; nt < 16; nt++)
            #pragma unroll
            for (int v = 0; v < 4; v++) s_[nt][v] = 0.f;

        const uint32_t aK = sbase + st * F_STAGE;
        #pragma unroll
        for (int kk = 0; kk < 2; kk++) {
            #pragma unroll
            for (int ntp = 0; ntp < 8; ntp++) {
                uint32_t off = (uint32_t)((ntp * 16 + (mi >> 1) * 8 + row8) * 40
                                          + kk * 16 + (mi & 1) * 8) * 2;
                uint32_t bh[4], bl[4];
                ldsm_x4(bh[0], bh[1], bh[2], bh[3], aK + off);
                ldsm_x4(bl[0], bl[1], bl[2], bl[3], aK + F_KL + off);
                mma_bf16(s_[2*ntp],   &qah[kk*4], &bh[0]);
                mma_bf16(s_[2*ntp+1], &qah[kk*4], &bh[2]);
                mma_bf16(s_[2*ntp],   &qal[kk*4], &bh[0]);
                mma_bf16(s_[2*ntp+1], &qal[kk*4], &bh[2]);
                mma_bf16(s_[2*ntp],   &qah[kk*4], &bl[0]);
                mma_bf16(s_[2*ntp+1], &qah[kk*4], &bl[2]);
            }
        }

        // ---- online softmax (rows rA = lane>>2, rB = rA+8 within warp tile) ----
        float ml0 = -1e30f, ml1 = -1e30f;
        #pragma unroll
        for (int nt = 0; nt < 16; nt++) {
            ml0 = fmaxf(ml0, fmaxf(s_[nt][0], s_[nt][1]));
            ml1 = fmaxf(ml1, fmaxf(s_[nt][2], s_[nt][3]));
        }
        ml0 = fmaxf(ml0, __shfl_xor_sync(0xffffffffu, ml0, 1));
        ml0 = fmaxf(ml0, __shfl_xor_sync(0xffffffffu, ml0, 2));
        ml1 = fmaxf(ml1, __shfl_xor_sync(0xffffffffu, ml1, 1));
        ml1 = fmaxf(ml1, __shfl_xor_sync(0xffffffffu, ml1, 2));
        const float mn0 = fmaxf(m0, ml0), mn1 = fmaxf(m1, ml1);
        const float sc0 = __expf(m0 - mn0), sc1 = __expf(m1 - mn1);
        m0 = mn0; m1 = mn1;

        float ls0 = 0.f, ls1 = 0.f;
        #pragma unroll
        for (int nt = 0; nt < 16; nt++) {
            s_[nt][0] = __expf(s_[nt][0] - m0);
            s_[nt][1] = __expf(s_[nt][1] - m0);
            s_[nt][2] = __expf(s_[nt][2] - m1);
            s_[nt][3] = __expf(s_[nt][3] - m1);
            ls0 += s_[nt][0] + s_[nt][1];
            ls1 += s_[nt][2] + s_[nt][3];
        }
        l0 = l0 * sc0 + ls0;
        l1 = l1 * sc1 + ls1;
        #pragma unroll
        for (int nt = 0; nt < 16; nt++) {
            o_[nt][0] *= sc0;  o_[nt][1] *= sc0;
            o_[nt][2] *= sc1;  o_[nt][3] *= sc1;
        }

        // ---- PV: O += Ph Vh + Pl Vh + Ph Vl ----
        const uint32_t aV = sbase + st * F_STAGE + F_V;
        #pragma unroll
        for (int ks = 0; ks < 8; ks++) {
            // build P A-fragments (C->A identity), hi/lo
            uint32_t pah[4], pal[4];
            #pragma unroll
            for (int t = 0; t < 2; t++) {
                const float p0 = s_[2*ks+t][0], p1 = s_[2*ks+t][1];
                const float p2 = s_[2*ks+t][2], p3 = s_[2*ks+t][3];
                uint32_t h01 = packbf2(p0, p1);
                uint32_t h23 = packbf2(p2, p3);
                __nv_bfloat162 hb01 = *(__nv_bfloat162*)&h01;
                __nv_bfloat162 hb23 = *(__nv_bfloat162*)&h23;
                pah[2*t]   = h01;
                pah[2*t+1] = h23;
                pal[2*t]   = packbf2(p0 - __bfloat162float(hb01.x),
                                     p1 - __bfloat162float(hb01.y));
                pal[2*t+1] = packbf2(p2 - __bfloat162float(hb23.x),
                                     p3 - __bfloat162float(hb23.y));
            }
            #pragma unroll
            for (int ntp = 0; ntp < 8; ntp++) {
                uint32_t off = (uint32_t)((ntp * 16 + (mi >> 1) * 8 + row8) * 136
                                          + ks * 16 + (mi & 1) * 8) * 2;
                uint32_t bh[4], bl[4];
                ldsm_x4(bh[0], bh[1], bh[2], bh[3], aV + off);
                ldsm_x4(bl[0], bl[1], bl[2], bl[3], aV + F_VL + off);
                mma_bf16(o_[2*ntp],   pah, &bh[0]);
                mma_bf16(o_[2*ntp+1], pah, &bh[2]);
                mma_bf16(o_[2*ntp],   pal, &bh[0]);
                mma_bf16(o_[2*ntp+1], pal, &bh[2]);
                mma_bf16(o_[2*ntp],   pah, &bl[0]);
                mma_bf16(o_[2*ntp+1], pah, &bl[2]);
            }
        }
        __syncthreads();
    }

    // ---- epilogue: normalize, bounce through smem to [c][i], +gamma/x ----
    l0 += __shfl_xor_sync(0xffffffffu, l0, 1);
    l0 += __shfl_xor_sync(0xffffffffu, l0, 2);
    l1 += __shfl_xor_sync(0xffffffffu, l1, 1);
    l1 += __shfl_xor_sync(0xffffffffu, l1, 2);
    const float inv0 = 1.f / l0, inv1 = 1.f / l1;

    float* sO = (float*)smem;            // [c 128][i 128] pitch 132
    const int rA = wid * 16 + (lane >> 2), rB = rA + 8;
    #pragma unroll
    for (int nt = 0; nt < 16; nt++) {
        const int c = nt * 8 + (lane & 3) * 2;
        sO[c * 132 + rA]       = o_[nt][0] * inv0;
        sO[(c + 1) * 132 + rA] = o_[nt][1] * inv0;
        sO[c * 132 + rB]       = o_[nt][2] * inv1;
        sO[(c + 1) * 132 + rB] = o_[nt][3] * inv1;
    }
    __syncthreads();

    const float g = gamma[0];
    #pragma unroll
    for (int it = 0; it < 16; it++) {
        int u = tid + 256 * it;               // 0..4095
        int r = u >> 5, c4 = (u & 31) * 4;
        float4 v4 = *(float4*)&sO[r * 132 + c4];
        size_t go = (size_t)(c0 + r) * WW + i0 + c4;
        float4 xv = *(const float4*)(xb + go);
        v4.x = g * v4.x + xv.x;
        v4.y = g * v4.y + xv.y;
        v4.z = g * v4.z + xv.z;
        v4.w = g * v4.w + xv.w;
        *(float4*)(ob + go) = v4;
    }
}

// ---------------------------------------------------------------------------
extern "C" void kernel_launch(void* const* d_in, const int* in_sizes, int n_in,
                              void* d_out, int out_size)
{
    const float* x     = (const float*)d_in[0];
    const float* wq    = (const float*)d_in[1];
    const float* bq    = (const float*)d_in[2];
    const float* wk    = (const float*)d_in[3];
    const float* bk    = (const float*)d_in[4];
    const float* wv    = (const float*)d_in[5];
    const float* bv    = (const float*)d_in[6];
    const float* gamma = (const float*)d_in[7];
    float* out = (float*)d_out;

    __nv_bfloat16 *vh, *vl, *xth, *xtl, *qth, *qtl, *kth, *ktl;
    __nv_bfloat16 *wqh, *wql, *wkh, *wkl, *wvh, *wvl;
    cudaGetSymbolAddress((void**)&vh, g_vh);
    cudaGetSymbolAddress((void**)&vl, g_vl);
    cudaGetSymbolAddress((void**)&xth, g_xth);
    cudaGetSymbolAddress((void**)&xtl, g_xtl);
    cudaGetSymbolAddress((void**)&qth, g_qth);
    cudaGetSymbolAddress((void**)&qtl, g_qtl);
    cudaGetSymbolAddress((void**)&kth, g_kth);
    cudaGetSymbolAddress((void**)&ktl, g_ktl);
    cudaGetSymbolAddress((void**)&wqh, g_wqh);
    cudaGetSymbolAddress((void**)&wql, g_wql);
    cudaGetSymbolAddress((void**)&wkh, g_wkh);
    cudaGetSymbolAddress((void**)&wkl, g_wkl);
    cudaGetSymbolAddress((void**)&wvh, g_wvh);
    cudaGetSymbolAddress((void**)&wvl, g_wvl);

    // 1. split weights
    split_flat<<<CQ * CH / 256, 256>>>(wq, wqh, wql);
    split_flat<<<CQ * CH / 256, 256>>>(wk, wkh, wkl);
    split_flat<<<CH * CH / 256, 256>>>(wv, wvh, wvl);

    // 2. transpose + split x
    transpose_split_x<<<dim3(WW / 32, CH / 32, BATCH), 256>>>(x, xth, xtl);

    // 3. q/k projections (transposed output)
    proj_qk<<<dim3(WW / 128, 2, BATCH), 256>>>(wqh, wql, wkh, wkl, bq, bk,
                                               xth, xtl, qth, qtl, kth, ktl);

    // 4. v projection
    proj_v<<<dim3(WW / 128, CH / 128, BATCH), 256>>>(wvh, wvl, bv, xth, xtl, vh, vl);

    // 5. fused attention
    cudaFuncSetAttribute(fused_attn, cudaFuncAttributeMaxDynamicSharedMemorySize, F_SMEM);
    fused_attn<<<dim3(WW / 128, CH / 128, BATCH), 256, F_SMEM>>>(
        qth, qtl, kth, ktl, vh, vl, x, gamma, out);
}

// round 6
// speedup vs baseline: 2.9743x; 1.0024x over previous
#include <cuda_runtime.h>
#include <cuda_bf16.h>
#include <cstdint>

// Problem constants
#define BATCH 16
#define CH    256
#define CQ    32
#define WW    2048

#define LOG2E 1.4426950408889634f

// ---------------------------------------------------------------------------
// Scratch (device globals: allocation-free per harness rules)
// ---------------------------------------------------------------------------
__device__ __nv_bfloat16 g_vh[(size_t)BATCH * CH * WW];           // V hi [b][c][j]
__device__ __nv_bfloat16 g_vl[(size_t)BATCH * CH * WW];           // V lo
__device__ __nv_bfloat16 g_xth[(size_t)BATCH * WW * CH];          // x^T hi [b][i][c]
__device__ __nv_bfloat16 g_xtl[(size_t)BATCH * WW * CH];          // x^T lo
__device__ __nv_bfloat16 g_qth[(size_t)BATCH * WW * CQ];          // q^T hi [b][i][d] (pre-scaled by log2e)
__device__ __nv_bfloat16 g_qtl[(size_t)BATCH * WW * CQ];
__device__ __nv_bfloat16 g_kth[(size_t)BATCH * WW * CQ];
__device__ __nv_bfloat16 g_ktl[(size_t)BATCH * WW * CQ];
__device__ __nv_bfloat16 g_wqh[CQ * CH], g_wql[CQ * CH];
__device__ __nv_bfloat16 g_wkh[CQ * CH], g_wkl[CQ * CH];
__device__ __nv_bfloat16 g_wvh[CH * CH], g_wvl[CH * CH];

// ---------------------------------------------------------------------------
// Helpers
// ---------------------------------------------------------------------------
__device__ __forceinline__ uint32_t smem_u32(const void* p) {
    uint32_t a;
    asm("{ .reg .u64 t; cvta.to.shared.u64 t, %1; cvt.u32.u64 %0, t; }" : "=r"(a) : "l"(p));
    return a;
}
__device__ __forceinline__ void ldsm_x4(uint32_t& r0, uint32_t& r1, uint32_t& r2, uint32_t& r3,
                                        uint32_t addr) {
    asm volatile("ldmatrix.sync.aligned.m8n8.x4.shared.b16 {%0,%1,%2,%3}, [%4];"
                 : "=r"(r0), "=r"(r1), "=r"(r2), "=r"(r3) : "r"(addr));
}
__device__ __forceinline__ void mma_bf16(float* c, const uint32_t* a, const uint32_t* b) {
    asm volatile(
        "mma.sync.aligned.m16n8k16.row.col.f32.bf16.bf16.f32 "
        "{%0,%1,%2,%3}, {%4,%5,%6,%7}, {%8,%9}, {%0,%1,%2,%3};"
        : "+f"(c[0]), "+f"(c[1]), "+f"(c[2]), "+f"(c[3])
        : "r"(a[0]), "r"(a[1]), "r"(a[2]), "r"(a[3]), "r"(b[0]), "r"(b[1]));
}
__device__ __forceinline__ void cp16(uint32_t dst, const void* src) {
    asm volatile("cp.async.ca.shared.global [%0], [%1], 16;" :: "r"(dst), "l"(src));
}
__device__ __forceinline__ void bsplit(float v, __nv_bfloat16& h, __nv_bfloat16& l) {
    h = __float2bfloat16(v);
    l = __float2bfloat16(v - __bfloat162float(h));
}
__device__ __forceinline__ uint32_t packbf2(float x, float y) {
    __nv_bfloat162 t = __floats2bfloat162_rn(x, y);
    return *(uint32_t*)&t;
}

// ---------------------------------------------------------------------------
// Split fp32 -> bf16 hi/lo (weights)
// ---------------------------------------------------------------------------
__global__ __launch_bounds__(256)
void split_flat(const float* __restrict__ s, __nv_bfloat16* __restrict__ h,
                __nv_bfloat16* __restrict__ l)
{
    int i = blockIdx.x * 256 + threadIdx.x;
    __nv_bfloat16 hh, ll;
    bsplit(s[i], hh, ll);
    h[i] = hh; l[i] = ll;
}

// ---------------------------------------------------------------------------
// x [b][c][i] fp32 -> xT hi/lo [b][i][c] bf16 (32x32 smem tiles)
// ---------------------------------------------------------------------------
__global__ __launch_bounds__(256)
void transpose_split_x(const float* __restrict__ X, __nv_bfloat16* __restrict__ XTH,
                       __nv_bfloat16* __restrict__ XTL)
{
    __shared__ float t[32][33];
    const int b = blockIdx.z;
    const int i0 = blockIdx.x * 32, c0 = blockIdx.y * 32;
    const int tx = threadIdx.x & 31, ty = threadIdx.x >> 5;
    const float* xb = X + (size_t)b * CH * WW;
    #pragma unroll
    for (int r = 0; r < 4; r++)
        t[ty + r * 8][tx] = xb[(size_t)(c0 + ty + r * 8) * WW + i0 + tx];
    __syncthreads();
    __nv_bfloat16* oh = XTH + (size_t)b * WW * CH;
    __nv_bfloat16* ol = XTL + (size_t)b * WW * CH;
    #pragma unroll
    for (int r = 0; r < 4; r++) {
        int i = ty + r * 8;
        __nv_bfloat16 h, l;
        bsplit(t[tx][i], h, l);
        oh[(size_t)(i0 + i) * CH + c0 + tx] = h;
        ol[(size_t)(i0 + i) * CH + c0 + tx] = l;
    }
}

// ---------------------------------------------------------------------------
// Q/K projection (mma.sync, 3-term split): qT[b][i][d] = (wq @ x)^T + bq
// Q output is pre-scaled by log2e (softmax uses exp2).
// ---------------------------------------------------------------------------
__global__ __launch_bounds__(256)
void proj_qk(const __nv_bfloat16* __restrict__ WHQ, const __nv_bfloat16* __restrict__ WLQ,
             const __nv_bfloat16* __restrict__ WHK, const __nv_bfloat16* __restrict__ WLK,
             const float* __restrict__ BQ, const float* __restrict__ BK_,
             const __nv_bfloat16* __restrict__ XTH, const __nv_bfloat16* __restrict__ XTL,
             __nv_bfloat16* __restrict__ QTH, __nv_bfloat16* __restrict__ QTL,
             __nv_bfloat16* __restrict__ KTH, __nv_bfloat16* __restrict__ KTL)
{
    __shared__ __nv_bfloat16 sAh[32][40], sAl[32][40], sBh[128][40], sBl[128][40];
    __shared__ float sc[129][33];
    const int tid = threadIdx.x, wid = tid >> 5, lane = tid & 31;
    const int b = blockIdx.z;
    const int n0 = blockIdx.x * 128;
    const bool isK = blockIdx.y == 1;
    const __nv_bfloat16* wh = isK ? WHK : WHQ;
    const __nv_bfloat16* wl = isK ? WLK : WLQ;
    const float* bias = isK ? BK_ : BQ;
    const float oscale = isK ? 1.0f : LOG2E;
    __nv_bfloat16* OH = (isK ? KTH : QTH) + (size_t)b * WW * CQ;
    __nv_bfloat16* OL = (isK ? KTL : QTL) + (size_t)b * WW * CQ;
    const __nv_bfloat16* xh = XTH + (size_t)b * WW * CH;
    const __nv_bfloat16* xl = XTL + (size_t)b * WW * CH;

    const int mw = wid & 1, nw = wid >> 1;
    const int mi = lane >> 3, row8 = lane & 7;
    const uint32_t aAh = smem_u32(sAh), aAl = smem_u32(sAl);
    const uint32_t aBh = smem_u32(sBh), aBl = smem_u32(sBl);

    float acc[4][4] = {};

    for (int kc = 0; kc < 8; kc++) {
        const int k0 = kc * 32;
        if (tid < 128) {
            int r = tid >> 2, c8 = (tid & 3) * 8;
            *(uint4*)&sAh[r][c8] = *(const uint4*)(wh + (size_t)r * CH + k0 + c8);
            *(uint4*)&sAl[r][c8] = *(const uint4*)(wl + (size_t)r * CH + k0 + c8);
        }
        #pragma unroll
        for (int i2 = 0; i2 < 2; i2++) {
            int u = tid + 256 * i2;
            int r = u >> 2, c8 = (u & 3) * 8;
            *(uint4*)&sBh[r][c8] = *(const uint4*)(xh + (size_t)(n0 + r) * CH + k0 + c8);
            *(uint4*)&sBl[r][c8] = *(const uint4*)(xl + (size_t)(n0 + r) * CH + k0 + c8);
        }
        __syncthreads();
        #pragma unroll
        for (int kk = 0; kk < 2; kk++) {
            const int ks = kk * 16;
            uint32_t bh[8], bl[8];
            #pragma unroll
            for (int q = 0; q < 2; q++) {
                uint32_t off = (uint32_t)((nw * 32 + q * 16 + (mi >> 1) * 8 + row8) * 40
                                          + ks + (mi & 1) * 8) * 2;
                ldsm_x4(bh[q*4+0], bh[q*4+1], bh[q*4+2], bh[q*4+3], aBh + off);
                ldsm_x4(bl[q*4+0], bl[q*4+1], bl[q*4+2], bl[q*4+3], aBl + off);
            }
            uint32_t a4[4];
            const uint32_t offA = (uint32_t)((mw * 16 + (mi & 1) * 8 + row8) * 40
                                             + ks + (mi >> 1) * 8) * 2;
            ldsm_x4(a4[0], a4[1], a4[2], a4[3], aAh + offA);
            #pragma unroll
            for (int g = 0; g < 4; g++) {
                mma_bf16(acc[g], a4, &bh[g * 2]);
                mma_bf16(acc[g], a4, &bl[g * 2]);
            }
            ldsm_x4(a4[0], a4[1], a4[2], a4[3], aAl + offA);
            #pragma unroll
            for (int g = 0; g < 4; g++)
                mma_bf16(acc[g], a4, &bh[g * 2]);
        }
        __syncthreads();
    }
    const int m = mw * 16 + (lane >> 2);
    #pragma unroll
    for (int g = 0; g < 4; g++) {
        int n = nw * 32 + g * 8 + (lane & 3) * 2;
        sc[n][m]         = (acc[g][0] + bias[m]) * oscale;
        sc[n + 1][m]     = (acc[g][1] + bias[m]) * oscale;
        sc[n][m + 8]     = (acc[g][2] + bias[m + 8]) * oscale;
        sc[n + 1][m + 8] = (acc[g][3] + bias[m + 8]) * oscale;
    }
    __syncthreads();
    const int n = tid >> 1, half = (tid & 1) * 16;
    #pragma unroll
    for (int j = 0; j < 16; j++) {
        __nv_bfloat16 h, l;
        bsplit(sc[n][half + j], h, l);
        OH[(size_t)(n0 + n) * CQ + half + j] = h;
        OL[(size_t)(n0 + n) * CQ + half + j] = l;
    }
}

// ---------------------------------------------------------------------------
// V projection (mma.sync, 3-term split): vh/vl[b][o][i] = wv @ x + bv
// ---------------------------------------------------------------------------
__global__ __launch_bounds__(256)
void proj_v(const __nv_bfloat16* __restrict__ WVH, const __nv_bfloat16* __restrict__ WVL,
            const float* __restrict__ BV,
            const __nv_bfloat16* __restrict__ XTH, const __nv_bfloat16* __restrict__ XTL,
            __nv_bfloat16* __restrict__ VH, __nv_bfloat16* __restrict__ VL)
{
    __shared__ __nv_bfloat16 sAh[128][40], sAl[128][40], sBh[128][40], sBl[128][40];
    const int tid = threadIdx.x, wid = tid >> 5, lane = tid & 31;
    const int b = blockIdx.z, my = blockIdx.y;
    const int n0 = blockIdx.x * 128;
    const __nv_bfloat16* xh = XTH + (size_t)b * WW * CH;
    const __nv_bfloat16* xl = XTL + (size_t)b * WW * CH;
    __nv_bfloat16* vh = VH + (size_t)b * CH * WW;
    __nv_bfloat16* vl = VL + (size_t)b * CH * WW;
    const int mw = wid & 1, nw = wid >> 1, mi = lane >> 3, row8 = lane & 7;
    const uint32_t aAh = smem_u32(sAh), aAl = smem_u32(sAl);
    const uint32_t aBh = smem_u32(sBh), aBl = smem_u32(sBl);

    float acc[4][4][4] = {};

    for (int kc = 0; kc < 8; kc++) {
        const int k0 = kc * 32;
        #pragma unroll
        for (int i2 = 0; i2 < 2; i2++) {
            int u = tid + 256 * i2;
            int r = u >> 2, c8 = (u & 3) * 8;
            *(uint4*)&sAh[r][c8] = *(const uint4*)(WVH + (size_t)(my * 128 + r) * CH + k0 + c8);
            *(uint4*)&sAl[r][c8] = *(const uint4*)(WVL + (size_t)(my * 128 + r) * CH + k0 + c8);
            *(uint4*)&sBh[r][c8] = *(const uint4*)(xh + (size_t)(n0 + r) * CH + k0 + c8);
            *(uint4*)&sBl[r][c8] = *(const uint4*)(xl + (size_t)(n0 + r) * CH + k0 + c8);
        }
        __syncthreads();
        #pragma unroll
        for (int kk = 0; kk < 2; kk++) {
            const int ks = kk * 16;
            uint32_t bh[8], bl[8];
            #pragma unroll
            for (int q = 0; q < 2; q++) {
                uint32_t off = (uint32_t)((nw * 32 + q * 16 + (mi >> 1) * 8 + row8) * 40
                                          + ks + (mi & 1) * 8) * 2;
                ldsm_x4(bh[q*4+0], bh[q*4+1], bh[q*4+2], bh[q*4+3], aBh + off);
                ldsm_x4(bl[q*4+0], bl[q*4+1], bl[q*4+2], bl[q*4+3], aBl + off);
            }
            uint32_t a[4][4];
            #pragma unroll
            for (int t = 0; t < 4; t++) {
                uint32_t off = (uint32_t)((mw * 64 + t * 16 + (mi & 1) * 8 + row8) * 40
                                          + ks + (mi >> 1) * 8) * 2;
                ldsm_x4(a[t][0], a[t][1], a[t][2], a[t][3], aAh + off);
            }
            #pragma unroll
            for (int t = 0; t < 4; t++)
                #pragma unroll
                for (int g = 0; g < 4; g++) {
                    mma_bf16(acc[t][g], a[t], &bh[g * 2]);
                    mma_bf16(acc[t][g], a[t], &bl[g * 2]);
                }
            #pragma unroll
            for (int t = 0; t < 4; t++) {
                uint32_t off = (uint32_t)((mw * 64 + t * 16 + (mi & 1) * 8 + row8) * 40
                                          + ks + (mi >> 1) * 8) * 2;
                ldsm_x4(a[t][0], a[t][1], a[t][2], a[t][3], aAl + off);
            }
            #pragma unroll
            for (int t = 0; t < 4; t++)
                #pragma unroll
                for (int g = 0; g < 4; g++)
                    mma_bf16(acc[t][g], a[t], &bh[g * 2]);
        }
        __syncthreads();
    }
    #pragma unroll
    for (int t = 0; t < 4; t++) {
        const int o = my * 128 + mw * 64 + t * 16 + (lane >> 2);
        const float b0 = BV[o], b8 = BV[o + 8];
        #pragma unroll
        for (int g = 0; g < 4; g++) {
            const int n = n0 + nw * 32 + g * 8 + (lane & 3) * 2;
            __nv_bfloat16 h0, l0, h1, l1;
            bsplit(acc[t][g][0] + b0, h0, l0);
            bsplit(acc[t][g][1] + b0, h1, l1);
            *(__nv_bfloat162*)&vh[(size_t)o * WW + n] = __nv_bfloat162{h0, h1};
            *(__nv_bfloat162*)&vl[(size_t)o * WW + n] = __nv_bfloat162{l0, l1};
            bsplit(acc[t][g][2] + b8, h0, l0);
            bsplit(acc[t][g][3] + b8, h1, l1);
            *(__nv_bfloat162*)&vh[(size_t)(o + 8) * WW + n] = __nv_bfloat162{h0, h1};
            *(__nv_bfloat162*)&vl[(size_t)(o + 8) * WW + n] = __nv_bfloat162{l0, l1};
        }
    }
}

// ---------------------------------------------------------------------------
// Fused flash attention: scores + softmax + PV + gamma/residual epilogue.
// CTA = (i-tile 128, channel-half 128, batch). 8 warps; warp owns 16 i-rows.
// j-tiles of 64, double-buffered; 112KB smem -> 2 CTAs/SM.
// ---------------------------------------------------------------------------
#define F_KLO   5120
#define F_VHI   10240
#define F_VLO   28672
#define F_STG   47104
#define F_Q     94208
#define F_QLO   10240
#define F_SMEM  114688

__global__ __launch_bounds__(256, 2)
void fused_attn(const __nv_bfloat16* __restrict__ QTH, const __nv_bfloat16* __restrict__ QTL,
                const __nv_bfloat16* __restrict__ KTH, const __nv_bfloat16* __restrict__ KTL,
                const __nv_bfloat16* __restrict__ VH, const __nv_bfloat16* __restrict__ VL,
                const float* __restrict__ X, const float* __restrict__ gamma,
                float* __restrict__ OUT)
{
    extern __shared__ char smem[];
    const uint32_t sbase = smem_u32(smem);
    const int tid = threadIdx.x, wid = tid >> 5, lane = tid & 31;
    const int mi = lane >> 3, row8 = lane & 7;
    const int i0 = blockIdx.x * 128;
    const int c0 = blockIdx.y * 128;
    const int b  = blockIdx.z;

    const __nv_bfloat16* qhg = QTH + (size_t)b * WW * CQ;
    const __nv_bfloat16* qlg = QTL + (size_t)b * WW * CQ;
    const __nv_bfloat16* khg = KTH + (size_t)b * WW * CQ;
    const __nv_bfloat16* klg = KTL + (size_t)b * WW * CQ;
    const __nv_bfloat16* vhg = VH + (size_t)b * CH * WW + (size_t)c0 * WW;
    const __nv_bfloat16* vlg = VL + (size_t)b * CH * WW + (size_t)c0 * WW;
    const float* xb = X + (size_t)b * CH * WW;
    float* ob = OUT + (size_t)b * CH * WW;

    // stage one j-tile of 64: K^T hi/lo (64x32, pitch 40) + V hi/lo (128x64, pitch 72)
    auto stage = [&](int jt, int st) {
        const int j0 = jt * 64;
        const uint32_t sb = sbase + st * F_STG;
        {
            int r = tid >> 2, c8 = (tid & 3) * 8;        // 256 threads = 64x4 chunks
            size_t go = (size_t)(j0 + r) * CQ + c8;
            uint32_t so = (uint32_t)(r * 40 + c8) * 2;
            cp16(sb + so, khg + go);
            cp16(sb + F_KLO + so, klg + go);
        }
        #pragma unroll
        for (int it = 0; it < 4; it++) {
            int u = tid + 256 * it;                      // 0..1023 = 128x8 chunks
            int r = u >> 3, c8 = (u & 7) * 8;
            size_t go = (size_t)r * WW + j0 + c8;
            uint32_t so = (uint32_t)(r * 72 + c8) * 2;
            cp16(sb + F_VHI + so, vhg + go);
            cp16(sb + F_VLO + so, vlg + go);
        }
    };

    stage(0, 0);
    asm volatile("cp.async.commit_group;");

    // load q tile (plain stores)
    #pragma unroll
    for (int it = 0; it < 2; it++) {
        int u = tid + 256 * it;
        int r = u >> 2, c8 = (u & 3) * 8;
        uint32_t so = (uint32_t)(r * 40 + c8) * 2;
        *(uint4*)(smem + F_Q + so) = *(const uint4*)(qhg + (size_t)(i0 + r) * CQ + c8);
        *(uint4*)(smem + F_Q + F_QLO + so) = *(const uint4*)(qlg + (size_t)(i0 + r) * CQ + c8);
    }
    __syncthreads();

    float s_[8][4];
    float o_[16][4] = {};
    float m0 = -1e30f, m1 = -1e30f, l0 = 0.f, l1 = 0.f;

    for (int jt = 0; jt < 32; jt++) {
        const int st = jt & 1;
        if (jt < 31) {
            stage(jt + 1, st ^ 1);
            asm volatile("cp.async.commit_group;");
            asm volatile("cp.async.wait_group 1;");
        } else {
            asm volatile("cp.async.wait_group 0;");
        }
        __syncthreads();

        // ---- scores: S = q k^T (3-term split), warp rows = wid*16..+15, j 0..63 ----
        #pragma unroll
        for (int nt = 0; nt < 8; nt++)
            #pragma unroll
            for (int v = 0; v < 4; v++) s_[nt][v] = 0.f;

        const uint32_t aK = sbase + st * F_STG;
        #pragma unroll
        for (int kk = 0; kk < 2; kk++) {
            uint32_t qah[4], qal[4];
            const uint32_t offA = (uint32_t)((wid * 16 + (mi & 1) * 8 + row8) * 40
                                             + kk * 16 + (mi >> 1) * 8) * 2;
            ldsm_x4(qah[0], qah[1], qah[2], qah[3], sbase + F_Q + offA);
            ldsm_x4(qal[0], qal[1], qal[2], qal[3], sbase + F_Q + F_QLO + offA);
            #pragma unroll
            for (int ntp = 0; ntp < 4; ntp++) {
                uint32_t off = (uint32_t)((ntp * 16 + (mi >> 1) * 8 + row8) * 40
                                          + kk * 16 + (mi & 1) * 8) * 2;
                uint32_t bh[4], bl[4];
                ldsm_x4(bh[0], bh[1], bh[2], bh[3], aK + off);
                ldsm_x4(bl[0], bl[1], bl[2], bl[3], aK + F_KLO + off);
                mma_bf16(s_[2*ntp],   qah, &bh[0]);
                mma_bf16(s_[2*ntp+1], qah, &bh[2]);
                mma_bf16(s_[2*ntp],   qal, &bh[0]);
                mma_bf16(s_[2*ntp+1], qal, &bh[2]);
                mma_bf16(s_[2*ntp],   qah, &bl[0]);
                mma_bf16(s_[2*ntp+1], qah, &bl[2]);
            }
        }

        // ---- online softmax (log2 domain; q pre-scaled by log2e) ----
        float ml0 = -1e30f, ml1 = -1e30f;
        #pragma unroll
        for (int nt = 0; nt < 8; nt++) {
            ml0 = fmaxf(ml0, fmaxf(s_[nt][0], s_[nt][1]));
            ml1 = fmaxf(ml1, fmaxf(s_[nt][2], s_[nt][3]));
        }
        ml0 = fmaxf(ml0, __shfl_xor_sync(0xffffffffu, ml0, 1));
        ml0 = fmaxf(ml0, __shfl_xor_sync(0xffffffffu, ml0, 2));
        ml1 = fmaxf(ml1, __shfl_xor_sync(0xffffffffu, ml1, 1));
        ml1 = fmaxf(ml1, __shfl_xor_sync(0xffffffffu, ml1, 2));
        const float mn0 = fmaxf(m0, ml0), mn1 = fmaxf(m1, ml1);
        const float sc0 = exp2f(m0 - mn0), sc1 = exp2f(m1 - mn1);
        m0 = mn0; m1 = mn1;

        float ls0 = 0.f, ls1 = 0.f;
        #pragma unroll
        for (int nt = 0; nt < 8; nt++) {
            s_[nt][0] = exp2f(s_[nt][0] - m0);
            s_[nt][1] = exp2f(s_[nt][1] - m0);
            s_[nt][2] = exp2f(s_[nt][2] - m1);
            s_[nt][3] = exp2f(s_[nt][3] - m1);
            ls0 += s_[nt][0] + s_[nt][1];
            ls1 += s_[nt][2] + s_[nt][3];
        }
        l0 = l0 * sc0 + ls0;
        l1 = l1 * sc1 + ls1;
        #pragma unroll
        for (int nt = 0; nt < 8; nt++) {
            o_[nt][0] *= sc0;  o_[nt][1] *= sc0;
            o_[nt][2] *= sc1;  o_[nt][3] *= sc1;
        }
        #pragma unroll
        for (int nt = 8; nt < 16; nt++) {
            o_[nt][0] *= sc0;  o_[nt][1] *= sc0;
            o_[nt][2] *= sc1;  o_[nt][3] *= sc1;
        }

        // ---- PV: O += Ph Vh + Pl Vh + Ph Vl ----
        const uint32_t aV = sbase + st * F_STG + F_VHI;
        #pragma unroll
        for (int ks = 0; ks < 4; ks++) {
            uint32_t pah[4], pal[4];
            #pragma unroll
            for (int t = 0; t < 2; t++) {
                const float p0 = s_[2*ks+t][0], p1 = s_[2*ks+t][1];
                const float p2 = s_[2*ks+t][2], p3 = s_[2*ks+t][3];
                uint32_t h01 = packbf2(p0, p1);
                uint32_t h23 = packbf2(p2, p3);
                __nv_bfloat162 hb01 = *(__nv_bfloat162*)&h01;
                __nv_bfloat162 hb23 = *(__nv_bfloat162*)&h23;
                pah[2*t]   = h01;
                pah[2*t+1] = h23;
                pal[2*t]   = packbf2(p0 - __bfloat162float(hb01.x),
                                     p1 - __bfloat162float(hb01.y));
                pal[2*t+1] = packbf2(p2 - __bfloat162float(hb23.x),
                                     p3 - __bfloat162float(hb23.y));
            }
            #pragma unroll
            for (int ntp = 0; ntp < 8; ntp++) {
                uint32_t off = (uint32_t)((ntp * 16 + (mi >> 1) * 8 + row8) * 72
                                          + ks * 16 + (mi & 1) * 8) * 2;
                uint32_t bh[4], bl[4];
                ldsm_x4(bh[0], bh[1], bh[2], bh[3], aV + off);
                ldsm_x4(bl[0], bl[1], bl[2], bl[3], aV + (F_VLO - F_VHI) + off);
                mma_bf16(o_[2*ntp],   pah, &bh[0]);
                mma_bf16(o_[2*ntp+1], pah, &bh[2]);
                mma_bf16(o_[2*ntp],   pal, &bh[0]);
                mma_bf16(o_[2*ntp+1], pal, &bh[2]);
                mma_bf16(o_[2*ntp],   pah, &bl[0]);
                mma_bf16(o_[2*ntp+1], pah, &bl[2]);
            }
        }
        __syncthreads();
    }

    // ---- epilogue: normalize, bounce through smem to [c][i], +gamma/x ----
    l0 += __shfl_xor_sync(0xffffffffu, l0, 1);
    l0 += __shfl_xor_sync(0xffffffffu, l0, 2);
    l1 += __shfl_xor_sync(0xffffffffu, l1, 1);
    l1 += __shfl_xor_sync(0xffffffffu, l1, 2);
    const float inv0 = 1.f / l0, inv1 = 1.f / l1;

    float* sO = (float*)smem;            // [c 128][i 128] pitch 132
    const int rA = wid * 16 + (lane >> 2), rB = rA + 8;
    #pragma unroll
    for (int nt = 0; nt < 16; nt++) {
        const int c = nt * 8 + (lane & 3) * 2;
        sO[c * 132 + rA]       = o_[nt][0] * inv0;
        sO[(c + 1) * 132 + rA] = o_[nt][1] * inv0;
        sO[c * 132 + rB]       = o_[nt][2] * inv1;
        sO[(c + 1) * 132 + rB] = o_[nt][3] * inv1;
    }
    __syncthreads();

    const float g = gamma[0];
    #pragma unroll
    for (int it = 0; it < 16; it++) {
        int u = tid + 256 * it;               // 0..4095
        int r = u >> 5, c4 = (u & 31) * 4;
        float4 v4 = *(float4*)&sO[r * 132 + c4];
        size_t go = (size_t)(c0 + r) * WW + i0 + c4;
        float4 xv = *(const float4*)(xb + go);
        v4.x = g * v4.x + xv.x;
        v4.y = g * v4.y + xv.y;
        v4.z = g * v4.z + xv.z;
        v4.w = g * v4.w + xv.w;
        *(float4*)(ob + go) = v4;
    }
}

// ---------------------------------------------------------------------------
extern "C" void kernel_launch(void* const* d_in, const int* in_sizes, int n_in,
                              void* d_out, int out_size)
{
    const float* x     = (const float*)d_in[0];
    const float* wq    = (const float*)d_in[1];
    const float* bq    = (const float*)d_in[2];
    const float* wk    = (const float*)d_in[3];
    const float* bk    = (const float*)d_in[4];
    const float* wv    = (const float*)d_in[5];
    const float* bv    = (const float*)d_in[6];
    const float* gamma = (const float*)d_in[7];
    float* out = (float*)d_out;

    __nv_bfloat16 *vh, *vl, *xth, *xtl, *qth, *qtl, *kth, *ktl;
    __nv_bfloat16 *wqh, *wql, *wkh, *wkl, *wvh, *wvl;
    cudaGetSymbolAddress((void**)&vh, g_vh);
    cudaGetSymbolAddress((void**)&vl, g_vl);
    cudaGetSymbolAddress((void**)&xth, g_xth);
    cudaGetSymbolAddress((void**)&xtl, g_xtl);
    cudaGetSymbolAddress((void**)&qth, g_qth);
    cudaGetSymbolAddress((void**)&qtl, g_qtl);
    cudaGetSymbolAddress((void**)&kth, g_kth);
    cudaGetSymbolAddress((void**)&ktl, g_ktl);
    cudaGetSymbolAddress((void**)&wqh, g_wqh);
    cudaGetSymbolAddress((void**)&wql, g_wql);
    cudaGetSymbolAddress((void**)&wkh, g_wkh);
    cudaGetSymbolAddress((void**)&wkl, g_wkl);
    cudaGetSymbolAddress((void**)&wvh, g_wvh);
    cudaGetSymbolAddress((void**)&wvl, g_wvl);

    // 1. split weights
    split_flat<<<CQ * CH / 256, 256>>>(wq, wqh, wql);
    split_flat<<<CQ * CH / 256, 256>>>(wk, wkh, wkl);
    split_flat<<<CH * CH / 256, 256>>>(wv, wvh, wvl);

    // 2. transpose + split x
    transpose_split_x<<<dim3(WW / 32, CH / 32, BATCH), 256>>>(x, xth, xtl);

    // 3. q/k projections (transposed output; q pre-scaled by log2e)
    proj_qk<<<dim3(WW / 128, 2, BATCH), 256>>>(wqh, wql, wkh, wkl, bq, bk,
                                               xth, xtl, qth, qtl, kth, ktl);

    // 4. v projection
    proj_v<<<dim3(WW / 128, CH / 128, BATCH), 256>>>(wvh, wvl, bv, xth, xtl, vh, vl);

    // 5. fused attention (2 CTAs/SM)
    cudaFuncSetAttribute(fused_attn, cudaFuncAttributeMaxDynamicSharedMemorySize, F_SMEM);
    fused_attn<<<dim3(WW / 128, CH / 128, BATCH), 256, F_SMEM>>>(
        qth, qtl, kth, ktl, vh, vl, x, gamma, out);
}

// round 7
// speedup vs baseline: 4.7475x; 1.5962x over previous
#include <cuda_runtime.h>
#include <cuda_bf16.h>
#include <cuda_fp16.h>
#include <cstdint>

// Problem constants
#define BATCH 16
#define CH    256
#define CQ    32
#define WW    2048

#define LOG2E 1.4426950408889634f

// ---------------------------------------------------------------------------
// Scratch (device globals: allocation-free per harness rules)
// ---------------------------------------------------------------------------
__device__ __half g_vh[(size_t)BATCH * CH * WW];                  // V fp16 [b][c][j]
__device__ __nv_bfloat16 g_xth[(size_t)BATCH * WW * CH];          // x^T hi [b][i][c]
__device__ __nv_bfloat16 g_xtl[(size_t)BATCH * WW * CH];          // x^T lo
__device__ __nv_bfloat16 g_qth[(size_t)BATCH * WW * CQ];          // q^T hi [b][i][d] (pre-scaled by log2e)
__device__ __nv_bfloat16 g_qtl[(size_t)BATCH * WW * CQ];
__device__ __nv_bfloat16 g_kth[(size_t)BATCH * WW * CQ];
__device__ __nv_bfloat16 g_ktl[(size_t)BATCH * WW * CQ];
__device__ __nv_bfloat16 g_wqh[CQ * CH], g_wql[CQ * CH];
__device__ __nv_bfloat16 g_wkh[CQ * CH], g_wkl[CQ * CH];
__device__ __nv_bfloat16 g_wvh[CH * CH], g_wvl[CH * CH];

// ---------------------------------------------------------------------------
// Helpers
// ---------------------------------------------------------------------------
__device__ __forceinline__ uint32_t smem_u32(const void* p) {
    uint32_t a;
    asm("{ .reg .u64 t; cvta.to.shared.u64 t, %1; cvt.u32.u64 %0, t; }" : "=r"(a) : "l"(p));
    return a;
}
__device__ __forceinline__ void ldsm_x4(uint32_t& r0, uint32_t& r1, uint32_t& r2, uint32_t& r3,
                                        uint32_t addr) {
    asm volatile("ldmatrix.sync.aligned.m8n8.x4.shared.b16 {%0,%1,%2,%3}, [%4];"
                 : "=r"(r0), "=r"(r1), "=r"(r2), "=r"(r3) : "r"(addr));
}
__device__ __forceinline__ void mma_bf16(float* c, const uint32_t* a, const uint32_t* b) {
    asm volatile(
        "mma.sync.aligned.m16n8k16.row.col.f32.bf16.bf16.f32 "
        "{%0,%1,%2,%3}, {%4,%5,%6,%7}, {%8,%9}, {%0,%1,%2,%3};"
        : "+f"(c[0]), "+f"(c[1]), "+f"(c[2]), "+f"(c[3])
        : "r"(a[0]), "r"(a[1]), "r"(a[2]), "r"(a[3]), "r"(b[0]), "r"(b[1]));
}
__device__ __forceinline__ void mma_fp16(float* c, const uint32_t* a, const uint32_t* b) {
    asm volatile(
        "mma.sync.aligned.m16n8k16.row.col.f32.f16.f16.f32 "
        "{%0,%1,%2,%3}, {%4,%5,%6,%7}, {%8,%9}, {%0,%1,%2,%3};"
        : "+f"(c[0]), "+f"(c[1]), "+f"(c[2]), "+f"(c[3])
        : "r"(a[0]), "r"(a[1]), "r"(a[2]), "r"(a[3]), "r"(b[0]), "r"(b[1]));
}
__device__ __forceinline__ void cp16(uint32_t dst, const void* src) {
    asm volatile("cp.async.ca.shared.global [%0], [%1], 16;" :: "r"(dst), "l"(src));
}
__device__ __forceinline__ void bsplit(float v, __nv_bfloat16& h, __nv_bfloat16& l) {
    h = __float2bfloat16(v);
    l = __float2bfloat16(v - __bfloat162float(h));
}
__device__ __forceinline__ uint32_t packh2(float x, float y) {
    __half2 t = __floats2half2_rn(x, y);
    return *(uint32_t*)&t;
}

// ---------------------------------------------------------------------------
// Split fp32 -> bf16 hi/lo (weights)
// ---------------------------------------------------------------------------
__global__ __launch_bounds__(256)
void split_flat(const float* __restrict__ s, __nv_bfloat16* __restrict__ h,
                __nv_bfloat16* __restrict__ l)
{
    int i = blockIdx.x * 256 + threadIdx.x;
    __nv_bfloat16 hh, ll;
    bsplit(s[i], hh, ll);
    h[i] = hh; l[i] = ll;
}

// ---------------------------------------------------------------------------
// x [b][c][i] fp32 -> xT hi/lo [b][i][c] bf16 (32x32 smem tiles)
// ---------------------------------------------------------------------------
__global__ __launch_bounds__(256)
void transpose_split_x(const float* __restrict__ X, __nv_bfloat16* __restrict__ XTH,
                       __nv_bfloat16* __restrict__ XTL)
{
    __shared__ float t[32][33];
    const int b = blockIdx.z;
    const int i0 = blockIdx.x * 32, c0 = blockIdx.y * 32;
    const int tx = threadIdx.x & 31, ty = threadIdx.x >> 5;
    const float* xb = X + (size_t)b * CH * WW;
    #pragma unroll
    for (int r = 0; r < 4; r++)
        t[ty + r * 8][tx] = xb[(size_t)(c0 + ty + r * 8) * WW + i0 + tx];
    __syncthreads();
    __nv_bfloat16* oh = XTH + (size_t)b * WW * CH;
    __nv_bfloat16* ol = XTL + (size_t)b * WW * CH;
    #pragma unroll
    for (int r = 0; r < 4; r++) {
        int i = ty + r * 8;
        __nv_bfloat16 h, l;
        bsplit(t[tx][i], h, l);
        oh[(size_t)(i0 + i) * CH + c0 + tx] = h;
        ol[(size_t)(i0 + i) * CH + c0 + tx] = l;
    }
}

// ---------------------------------------------------------------------------
// Q/K projection (mma.sync, 3-term split): qT[b][i][d] = (wq @ x)^T + bq
// Q output is pre-scaled by log2e (softmax uses exp2).
// ---------------------------------------------------------------------------
__global__ __launch_bounds__(256)
void proj_qk(const __nv_bfloat16* __restrict__ WHQ, const __nv_bfloat16* __restrict__ WLQ,
             const __nv_bfloat16* __restrict__ WHK, const __nv_bfloat16* __restrict__ WLK,
             const float* __restrict__ BQ, const float* __restrict__ BK_,
             const __nv_bfloat16* __restrict__ XTH, const __nv_bfloat16* __restrict__ XTL,
             __nv_bfloat16* __restrict__ QTH, __nv_bfloat16* __restrict__ QTL,
             __nv_bfloat16* __restrict__ KTH, __nv_bfloat16* __restrict__ KTL)
{
    __shared__ __nv_bfloat16 sAh[32][40], sAl[32][40], sBh[128][40], sBl[128][40];
    __shared__ float sc[129][33];
    const int tid = threadIdx.x, wid = tid >> 5, lane = tid & 31;
    const int b = blockIdx.z;
    const int n0 = blockIdx.x * 128;
    const bool isK = blockIdx.y == 1;
    const __nv_bfloat16* wh = isK ? WHK : WHQ;
    const __nv_bfloat16* wl = isK ? WLK : WLQ;
    const float* bias = isK ? BK_ : BQ;
    const float oscale = isK ? 1.0f : LOG2E;
    __nv_bfloat16* OH = (isK ? KTH : QTH) + (size_t)b * WW * CQ;
    __nv_bfloat16* OL = (isK ? KTL : QTL) + (size_t)b * WW * CQ;
    const __nv_bfloat16* xh = XTH + (size_t)b * WW * CH;
    const __nv_bfloat16* xl = XTL + (size_t)b * WW * CH;

    const int mw = wid & 1, nw = wid >> 1;
    const int mi = lane >> 3, row8 = lane & 7;
    const uint32_t aAh = smem_u32(sAh), aAl = smem_u32(sAl);
    const uint32_t aBh = smem_u32(sBh), aBl = smem_u32(sBl);

    float acc[4][4] = {};

    for (int kc = 0; kc < 8; kc++) {
        const int k0 = kc * 32;
        if (tid < 128) {
            int r = tid >> 2, c8 = (tid & 3) * 8;
            *(uint4*)&sAh[r][c8] = *(const uint4*)(wh + (size_t)r * CH + k0 + c8);
            *(uint4*)&sAl[r][c8] = *(const uint4*)(wl + (size_t)r * CH + k0 + c8);
        }
        #pragma unroll
        for (int i2 = 0; i2 < 2; i2++) {
            int u = tid + 256 * i2;
            int r = u >> 2, c8 = (u & 3) * 8;
            *(uint4*)&sBh[r][c8] = *(const uint4*)(xh + (size_t)(n0 + r) * CH + k0 + c8);
            *(uint4*)&sBl[r][c8] = *(const uint4*)(xl + (size_t)(n0 + r) * CH + k0 + c8);
        }
        __syncthreads();
        #pragma unroll
        for (int kk = 0; kk < 2; kk++) {
            const int ks = kk * 16;
            uint32_t bh[8], bl[8];
            #pragma unroll
            for (int q = 0; q < 2; q++) {
                uint32_t off = (uint32_t)((nw * 32 + q * 16 + (mi >> 1) * 8 + row8) * 40
                                          + ks + (mi & 1) * 8) * 2;
                ldsm_x4(bh[q*4+0], bh[q*4+1], bh[q*4+2], bh[q*4+3], aBh + off);
                ldsm_x4(bl[q*4+0], bl[q*4+1], bl[q*4+2], bl[q*4+3], aBl + off);
            }
            uint32_t a4[4];
            const uint32_t offA = (uint32_t)((mw * 16 + (mi & 1) * 8 + row8) * 40
                                             + ks + (mi >> 1) * 8) * 2;
            ldsm_x4(a4[0], a4[1], a4[2], a4[3], aAh + offA);
            #pragma unroll
            for (int g = 0; g < 4; g++) {
                mma_bf16(acc[g], a4, &bh[g * 2]);
                mma_bf16(acc[g], a4, &bl[g * 2]);
            }
            ldsm_x4(a4[0], a4[1], a4[2], a4[3], aAl + offA);
            #pragma unroll
            for (int g = 0; g < 4; g++)
                mma_bf16(acc[g], a4, &bh[g * 2]);
        }
        __syncthreads();
    }
    const int m = mw * 16 + (lane >> 2);
    #pragma unroll
    for (int g = 0; g < 4; g++) {
        int n = nw * 32 + g * 8 + (lane & 3) * 2;
        sc[n][m]         = (acc[g][0] + bias[m]) * oscale;
        sc[n + 1][m]     = (acc[g][1] + bias[m]) * oscale;
        sc[n][m + 8]     = (acc[g][2] + bias[m + 8]) * oscale;
        sc[n + 1][m + 8] = (acc[g][3] + bias[m + 8]) * oscale;
    }
    __syncthreads();
    const int n = tid >> 1, half = (tid & 1) * 16;
    #pragma unroll
    for (int j = 0; j < 16; j++) {
        __nv_bfloat16 h, l;
        bsplit(sc[n][half + j], h, l);
        OH[(size_t)(n0 + n) * CQ + half + j] = h;
        OL[(size_t)(n0 + n) * CQ + half + j] = l;
    }
}

// ---------------------------------------------------------------------------
// V projection (mma.sync, 3-term bf16 split GEMM): v[b][o][i] = wv @ x + bv
// Output: single fp16.
// ---------------------------------------------------------------------------
__global__ __launch_bounds__(256)
void proj_v(const __nv_bfloat16* __restrict__ WVH, const __nv_bfloat16* __restrict__ WVL,
            const float* __restrict__ BV,
            const __nv_bfloat16* __restrict__ XTH, const __nv_bfloat16* __restrict__ XTL,
            __half* __restrict__ VH)
{
    __shared__ __nv_bfloat16 sAh[128][40], sAl[128][40], sBh[128][40], sBl[128][40];
    const int tid = threadIdx.x, wid = tid >> 5, lane = tid & 31;
    const int b = blockIdx.z, my = blockIdx.y;
    const int n0 = blockIdx.x * 128;
    const __nv_bfloat16* xh = XTH + (size_t)b * WW * CH;
    const __nv_bfloat16* xl = XTL + (size_t)b * WW * CH;
    __half* vh = VH + (size_t)b * CH * WW;
    const int mw = wid & 1, nw = wid >> 1, mi = lane >> 3, row8 = lane & 7;
    const uint32_t aAh = smem_u32(sAh), aAl = smem_u32(sAl);
    const uint32_t aBh = smem_u32(sBh), aBl = smem_u32(sBl);

    float acc[4][4][4] = {};

    for (int kc = 0; kc < 8; kc++) {
        const int k0 = kc * 32;
        #pragma unroll
        for (int i2 = 0; i2 < 2; i2++) {
            int u = tid + 256 * i2;
            int r = u >> 2, c8 = (u & 3) * 8;
            *(uint4*)&sAh[r][c8] = *(const uint4*)(WVH + (size_t)(my * 128 + r) * CH + k0 + c8);
            *(uint4*)&sAl[r][c8] = *(const uint4*)(WVL + (size_t)(my * 128 + r) * CH + k0 + c8);
            *(uint4*)&sBh[r][c8] = *(const uint4*)(xh + (size_t)(n0 + r) * CH + k0 + c8);
            *(uint4*)&sBl[r][c8] = *(const uint4*)(xl + (size_t)(n0 + r) * CH + k0 + c8);
        }
        __syncthreads();
        #pragma unroll
        for (int kk = 0; kk < 2; kk++) {
            const int ks = kk * 16;
            uint32_t bh[8], bl[8];
            #pragma unroll
            for (int q = 0; q < 2; q++) {
                uint32_t off = (uint32_t)((nw * 32 + q * 16 + (mi >> 1) * 8 + row8) * 40
                                          + ks + (mi & 1) * 8) * 2;
                ldsm_x4(bh[q*4+0], bh[q*4+1], bh[q*4+2], bh[q*4+3], aBh + off);
                ldsm_x4(bl[q*4+0], bl[q*4+1], bl[q*4+2], bl[q*4+3], aBl + off);
            }
            uint32_t a[4][4];
            #pragma unroll
            for (int t = 0; t < 4; t++) {
                uint32_t off = (uint32_t)((mw * 64 + t * 16 + (mi & 1) * 8 + row8) * 40
                                          + ks + (mi >> 1) * 8) * 2;
                ldsm_x4(a[t][0], a[t][1], a[t][2], a[t][3], aAh + off);
            }
            #pragma unroll
            for (int t = 0; t < 4; t++)
                #pragma unroll
                for (int g = 0; g < 4; g++) {
                    mma_bf16(acc[t][g], a[t], &bh[g * 2]);
                    mma_bf16(acc[t][g], a[t], &bl[g * 2]);
                }
            #pragma unroll
            for (int t = 0; t < 4; t++) {
                uint32_t off = (uint32_t)((mw * 64 + t * 16 + (mi & 1) * 8 + row8) * 40
                                          + ks + (mi >> 1) * 8) * 2;
                ldsm_x4(a[t][0], a[t][1], a[t][2], a[t][3], aAl + off);
            }
            #pragma unroll
            for (int t = 0; t < 4; t++)
                #pragma unroll
                for (int g = 0; g < 4; g++)
                    mma_bf16(acc[t][g], a[t], &bh[g * 2]);
        }
        __syncthreads();
    }
    #pragma unroll
    for (int t = 0; t < 4; t++) {
        const int o = my * 128 + mw * 64 + t * 16 + (lane >> 2);
        const float b0 = BV[o], b8 = BV[o + 8];
        #pragma unroll
        for (int g = 0; g < 4; g++) {
            const int n = n0 + nw * 32 + g * 8 + (lane & 3) * 2;
            *(__half2*)&vh[(size_t)o * WW + n] =
                __floats2half2_rn(acc[t][g][0] + b0, acc[t][g][1] + b0);
            *(__half2*)&vh[(size_t)(o + 8) * WW + n] =
                __floats2half2_rn(acc[t][g][2] + b8, acc[t][g][3] + b8);
        }
    }
}

// ---------------------------------------------------------------------------
// Fused flash attention: scores(bf16 3-term) + softmax + PV(fp16 single-term)
// CTA = (i-tile 128, channel-half 128, batch). 8 warps; warp owns 16 i-rows.
// j-tiles of 64 double-buffered, softmax in 32-j steps. 76KB smem, 2 CTA/SM.
// ---------------------------------------------------------------------------
#define F_KLO   5120
#define F_VHI   10240
#define F_STG   28672
#define F_Q     57344
#define F_QLO   10240
#define F_SMEM  77824

__global__ __launch_bounds__(256, 2)
void fused_attn(const __nv_bfloat16* __restrict__ QTH, const __nv_bfloat16* __restrict__ QTL,
                const __nv_bfloat16* __restrict__ KTH, const __nv_bfloat16* __restrict__ KTL,
                const __half* __restrict__ VH,
                const float* __restrict__ X, const float* __restrict__ gamma,
                float* __restrict__ OUT)
{
    extern __shared__ char smem[];
    const uint32_t sbase = smem_u32(smem);
    const int tid = threadIdx.x, wid = tid >> 5, lane = tid & 31;
    const int mi = lane >> 3, row8 = lane & 7;
    const int i0 = blockIdx.x * 128;
    const int c0 = blockIdx.y * 128;
    const int b  = blockIdx.z;

    const __nv_bfloat16* qhg = QTH + (size_t)b * WW * CQ;
    const __nv_bfloat16* qlg = QTL + (size_t)b * WW * CQ;
    const __nv_bfloat16* khg = KTH + (size_t)b * WW * CQ;
    const __nv_bfloat16* klg = KTL + (size_t)b * WW * CQ;
    const __half* vhg = VH + (size_t)b * CH * WW + (size_t)c0 * WW;
    const float* xb = X + (size_t)b * CH * WW;
    float* ob = OUT + (size_t)b * CH * WW;

    // stage one 64-j tile: K^T bf16 hi/lo (64x32, pitch 40) + V fp16 (128x64, pitch 72)
    auto stage = [&](int jt, int st) {
        const int j0 = jt * 64;
        const uint32_t sb = sbase + st * F_STG;
        {
            int r = tid >> 2, c8 = (tid & 3) * 8;
            size_t go = (size_t)(j0 + r) * CQ + c8;
            uint32_t so = (uint32_t)(r * 40 + c8) * 2;
            cp16(sb + so, khg + go);
            cp16(sb + F_KLO + so, klg + go);
        }
        #pragma unroll
        for (int it = 0; it < 4; it++) {
            int u = tid + 256 * it;                      // 0..1023 = 128x8 chunks
            int r = u >> 3, c8 = (u & 7) * 8;
            cp16(sb + F_VHI + (uint32_t)(r * 72 + c8) * 2, vhg + (size_t)r * WW + j0 + c8);
        }
    };

    stage(0, 0);
    asm volatile("cp.async.commit_group;");

    // load q tile (plain stores)
    #pragma unroll
    for (int it = 0; it < 2; it++) {
        int u = tid + 256 * it;
        int r = u >> 2, c8 = (u & 3) * 8;
        uint32_t so = (uint32_t)(r * 40 + c8) * 2;
        *(uint4*)(smem + F_Q + so) = *(const uint4*)(qhg + (size_t)(i0 + r) * CQ + c8);
        *(uint4*)(smem + F_Q + F_QLO + so) = *(const uint4*)(qlg + (size_t)(i0 + r) * CQ + c8);
    }
    __syncthreads();

    // cache q fragments (loop-invariant)
    uint32_t qah[8], qal[8];
    #pragma unroll
    for (int kk = 0; kk < 2; kk++) {
        const uint32_t offA = (uint32_t)((wid * 16 + (mi & 1) * 8 + row8) * 40
                                         + kk * 16 + (mi >> 1) * 8) * 2;
        ldsm_x4(qah[kk*4+0], qah[kk*4+1], qah[kk*4+2], qah[kk*4+3], sbase + F_Q + offA);
        ldsm_x4(qal[kk*4+0], qal[kk*4+1], qal[kk*4+2], qal[kk*4+3], sbase + F_Q + F_QLO + offA);
    }

    float o_[16][4] = {};
    float m0 = -1e30f, m1 = -1e30f, l0 = 0.f, l1 = 0.f;

    for (int jt = 0; jt < 32; jt++) {
        const int st = jt & 1;
        if (jt < 31) {
            stage(jt + 1, st ^ 1);
            asm volatile("cp.async.commit_group;");
            asm volatile("cp.async.wait_group 1;");
        } else {
            asm volatile("cp.async.wait_group 0;");
        }
        __syncthreads();

        const uint32_t aK = sbase + st * F_STG;
        const uint32_t aV = aK + F_VHI;

        #pragma unroll
        for (int jh = 0; jh < 2; jh++) {
            // ---- scores for 32 j: bf16 3-term ----
            float s_[4][4] = {};
            #pragma unroll
            for (int kk = 0; kk < 2; kk++) {
                #pragma unroll
                for (int ntp = 0; ntp < 2; ntp++) {
                    uint32_t off = (uint32_t)((jh * 32 + ntp * 16 + (mi >> 1) * 8 + row8) * 40
                                              + kk * 16 + (mi & 1) * 8) * 2;
                    uint32_t bh[4], bl[4];
                    ldsm_x4(bh[0], bh[1], bh[2], bh[3], aK + off);
                    ldsm_x4(bl[0], bl[1], bl[2], bl[3], aK + F_KLO + off);
                    mma_bf16(s_[2*ntp],   &qah[kk*4], &bh[0]);
                    mma_bf16(s_[2*ntp+1], &qah[kk*4], &bh[2]);
                    mma_bf16(s_[2*ntp],   &qal[kk*4], &bh[0]);
                    mma_bf16(s_[2*ntp+1], &qal[kk*4], &bh[2]);
                    mma_bf16(s_[2*ntp],   &qah[kk*4], &bl[0]);
                    mma_bf16(s_[2*ntp+1], &qah[kk*4], &bl[2]);
                }
            }

            // ---- online softmax (log2 domain) ----
            float ml0 = -1e30f, ml1 = -1e30f;
            #pragma unroll
            for (int nt = 0; nt < 4; nt++) {
                ml0 = fmaxf(ml0, fmaxf(s_[nt][0], s_[nt][1]));
                ml1 = fmaxf(ml1, fmaxf(s_[nt][2], s_[nt][3]));
            }
            ml0 = fmaxf(ml0, __shfl_xor_sync(0xffffffffu, ml0, 1));
            ml0 = fmaxf(ml0, __shfl_xor_sync(0xffffffffu, ml0, 2));
            ml1 = fmaxf(ml1, __shfl_xor_sync(0xffffffffu, ml1, 1));
            ml1 = fmaxf(ml1, __shfl_xor_sync(0xffffffffu, ml1, 2));
            const float mn0 = fmaxf(m0, ml0), mn1 = fmaxf(m1, ml1);
            const float sc0 = exp2f(m0 - mn0), sc1 = exp2f(m1 - mn1);
            m0 = mn0; m1 = mn1;

            float ls0 = 0.f, ls1 = 0.f;
            #pragma unroll
            for (int nt = 0; nt < 4; nt++) {
                s_[nt][0] = exp2f(s_[nt][0] - m0);
                s_[nt][1] = exp2f(s_[nt][1] - m0);
                s_[nt][2] = exp2f(s_[nt][2] - m1);
                s_[nt][3] = exp2f(s_[nt][3] - m1);
                ls0 += s_[nt][0] + s_[nt][1];
                ls1 += s_[nt][2] + s_[nt][3];
            }
            l0 = l0 * sc0 + ls0;
            l1 = l1 * sc1 + ls1;
            #pragma unroll
            for (int nt = 0; nt < 16; nt++) {
                o_[nt][0] *= sc0;  o_[nt][1] *= sc0;
                o_[nt][2] *= sc1;  o_[nt][3] *= sc1;
            }

            // ---- PV: O += P(fp16) V(fp16), single term ----
            #pragma unroll
            for (int ksl = 0; ksl < 2; ksl++) {
                const int ks = jh * 2 + ksl;
                uint32_t pa[4];
                pa[0] = packh2(s_[2*ksl][0],   s_[2*ksl][1]);
                pa[1] = packh2(s_[2*ksl][2],   s_[2*ksl][3]);
                pa[2] = packh2(s_[2*ksl+1][0], s_[2*ksl+1][1]);
                pa[3] = packh2(s_[2*ksl+1][2], s_[2*ksl+1][3]);
                #pragma unroll
                for (int ntp = 0; ntp < 8; ntp++) {
                    uint32_t off = (uint32_t)((ntp * 16 + (mi >> 1) * 8 + row8) * 72
                                              + ks * 16 + (mi & 1) * 8) * 2;
                    uint32_t bv[4];
                    ldsm_x4(bv[0], bv[1], bv[2], bv[3], aV + off);
                    mma_fp16(o_[2*ntp],   pa, &bv[0]);
                    mma_fp16(o_[2*ntp+1], pa, &bv[2]);
                }
            }
        }
        __syncthreads();
    }

    // ---- epilogue: normalize, bounce through smem to [c][i], +gamma/x ----
    l0 += __shfl_xor_sync(0xffffffffu, l0, 1);
    l0 += __shfl_xor_sync(0xffffffffu, l0, 2);
    l1 += __shfl_xor_sync(0xffffffffu, l1, 1);
    l1 += __shfl_xor_sync(0xffffffffu, l1, 2);
    const float inv0 = 1.f / l0, inv1 = 1.f / l1;

    float* sO = (float*)smem;            // [c 128][i 128] pitch 132
    const int rA = wid * 16 + (lane >> 2), rB = rA + 8;
    #pragma unroll
    for (int nt = 0; nt < 16; nt++) {
        const int c = nt * 8 + (lane & 3) * 2;
        sO[c * 132 + rA]       = o_[nt][0] * inv0;
        sO[(c + 1) * 132 + rA] = o_[nt][1] * inv0;
        sO[c * 132 + rB]       = o_[nt][2] * inv1;
        sO[(c + 1) * 132 + rB] = o_[nt][3] * inv1;
    }
    __syncthreads();

    const float g = gamma[0];
    #pragma unroll
    for (int it = 0; it < 16; it++) {
        int u = tid + 256 * it;               // 0..4095
        int r = u >> 5, c4 = (u & 31) * 4;
        float4 v4 = *(float4*)&sO[r * 132 + c4];
        size_t go = (size_t)(c0 + r) * WW + i0 + c4;
        float4 xv = *(const float4*)(xb + go);
        v4.x = g * v4.x + xv.x;
        v4.y = g * v4.y + xv.y;
        v4.z = g * v4.z + xv.z;
        v4.w = g * v4.w + xv.w;
        *(float4*)(ob + go) = v4;
    }
}

// ---------------------------------------------------------------------------
extern "C" void kernel_launch(void* const* d_in, const int* in_sizes, int n_in,
                              void* d_out, int out_size)
{
    const float* x     = (const float*)d_in[0];
    const float* wq    = (const float*)d_in[1];
    const float* bq    = (const float*)d_in[2];
    const float* wk    = (const float*)d_in[3];
    const float* bk    = (const float*)d_in[4];
    const float* wv    = (const float*)d_in[5];
    const float* bv    = (const float*)d_in[6];
    const float* gamma = (const float*)d_in[7];
    float* out = (float*)d_out;

    __half* vh;
    __nv_bfloat16 *xth, *xtl, *qth, *qtl, *kth, *ktl;
    __nv_bfloat16 *wqh, *wql, *wkh, *wkl, *wvh, *wvl;
    cudaGetSymbolAddress((void**)&vh, g_vh);
    cudaGetSymbolAddress((void**)&xth, g_xth);
    cudaGetSymbolAddress((void**)&xtl, g_xtl);
    cudaGetSymbolAddress((void**)&qth, g_qth);
    cudaGetSymbolAddress((void**)&qtl, g_qtl);
    cudaGetSymbolAddress((void**)&kth, g_kth);
    cudaGetSymbolAddress((void**)&ktl, g_ktl);
    cudaGetSymbolAddress((void**)&wqh, g_wqh);
    cudaGetSymbolAddress((void**)&wql, g_wql);
    cudaGetSymbolAddress((void**)&wkh, g_wkh);
    cudaGetSymbolAddress((void**)&wkl, g_wkl);
    cudaGetSymbolAddress((void**)&wvh, g_wvh);
    cudaGetSymbolAddress((void**)&wvl, g_wvl);

    // 1. split weights
    split_flat<<<CQ * CH / 256, 256>>>(wq, wqh, wql);
    split_flat<<<CQ * CH / 256, 256>>>(wk, wkh, wkl);
    split_flat<<<CH * CH / 256, 256>>>(wv, wvh, wvl);

    // 2. transpose + split x
    transpose_split_x<<<dim3(WW / 32, CH / 32, BATCH), 256>>>(x, xth, xtl);

    // 3. q/k projections (transposed output; q pre-scaled by log2e)
    proj_qk<<<dim3(WW / 128, 2, BATCH), 256>>>(wqh, wql, wkh, wkl, bq, bk,
                                               xth, xtl, qth, qtl, kth, ktl);

    // 4. v projection (fp16 output)
    proj_v<<<dim3(WW / 128, CH / 128, BATCH), 256>>>(wvh, wvl, bv, xth, xtl, vh);

    // 5. fused attention (2 CTAs/SM)
    cudaFuncSetAttribute(fused_attn, cudaFuncAttributeMaxDynamicSharedMemorySize, F_SMEM);
    fused_attn<<<dim3(WW / 128, CH / 128, BATCH), 256, F_SMEM>>>(
        qth, qtl, kth, ktl, vh, x, gamma, out);
}

// round 9
// speedup vs baseline: 5.7599x; 1.2132x over previous
#include <cuda_runtime.h>
#include <cuda_bf16.h>
#include <cuda_fp16.h>
#include <cstdint>

// Problem constants
#define BATCH 16
#define CH    256
#define CQ    32
#define WW    2048

#define LOG2E 1.4426950408889634f

// ---------------------------------------------------------------------------
// Scratch (device globals: allocation-free per harness rules)
// ---------------------------------------------------------------------------
__device__ __half g_vh[(size_t)BATCH * CH * WW];                  // V fp16 [b][c][j]
__device__ __half g_qt[(size_t)BATCH * WW * CQ];                  // q^T fp16 [b][i][d] (pre-scaled log2e)
__device__ __half g_kt[(size_t)BATCH * WW * CQ];                  // k^T fp16
__device__ __nv_bfloat16 g_xth[(size_t)BATCH * WW * CH];          // x^T hi [b][i][c]
__device__ __nv_bfloat16 g_xtl[(size_t)BATCH * WW * CH];          // x^T lo
__device__ __nv_bfloat16 g_wqh[CQ * CH], g_wql[CQ * CH];
__device__ __nv_bfloat16 g_wkh[CQ * CH], g_wkl[CQ * CH];
__device__ __nv_bfloat16 g_wvh[CH * CH], g_wvl[CH * CH];

// ---------------------------------------------------------------------------
// Helpers
// ---------------------------------------------------------------------------
__device__ __forceinline__ uint32_t smem_u32(const void* p) {
    uint32_t a;
    asm("{ .reg .u64 t; cvta.to.shared.u64 t, %1; cvt.u32.u64 %0, t; }" : "=r"(a) : "l"(p));
    return a;
}
__device__ __forceinline__ void ldsm_x4(uint32_t& r0, uint32_t& r1, uint32_t& r2, uint32_t& r3,
                                        uint32_t addr) {
    asm volatile("ldmatrix.sync.aligned.m8n8.x4.shared.b16 {%0,%1,%2,%3}, [%4];"
                 : "=r"(r0), "=r"(r1), "=r"(r2), "=r"(r3) : "r"(addr));
}
__device__ __forceinline__ void mma_bf16(float* c, const uint32_t* a, const uint32_t* b) {
    asm volatile(
        "mma.sync.aligned.m16n8k16.row.col.f32.bf16.bf16.f32 "
        "{%0,%1,%2,%3}, {%4,%5,%6,%7}, {%8,%9}, {%0,%1,%2,%3};"
        : "+f"(c[0]), "+f"(c[1]), "+f"(c[2]), "+f"(c[3])
        : "r"(a[0]), "r"(a[1]), "r"(a[2]), "r"(a[3]), "r"(b[0]), "r"(b[1]));
}
__device__ __forceinline__ void mma_fp16(float* c, const uint32_t* a, const uint32_t* b) {
    asm volatile(
        "mma.sync.aligned.m16n8k16.row.col.f32.f16.f16.f32 "
        "{%0,%1,%2,%3}, {%4,%5,%6,%7}, {%8,%9}, {%0,%1,%2,%3};"
        : "+f"(c[0]), "+f"(c[1]), "+f"(c[2]), "+f"(c[3])
        : "r"(a[0]), "r"(a[1]), "r"(a[2]), "r"(a[3]), "r"(b[0]), "r"(b[1]));
}
__device__ __forceinline__ void cp16(uint32_t dst, const void* src) {
    asm volatile("cp.async.ca.shared.global [%0], [%1], 16;" :: "r"(dst), "l"(src));
}
__device__ __forceinline__ void bsplit(float v, __nv_bfloat16& h, __nv_bfloat16& l) {
    h = __float2bfloat16(v);
    l = __float2bfloat16(v - __bfloat162float(h));
}
__device__ __forceinline__ uint32_t packh2(float x, float y) {
    __half2 t = __floats2half2_rn(x, y);
    return *(uint32_t*)&t;
}

// ---------------------------------------------------------------------------
// Split fp32 -> bf16 hi/lo (weights)
// ---------------------------------------------------------------------------
__global__ __launch_bounds__(256)
void split_flat(const float* __restrict__ s, __nv_bfloat16* __restrict__ h,
                __nv_bfloat16* __restrict__ l)
{
    int i = blockIdx.x * 256 + threadIdx.x;
    __nv_bfloat16 hh, ll;
    bsplit(s[i], hh, ll);
    h[i] = hh; l[i] = ll;
}

// ---------------------------------------------------------------------------
// x [b][c][i] fp32 -> xT hi/lo [b][i][c] bf16 (32x32 smem tiles)
// ---------------------------------------------------------------------------
__global__ __launch_bounds__(256)
void transpose_split_x(const float* __restrict__ X, __nv_bfloat16* __restrict__ XTH,
                       __nv_bfloat16* __restrict__ XTL)
{
    __shared__ float t[32][33];
    const int b = blockIdx.z;
    const int i0 = blockIdx.x * 32, c0 = blockIdx.y * 32;
    const int tx = threadIdx.x & 31, ty = threadIdx.x >> 5;
    const float* xb = X + (size_t)b * CH * WW;
    #pragma unroll
    for (int r = 0; r < 4; r++)
        t[ty + r * 8][tx] = xb[(size_t)(c0 + ty + r * 8) * WW + i0 + tx];
    __syncthreads();
    __nv_bfloat16* oh = XTH + (size_t)b * WW * CH;
    __nv_bfloat16* ol = XTL + (size_t)b * WW * CH;
    #pragma unroll
    for (int r = 0; r < 4; r++) {
        int i = ty + r * 8;
        __nv_bfloat16 h, l;
        bsplit(t[tx][i], h, l);
        oh[(size_t)(i0 + i) * CH + c0 + tx] = h;
        ol[(size_t)(i0 + i) * CH + c0 + tx] = l;
    }
}

// ---------------------------------------------------------------------------
// Q/K projection (mma.sync, 3-term split internally): qT[b][i][d] fp16
// Q output pre-scaled by log2e (softmax uses exp2).
// ---------------------------------------------------------------------------
__global__ __launch_bounds__(256)
void proj_qk(const __nv_bfloat16* __restrict__ WHQ, const __nv_bfloat16* __restrict__ WLQ,
             const __nv_bfloat16* __restrict__ WHK, const __nv_bfloat16* __restrict__ WLK,
             const float* __restrict__ BQ, const float* __restrict__ BK_,
             const __nv_bfloat16* __restrict__ XTH, const __nv_bfloat16* __restrict__ XTL,
             __half* __restrict__ QT, __half* __restrict__ KT)
{
    __shared__ __nv_bfloat16 sAh[32][40], sAl[32][40], sBh[128][40], sBl[128][40];
    __shared__ float sc[129][33];
    const int tid = threadIdx.x, wid = tid >> 5, lane = tid & 31;
    const int b = blockIdx.z;
    const int n0 = blockIdx.x * 128;
    const bool isK = blockIdx.y == 1;
    const __nv_bfloat16* wh = isK ? WHK : WHQ;
    const __nv_bfloat16* wl = isK ? WLK : WLQ;
    const float* bias = isK ? BK_ : BQ;
    const float oscale = isK ? 1.0f : LOG2E;
    __half* OT = (isK ? KT : QT) + (size_t)b * WW * CQ;
    const __nv_bfloat16* xh = XTH + (size_t)b * WW * CH;
    const __nv_bfloat16* xl = XTL + (size_t)b * WW * CH;

    const int mw = wid & 1, nw = wid >> 1;
    const int mi = lane >> 3, row8 = lane & 7;
    const uint32_t aAh = smem_u32(sAh), aAl = smem_u32(sAl);
    const uint32_t aBh = smem_u32(sBh), aBl = smem_u32(sBl);

    float acc[4][4] = {};

    for (int kc = 0; kc < 8; kc++) {
        const int k0 = kc * 32;
        if (tid < 128) {
            int r = tid >> 2, c8 = (tid & 3) * 8;
            *(uint4*)&sAh[r][c8] = *(const uint4*)(wh + (size_t)r * CH + k0 + c8);
            *(uint4*)&sAl[r][c8] = *(const uint4*)(wl + (size_t)r * CH + k0 + c8);
        }
        #pragma unroll
        for (int i2 = 0; i2 < 2; i2++) {
            int u = tid + 256 * i2;
            int r = u >> 2, c8 = (u & 3) * 8;
            *(uint4*)&sBh[r][c8] = *(const uint4*)(xh + (size_t)(n0 + r) * CH + k0 + c8);
            *(uint4*)&sBl[r][c8] = *(const uint4*)(xl + (size_t)(n0 + r) * CH + k0 + c8);
        }
        __syncthreads();
        #pragma unroll
        for (int kk = 0; kk < 2; kk++) {
            const int ks = kk * 16;
            uint32_t bh[8], bl[8];
            #pragma unroll
            for (int q = 0; q < 2; q++) {
                uint32_t off = (uint32_t)((nw * 32 + q * 16 + (mi >> 1) * 8 + row8) * 40
                                          + ks + (mi & 1) * 8) * 2;
                ldsm_x4(bh[q*4+0], bh[q*4+1], bh[q*4+2], bh[q*4+3], aBh + off);
                ldsm_x4(bl[q*4+0], bl[q*4+1], bl[q*4+2], bl[q*4+3], aBl + off);
            }
            uint32_t a4[4];
            const uint32_t offA = (uint32_t)((mw * 16 + (mi & 1) * 8 + row8) * 40
                                             + ks + (mi >> 1) * 8) * 2;
            ldsm_x4(a4[0], a4[1], a4[2], a4[3], aAh + offA);
            #pragma unroll
            for (int g = 0; g < 4; g++) {
                mma_bf16(acc[g], a4, &bh[g * 2]);
                mma_bf16(acc[g], a4, &bl[g * 2]);
            }
            ldsm_x4(a4[0], a4[1], a4[2], a4[3], aAl + offA);
            #pragma unroll
            for (int g = 0; g < 4; g++)
                mma_bf16(acc[g], a4, &bh[g * 2]);
        }
        __syncthreads();
    }
    const int m = mw * 16 + (lane >> 2);
    #pragma unroll
    for (int g = 0; g < 4; g++) {
        int n = nw * 32 + g * 8 + (lane & 3) * 2;
        sc[n][m]         = (acc[g][0] + bias[m]) * oscale;
        sc[n + 1][m]     = (acc[g][1] + bias[m]) * oscale;
        sc[n][m + 8]     = (acc[g][2] + bias[m + 8]) * oscale;
        sc[n + 1][m + 8] = (acc[g][3] + bias[m + 8]) * oscale;
    }
    __syncthreads();
    const int n = tid >> 1, half = (tid & 1) * 16;
    #pragma unroll
    for (int j = 0; j < 16; j += 2) {
        *(__half2*)&OT[(size_t)(n0 + n) * CQ + half + j] =
            __floats2half2_rn(sc[n][half + j], sc[n][half + j + 1]);
    }
}

// ---------------------------------------------------------------------------
// V projection (mma.sync, 3-term bf16 split GEMM): v[b][o][i] = wv @ x + bv
// Output: single fp16.
// ---------------------------------------------------------------------------
__global__ __launch_bounds__(256)
void proj_v(const __nv_bfloat16* __restrict__ WVH, const __nv_bfloat16* __restrict__ WVL,
            const float* __restrict__ BV,
            const __nv_bfloat16* __restrict__ XTH, const __nv_bfloat16* __restrict__ XTL,
            __half* __restrict__ VH)
{
    __shared__ __nv_bfloat16 sAh[128][40], sAl[128][40], sBh[128][40], sBl[128][40];
    const int tid = threadIdx.x, wid = tid >> 5, lane = tid & 31;
    const int b = blockIdx.z, my = blockIdx.y;
    const int n0 = blockIdx.x * 128;
    const __nv_bfloat16* xh = XTH + (size_t)b * WW * CH;
    const __nv_bfloat16* xl = XTL + (size_t)b * WW * CH;
    __half* vh = VH + (size_t)b * CH * WW;
    const int mw = wid & 1, nw = wid >> 1, mi = lane >> 3, row8 = lane & 7;
    const uint32_t aAh = smem_u32(sAh), aAl = smem_u32(sAl);
    const uint32_t aBh = smem_u32(sBh), aBl = smem_u32(sBl);

    float acc[4][4][4] = {};

    for (int kc = 0; kc < 8; kc++) {
        const int k0 = kc * 32;
        #pragma unroll
        for (int i2 = 0; i2 < 2; i2++) {
            int u = tid + 256 * i2;
            int r = u >> 2, c8 = (u & 3) * 8;
            *(uint4*)&sAh[r][c8] = *(const uint4*)(WVH + (size_t)(my * 128 + r) * CH + k0 + c8);
            *(uint4*)&sAl[r][c8] = *(const uint4*)(WVL + (size_t)(my * 128 + r) * CH + k0 + c8);
            *(uint4*)&sBh[r][c8] = *(const uint4*)(xh + (size_t)(n0 + r) * CH + k0 + c8);
            *(uint4*)&sBl[r][c8] = *(const uint4*)(xl + (size_t)(n0 + r) * CH + k0 + c8);
        }
        __syncthreads();
        #pragma unroll
        for (int kk = 0; kk < 2; kk++) {
            const int ks = kk * 16;
            uint32_t bh[8], bl[8];
            #pragma unroll
            for (int q = 0; q < 2; q++) {
                uint32_t off = (uint32_t)((nw * 32 + q * 16 + (mi >> 1) * 8 + row8) * 40
                                          + ks + (mi & 1) * 8) * 2;
                ldsm_x4(bh[q*4+0], bh[q*4+1], bh[q*4+2], bh[q*4+3], aBh + off);
                ldsm_x4(bl[q*4+0], bl[q*4+1], bl[q*4+2], bl[q*4+3], aBl + off);
            }
            uint32_t a[4][4];
            #pragma unroll
            for (int t = 0; t < 4; t++) {
                uint32_t off = (uint32_t)((mw * 64 + t * 16 + (mi & 1) * 8 + row8) * 40
                                          + ks + (mi >> 1) * 8) * 2;
                ldsm_x4(a[t][0], a[t][1], a[t][2], a[t][3], aAh + off);
            }
            #pragma unroll
            for (int t = 0; t < 4; t++)
                #pragma unroll
                for (int g = 0; g < 4; g++) {
                    mma_bf16(acc[t][g], a[t], &bh[g * 2]);
                    mma_bf16(acc[t][g], a[t], &bl[g * 2]);
                }
            #pragma unroll
            for (int t = 0; t < 4; t++) {
                uint32_t off = (uint32_t)((mw * 64 + t * 16 + (mi & 1) * 8 + row8) * 40
                                          + ks + (mi >> 1) * 8) * 2;
                ldsm_x4(a[t][0], a[t][1], a[t][2], a[t][3], aAl + off);
            }
            #pragma unroll
            for (int t = 0; t < 4; t++)
                #pragma unroll
                for (int g = 0; g < 4; g++)
                    mma_bf16(acc[t][g], a[t], &bh[g * 2]);
        }
        __syncthreads();
    }
    #pragma unroll
    for (int t = 0; t < 4; t++) {
        const int o = my * 128 + mw * 64 + t * 16 + (lane >> 2);
        const float b0 = BV[o], b8 = BV[o + 8];
        #pragma unroll
        for (int g = 0; g < 4; g++) {
            const int n = n0 + nw * 32 + g * 8 + (lane & 3) * 2;
            *(__half2*)&vh[(size_t)o * WW + n] =
                __floats2half2_rn(acc[t][g][0] + b0, acc[t][g][1] + b0);
            *(__half2*)&vh[(size_t)(o + 8) * WW + n] =
                __floats2half2_rn(acc[t][g][2] + b8, acc[t][g][3] + b8);
        }
    }
}

// ---------------------------------------------------------------------------
// Fused flash attention, all-fp16 single-term MMAs.
// CTA = (i-tile 128, channel-half 128, batch). 8 warps; warp owns 16 i-rows.
// j-tiles of 64 double-buffered, softmax in 32-j steps.
// ---------------------------------------------------------------------------
#define F_VOFF  5120                 // K tile bytes (64 x pitch40 fp16)
#define F_STG   23552                // + V tile (128 x pitch72 fp16)
#define F_Q     47104                // 2 stages
#define F_SMEM  69632                // >= max(F_Q + 10240, sO 67584)

__global__ __launch_bounds__(256, 2)
void fused_attn(const __half* __restrict__ QT, const __half* __restrict__ KT,
                const __half* __restrict__ VH,
                const float* __restrict__ X, const float* __restrict__ gamma,
                float* __restrict__ OUT)
{
    extern __shared__ char smem[];
    const uint32_t sbase = smem_u32(smem);
    const int tid = threadIdx.x, wid = tid >> 5, lane = tid & 31;
    const int mi = lane >> 3, row8 = lane & 7;
    const int i0 = blockIdx.x * 128;
    const int c0 = blockIdx.y * 128;
    const int b  = blockIdx.z;

    const __half* qg = QT + (size_t)b * WW * CQ;
    const __half* kg = KT + (size_t)b * WW * CQ;
    const __half* vhg = VH + (size_t)b * CH * WW + (size_t)c0 * WW;
    const float* xb = X + (size_t)b * CH * WW;
    float* ob = OUT + (size_t)b * CH * WW;

    // stage one 64-j tile: K^T fp16 (64x32, pitch 40) + V fp16 (128x64, pitch 72)
    auto stage = [&](int jt, int st) {
        const int j0 = jt * 64;
        const uint32_t sb = sbase + st * F_STG;
        {
            int r = tid >> 2, c8 = (tid & 3) * 8;
            cp16(sb + (uint32_t)(r * 40 + c8) * 2, kg + (size_t)(j0 + r) * CQ + c8);
        }
        #pragma unroll
        for (int it = 0; it < 4; it++) {
            int u = tid + 256 * it;                      // 0..1023 = 128x8 chunks
            int r = u >> 3, c8 = (u & 7) * 8;
            cp16(sb + F_VOFF + (uint32_t)(r * 72 + c8) * 2, vhg + (size_t)r * WW + j0 + c8);
        }
    };

    stage(0, 0);
    asm volatile("cp.async.commit_group;");

    // load q tile (plain stores)
    #pragma unroll
    for (int it = 0; it < 2; it++) {
        int u = tid + 256 * it;
        int r = u >> 2, c8 = (u & 3) * 8;
        *(uint4*)(smem + F_Q + (uint32_t)(r * 40 + c8) * 2) =
            *(const uint4*)(qg + (size_t)(i0 + r) * CQ + c8);
    }
    __syncthreads();

    // cache q fragments (loop-invariant)
    uint32_t qa[8];
    #pragma unroll
    for (int kk = 0; kk < 2; kk++) {
        const uint32_t offA = (uint32_t)((wid * 16 + (mi & 1) * 8 + row8) * 40
                                         + kk * 16 + (mi >> 1) * 8) * 2;
        ldsm_x4(qa[kk*4+0], qa[kk*4+1], qa[kk*4+2], qa[kk*4+3], sbase + F_Q + offA);
    }

    float o_[16][4] = {};
    float m0 = -1e30f, m1 = -1e30f, l0 = 0.f, l1 = 0.f;

    for (int jt = 0; jt < 32; jt++) {
        const int st = jt & 1;
        if (jt < 31) {
            stage(jt + 1, st ^ 1);
            asm volatile("cp.async.commit_group;");
            asm volatile("cp.async.wait_group 1;");
        } else {
            asm volatile("cp.async.wait_group 0;");
        }
        __syncthreads();

        const uint32_t aK = sbase + st * F_STG;
        const uint32_t aV = aK + F_VOFF;

        #pragma unroll
        for (int jh = 0; jh < 2; jh++) {
            // ---- scores for 32 j: single-term fp16 ----
            float s_[4][4] = {};
            #pragma unroll
            for (int kk = 0; kk < 2; kk++) {
                #pragma unroll
                for (int ntp = 0; ntp < 2; ntp++) {
                    uint32_t off = (uint32_t)((jh * 32 + ntp * 16 + (mi >> 1) * 8 + row8) * 40
                                              + kk * 16 + (mi & 1) * 8) * 2;
                    uint32_t bk[4];
                    ldsm_x4(bk[0], bk[1], bk[2], bk[3], aK + off);
                    mma_fp16(s_[2*ntp],   &qa[kk*4], &bk[0]);
                    mma_fp16(s_[2*ntp+1], &qa[kk*4], &bk[2]);
                }
            }

            // ---- online softmax (log2 domain) ----
            float ml0 = -1e30f, ml1 = -1e30f;
            #pragma unroll
            for (int nt = 0; nt < 4; nt++) {
                ml0 = fmaxf(ml0, fmaxf(s_[nt][0], s_[nt][1]));
                ml1 = fmaxf(ml1, fmaxf(s_[nt][2], s_[nt][3]));
            }
            ml0 = fmaxf(ml0, __shfl_xor_sync(0xffffffffu, ml0, 1));
            ml0 = fmaxf(ml0, __shfl_xor_sync(0xffffffffu, ml0, 2));
            ml1 = fmaxf(ml1, __shfl_xor_sync(0xffffffffu, ml1, 1));
            ml1 = fmaxf(ml1, __shfl_xor_sync(0xffffffffu, ml1, 2));
            const float mn0 = fmaxf(m0, ml0), mn1 = fmaxf(m1, ml1);
            const float sc0 = exp2f(m0 - mn0), sc1 = exp2f(m1 - mn1);
            m0 = mn0; m1 = mn1;

            float ls0 = 0.f, ls1 = 0.f;
            #pragma unroll
            for (int nt = 0; nt < 4; nt++) {
                s_[nt][0] = exp2f(s_[nt][0] - m0);
                s_[nt][1] = exp2f(s_[nt][1] - m0);
                s_[nt][2] = exp2f(s_[nt][2] - m1);
                s_[nt][3] = exp2f(s_[nt][3] - m1);
                ls0 += s_[nt][0] + s_[nt][1];
                ls1 += s_[nt][2] + s_[nt][3];
            }
            l0 = l0 * sc0 + ls0;
            l1 = l1 * sc1 + ls1;
            #pragma unroll
            for (int nt = 0; nt < 16; nt++) {
                o_[nt][0] *= sc0;  o_[nt][1] *= sc0;
                o_[nt][2] *= sc1;  o_[nt][3] *= sc1;
            }

            // ---- PV: O += P(fp16) V(fp16), single term ----
            #pragma unroll
            for (int ksl = 0; ksl < 2; ksl++) {
                const int ks = jh * 2 + ksl;
                uint32_t pa[4];
                pa[0] = packh2(s_[2*ksl][0],   s_[2*ksl][1]);
                pa[1] = packh2(s_[2*ksl][2],   s_[2*ksl][3]);
                pa[2] = packh2(s_[2*ksl+1][0], s_[2*ksl+1][1]);
                pa[3] = packh2(s_[2*ksl+1][2], s_[2*ksl+1][3]);
                #pragma unroll
                for (int ntp = 0; ntp < 8; ntp++) {
                    uint32_t off = (uint32_t)((ntp * 16 + (mi >> 1) * 8 + row8) * 72
                                              + ks * 16 + (mi & 1) * 8) * 2;
                    uint32_t bv[4];
                    ldsm_x4(bv[0], bv[1], bv[2], bv[3], aV + off);
                    mma_fp16(o_[2*ntp],   pa, &bv[0]);
                    mma_fp16(o_[2*ntp+1], pa, &bv[2]);
                }
            }
        }
        __syncthreads();
    }

    // ---- epilogue: normalize, bounce through smem to [c][i], +gamma/x ----
    l0 += __shfl_xor_sync(0xffffffffu, l0, 1);
    l0 += __shfl_xor_sync(0xffffffffu, l0, 2);
    l1 += __shfl_xor_sync(0xffffffffu, l1, 1);
    l1 += __shfl_xor_sync(0xffffffffu, l1, 2);
    const float inv0 = 1.f / l0, inv1 = 1.f / l1;

    float* sO = (float*)smem;            // [c 128][i 128] pitch 132
    const int rA = wid * 16 + (lane >> 2), rB = rA + 8;
    #pragma unroll
    for (int nt = 0; nt < 16; nt++) {
        const int c = nt * 8 + (lane & 3) * 2;
        sO[c * 132 + rA]       = o_[nt][0] * inv0;
        sO[(c + 1) * 132 + rA] = o_[nt][1] * inv0;
        sO[c * 132 + rB]       = o_[nt][2] * inv1;
        sO[(c + 1) * 132 + rB] = o_[nt][3] * inv1;
    }
    __syncthreads();

    const float g = gamma[0];
    #pragma unroll
    for (int it = 0; it < 16; it++) {
        int u = tid + 256 * it;               // 0..4095
        int r = u >> 5, c4 = (u & 31) * 4;
        float4 v4 = *(float4*)&sO[r * 132 + c4];
        size_t go = (size_t)(c0 + r) * WW + i0 + c4;
        float4 xv = *(const float4*)(xb + go);
        v4.x = g * v4.x + xv.x;
        v4.y = g * v4.y + xv.y;
        v4.z = g * v4.z + xv.z;
        v4.w = g * v4.w + xv.w;
        *(float4*)(ob + go) = v4;
    }
}

// ---------------------------------------------------------------------------
extern "C" void kernel_launch(void* const* d_in, const int* in_sizes, int n_in,
                              void* d_out, int out_size)
{
    const float* x     = (const float*)d_in[0];
    const float* wq    = (const float*)d_in[1];
    const float* bq    = (const float*)d_in[2];
    const float* wk    = (const float*)d_in[3];
    const float* bk    = (const float*)d_in[4];
    const float* wv    = (const float*)d_in[5];
    const float* bv    = (const float*)d_in[6];
    const float* gamma = (const float*)d_in[7];
    float* out = (float*)d_out;

    __half *vh, *qt, *kt;
    __nv_bfloat16 *xth, *xtl;
    __nv_bfloat16 *wqh, *wql, *wkh, *wkl, *wvh, *wvl;
    cudaGetSymbolAddress((void**)&vh, g_vh);
    cudaGetSymbolAddress((void**)&qt, g_qt);
    cudaGetSymbolAddress((void**)&kt, g_kt);
    cudaGetSymbolAddress((void**)&xth, g_xth);
    cudaGetSymbolAddress((void**)&xtl, g_xtl);
    cudaGetSymbolAddress((void**)&wqh, g_wqh);
    cudaGetSymbolAddress((void**)&wql, g_wql);
    cudaGetSymbolAddress((void**)&wkh, g_wkh);
    cudaGetSymbolAddress((void**)&wkl, g_wkl);
    cudaGetSymbolAddress((void**)&wvh, g_wvh);
    cudaGetSymbolAddress((void**)&wvl, g_wvl);

    // 1. split weights
    split_flat<<<CQ * CH / 256, 256>>>(wq, wqh, wql);
    split_flat<<<CQ * CH / 256, 256>>>(wk, wkh, wkl);
    split_flat<<<CH * CH / 256, 256>>>(wv, wvh, wvl);

    // 2. transpose + split x
    transpose_split_x<<<dim3(WW / 32, CH / 32, BATCH), 256>>>(x, xth, xtl);

    // 3. q/k projections (fp16 output; q pre-scaled by log2e)
    proj_qk<<<dim3(WW / 128, 2, BATCH), 256>>>(wqh, wql, wkh, wkl, bq, bk,
                                               xth, xtl, qt, kt);

    // 4. v projection (fp16 output)
    proj_v<<<dim3(WW / 128, CH / 128, BATCH), 256>>>(wvh, wvl, bv, xth, xtl, vh);

    // 5. fused attention (2 CTAs/SM)
    cudaFuncSetAttribute(fused_attn, cudaFuncAttributeMaxDynamicSharedMemorySize, F_SMEM);
    fused_attn<<<dim3(WW / 128, CH / 128, BATCH), 256, F_SMEM>>>(
        qt, kt, vh, x, gamma, out);
}

// round 10
// speedup vs baseline: 6.2170x; 1.0794x over previous
#include <cuda_runtime.h>
#include <cuda_bf16.h>
#include <cuda_fp16.h>
#include <cstdint>

// Problem constants
#define BATCH 16
#define CH    256
#define CQ    32
#define WW    2048

#define LOG2E 1.4426950408889634f

// ---------------------------------------------------------------------------
// Scratch (device globals: allocation-free per harness rules)
// ---------------------------------------------------------------------------
__device__ __half g_vh[(size_t)BATCH * CH * WW];                  // V fp16 [b][c][j]
__device__ __half g_qt[(size_t)BATCH * WW * CQ];                  // q^T fp16 [b][i][d] (pre-scaled log2e)
__device__ __half g_kt[(size_t)BATCH * WW * CQ];                  // k^T fp16
__device__ __half g_xt[(size_t)BATCH * WW * CH];                  // x^T fp16 [b][i][c]
__device__ __half g_wqh[CQ * CH], g_wql[CQ * CH];                 // weights fp16 hi/lo
__device__ __half g_wkh[CQ * CH], g_wkl[CQ * CH];
__device__ __half g_wvh[CH * CH], g_wvl[CH * CH];

// ---------------------------------------------------------------------------
// Helpers
// ---------------------------------------------------------------------------
__device__ __forceinline__ uint32_t smem_u32(const void* p) {
    uint32_t a;
    asm("{ .reg .u64 t; cvta.to.shared.u64 t, %1; cvt.u32.u64 %0, t; }" : "=r"(a) : "l"(p));
    return a;
}
__device__ __forceinline__ void ldsm_x4(uint32_t& r0, uint32_t& r1, uint32_t& r2, uint32_t& r3,
                                        uint32_t addr) {
    asm volatile("ldmatrix.sync.aligned.m8n8.x4.shared.b16 {%0,%1,%2,%3}, [%4];"
                 : "=r"(r0), "=r"(r1), "=r"(r2), "=r"(r3) : "r"(addr));
}
__device__ __forceinline__ void mma_fp16(float* c, const uint32_t* a, const uint32_t* b) {
    asm volatile(
        "mma.sync.aligned.m16n8k16.row.col.f32.f16.f16.f32 "
        "{%0,%1,%2,%3}, {%4,%5,%6,%7}, {%8,%9}, {%0,%1,%2,%3};"
        : "+f"(c[0]), "+f"(c[1]), "+f"(c[2]), "+f"(c[3])
        : "r"(a[0]), "r"(a[1]), "r"(a[2]), "r"(a[3]), "r"(b[0]), "r"(b[1]));
}
__device__ __forceinline__ void cp16(uint32_t dst, const void* src) {
    asm volatile("cp.async.ca.shared.global [%0], [%1], 16;" :: "r"(dst), "l"(src));
}
__device__ __forceinline__ void hsplit(float v, __half& h, __half& l) {
    h = __float2half(v);
    l = __float2half(v - __half2float(h));
}
__device__ __forceinline__ uint32_t packh2(float x, float y) {
    __half2 t = __floats2half2_rn(x, y);
    return *(uint32_t*)&t;
}

// ---------------------------------------------------------------------------
// Split fp32 -> fp16 hi/lo (weights)
// ---------------------------------------------------------------------------
__global__ __launch_bounds__(256)
void split_flat(const float* __restrict__ s, __half* __restrict__ h, __half* __restrict__ l)
{
    int i = blockIdx.x * 256 + threadIdx.x;
    __half hh, ll;
    hsplit(s[i], hh, ll);
    h[i] = hh; l[i] = ll;
}

// ---------------------------------------------------------------------------
// x [b][c][i] fp32 -> x^T [b][i][c] single fp16 (32x32 smem tiles)
// ---------------------------------------------------------------------------
__global__ __launch_bounds__(256)
void transpose_x(const float* __restrict__ X, __half* __restrict__ XT)
{
    __shared__ float t[32][33];
    const int b = blockIdx.z;
    const int i0 = blockIdx.x * 32, c0 = blockIdx.y * 32;
    const int tx = threadIdx.x & 31, ty = threadIdx.x >> 5;
    const float* xb = X + (size_t)b * CH * WW;
    #pragma unroll
    for (int r = 0; r < 4; r++)
        t[ty + r * 8][tx] = xb[(size_t)(c0 + ty + r * 8) * WW + i0 + tx];
    __syncthreads();
    __half* o = XT + (size_t)b * WW * CH;
    #pragma unroll
    for (int r = 0; r < 4; r++) {
        int i = ty + r * 8;
        o[(size_t)(i0 + i) * CH + c0 + tx] = __float2half(t[tx][i]);
    }
}

// ---------------------------------------------------------------------------
// Q/K projection (2-term fp16: wh.x + wl.x): qT[b][i][d] fp16
// Q output pre-scaled by log2e (softmax uses exp2).
// ---------------------------------------------------------------------------
__global__ __launch_bounds__(256)
void proj_qk(const __half* __restrict__ WHQ, const __half* __restrict__ WLQ,
             const __half* __restrict__ WHK, const __half* __restrict__ WLK,
             const float* __restrict__ BQ, const float* __restrict__ BK_,
             const __half* __restrict__ XT,
             __half* __restrict__ QT, __half* __restrict__ KT)
{
    __shared__ __half sAh[32][40], sAl[32][40], sB[128][40];
    __shared__ float sc[129][33];
    const int tid = threadIdx.x, wid = tid >> 5, lane = tid & 31;
    const int b = blockIdx.z;
    const int n0 = blockIdx.x * 128;
    const bool isK = blockIdx.y == 1;
    const __half* wh = isK ? WHK : WHQ;
    const __half* wl = isK ? WLK : WLQ;
    const float* bias = isK ? BK_ : BQ;
    const float oscale = isK ? 1.0f : LOG2E;
    __half* OT = (isK ? KT : QT) + (size_t)b * WW * CQ;
    const __half* xg = XT + (size_t)b * WW * CH;

    const int mw = wid & 1, nw = wid >> 1;
    const int mi = lane >> 3, row8 = lane & 7;
    const uint32_t aAh = smem_u32(sAh), aAl = smem_u32(sAl), aB = smem_u32(sB);

    float acc[4][4] = {};

    for (int kc = 0; kc < 8; kc++) {
        const int k0 = kc * 32;
        if (tid < 128) {
            int r = tid >> 2, c8 = (tid & 3) * 8;
            *(uint4*)&sAh[r][c8] = *(const uint4*)(wh + (size_t)r * CH + k0 + c8);
            *(uint4*)&sAl[r][c8] = *(const uint4*)(wl + (size_t)r * CH + k0 + c8);
        }
        #pragma unroll
        for (int i2 = 0; i2 < 2; i2++) {
            int u = tid + 256 * i2;
            int r = u >> 2, c8 = (u & 3) * 8;
            *(uint4*)&sB[r][c8] = *(const uint4*)(xg + (size_t)(n0 + r) * CH + k0 + c8);
        }
        __syncthreads();
        #pragma unroll
        for (int kk = 0; kk < 2; kk++) {
            const int ks = kk * 16;
            uint32_t bb[8];
            #pragma unroll
            for (int q = 0; q < 2; q++) {
                uint32_t off = (uint32_t)((nw * 32 + q * 16 + (mi >> 1) * 8 + row8) * 40
                                          + ks + (mi & 1) * 8) * 2;
                ldsm_x4(bb[q*4+0], bb[q*4+1], bb[q*4+2], bb[q*4+3], aB + off);
            }
            uint32_t a4[4];
            const uint32_t offA = (uint32_t)((mw * 16 + (mi & 1) * 8 + row8) * 40
                                             + ks + (mi >> 1) * 8) * 2;
            ldsm_x4(a4[0], a4[1], a4[2], a4[3], aAh + offA);
            #pragma unroll
            for (int g = 0; g < 4; g++)
                mma_fp16(acc[g], a4, &bb[g * 2]);
            ldsm_x4(a4[0], a4[1], a4[2], a4[3], aAl + offA);
            #pragma unroll
            for (int g = 0; g < 4; g++)
                mma_fp16(acc[g], a4, &bb[g * 2]);
        }
        __syncthreads();
    }
    const int m = mw * 16 + (lane >> 2);
    #pragma unroll
    for (int g = 0; g < 4; g++) {
        int n = nw * 32 + g * 8 + (lane & 3) * 2;
        sc[n][m]         = (acc[g][0] + bias[m]) * oscale;
        sc[n + 1][m]     = (acc[g][1] + bias[m]) * oscale;
        sc[n][m + 8]     = (acc[g][2] + bias[m + 8]) * oscale;
        sc[n + 1][m + 8] = (acc[g][3] + bias[m + 8]) * oscale;
    }
    __syncthreads();
    const int n = tid >> 1, half = (tid & 1) * 16;
    #pragma unroll
    for (int j = 0; j < 16; j += 2) {
        *(__half2*)&OT[(size_t)(n0 + n) * CQ + half + j] =
            __floats2half2_rn(sc[n][half + j], sc[n][half + j + 1]);
    }
}

// ---------------------------------------------------------------------------
// V projection (2-term fp16): v[b][o][i] = wv @ x + bv, fp16 out
// ---------------------------------------------------------------------------
__global__ __launch_bounds__(256)
void proj_v(const __half* __restrict__ WVH, const __half* __restrict__ WVL,
            const float* __restrict__ BV, const __half* __restrict__ XT,
            __half* __restrict__ VH)
{
    __shared__ __half sAh[128][40], sAl[128][40], sB[128][40];
    const int tid = threadIdx.x, wid = tid >> 5, lane = tid & 31;
    const int b = blockIdx.z, my = blockIdx.y;
    const int n0 = blockIdx.x * 128;
    const __half* xg = XT + (size_t)b * WW * CH;
    __half* vh = VH + (size_t)b * CH * WW;
    const int mw = wid & 1, nw = wid >> 1, mi = lane >> 3, row8 = lane & 7;
    const uint32_t aAh = smem_u32(sAh), aAl = smem_u32(sAl), aB = smem_u32(sB);

    float acc[4][4][4] = {};

    for (int kc = 0; kc < 8; kc++) {
        const int k0 = kc * 32;
        #pragma unroll
        for (int i2 = 0; i2 < 2; i2++) {
            int u = tid + 256 * i2;
            int r = u >> 2, c8 = (u & 3) * 8;
            *(uint4*)&sAh[r][c8] = *(const uint4*)(WVH + (size_t)(my * 128 + r) * CH + k0 + c8);
            *(uint4*)&sAl[r][c8] = *(const uint4*)(WVL + (size_t)(my * 128 + r) * CH + k0 + c8);
            *(uint4*)&sB[r][c8]  = *(const uint4*)(xg + (size_t)(n0 + r) * CH + k0 + c8);
        }
        __syncthreads();
        #pragma unroll
        for (int kk = 0; kk < 2; kk++) {
            const int ks = kk * 16;
            uint32_t bb[8];
            #pragma unroll
            for (int q = 0; q < 2; q++) {
                uint32_t off = (uint32_t)((nw * 32 + q * 16 + (mi >> 1) * 8 + row8) * 40
                                          + ks + (mi & 1) * 8) * 2;
                ldsm_x4(bb[q*4+0], bb[q*4+1], bb[q*4+2], bb[q*4+3], aB + off);
            }
            uint32_t a[4][4];
            #pragma unroll
            for (int t = 0; t < 4; t++) {
                uint32_t off = (uint32_t)((mw * 64 + t * 16 + (mi & 1) * 8 + row8) * 40
                                          + ks + (mi >> 1) * 8) * 2;
                ldsm_x4(a[t][0], a[t][1], a[t][2], a[t][3], aAh + off);
            }
            #pragma unroll
            for (int t = 0; t < 4; t++)
                #pragma unroll
                for (int g = 0; g < 4; g++)
                    mma_fp16(acc[t][g], a[t], &bb[g * 2]);
            #pragma unroll
            for (int t = 0; t < 4; t++) {
                uint32_t off = (uint32_t)((mw * 64 + t * 16 + (mi & 1) * 8 + row8) * 40
                                          + ks + (mi >> 1) * 8) * 2;
                ldsm_x4(a[t][0], a[t][1], a[t][2], a[t][3], aAl + off);
            }
            #pragma unroll
            for (int t = 0; t < 4; t++)
                #pragma unroll
                for (int g = 0; g < 4; g++)
                    mma_fp16(acc[t][g], a[t], &bb[g * 2]);
        }
        __syncthreads();
    }
    #pragma unroll
    for (int t = 0; t < 4; t++) {
        const int o = my * 128 + mw * 64 + t * 16 + (lane >> 2);
        const float b0 = BV[o], b8 = BV[o + 8];
        #pragma unroll
        for (int g = 0; g < 4; g++) {
            const int n = n0 + nw * 32 + g * 8 + (lane & 3) * 2;
            *(__half2*)&vh[(size_t)o * WW + n] =
                __floats2half2_rn(acc[t][g][0] + b0, acc[t][g][1] + b0);
            *(__half2*)&vh[(size_t)(o + 8) * WW + n] =
                __floats2half2_rn(acc[t][g][2] + b8, acc[t][g][3] + b8);
        }
    }
}

// ---------------------------------------------------------------------------
// Fused flash attention, all-fp16 single-term MMAs, softmax per 64-j tile.
// CTA = (i-tile 128, channel-half 128, batch). 8 warps; warp owns 16 i-rows.
// ---------------------------------------------------------------------------
#define F_VOFF  5120                 // K tile bytes (64 x pitch40 fp16)
#define F_STG   23552                // + V tile (128 x pitch72 fp16)
#define F_Q     47104                // 2 stages
#define F_SMEM  69632                // >= max(F_Q + 10240, sO 67584)

__global__ __launch_bounds__(256, 2)
void fused_attn(const __half* __restrict__ QT, const __half* __restrict__ KT,
                const __half* __restrict__ VH,
                const float* __restrict__ X, const float* __restrict__ gamma,
                float* __restrict__ OUT)
{
    extern __shared__ char smem[];
    const uint32_t sbase = smem_u32(smem);
    const int tid = threadIdx.x, wid = tid >> 5, lane = tid & 31;
    const int mi = lane >> 3, row8 = lane & 7;
    const int i0 = blockIdx.x * 128;
    const int c0 = blockIdx.y * 128;
    const int b  = blockIdx.z;

    const __half* qg = QT + (size_t)b * WW * CQ;
    const __half* kg = KT + (size_t)b * WW * CQ;
    const __half* vhg = VH + (size_t)b * CH * WW + (size_t)c0 * WW;
    const float* xb = X + (size_t)b * CH * WW;
    float* ob = OUT + (size_t)b * CH * WW;

    auto stage = [&](int jt, int st) {
        const int j0 = jt * 64;
        const uint32_t sb = sbase + st * F_STG;
        {
            int r = tid >> 2, c8 = (tid & 3) * 8;
            cp16(sb + (uint32_t)(r * 40 + c8) * 2, kg + (size_t)(j0 + r) * CQ + c8);
        }
        #pragma unroll
        for (int it = 0; it < 4; it++) {
            int u = tid + 256 * it;                      // 0..1023 = 128x8 chunks
            int r = u >> 3, c8 = (u & 7) * 8;
            cp16(sb + F_VOFF + (uint32_t)(r * 72 + c8) * 2, vhg + (size_t)r * WW + j0 + c8);
        }
    };

    stage(0, 0);
    asm volatile("cp.async.commit_group;");

    // load q tile (plain stores)
    #pragma unroll
    for (int it = 0; it < 2; it++) {
        int u = tid + 256 * it;
        int r = u >> 2, c8 = (u & 3) * 8;
        *(uint4*)(smem + F_Q + (uint32_t)(r * 40 + c8) * 2) =
            *(const uint4*)(qg + (size_t)(i0 + r) * CQ + c8);
    }
    __syncthreads();

    // cache q fragments (loop-invariant)
    uint32_t qa[8];
    #pragma unroll
    for (int kk = 0; kk < 2; kk++) {
        const uint32_t offA = (uint32_t)((wid * 16 + (mi & 1) * 8 + row8) * 40
                                         + kk * 16 + (mi >> 1) * 8) * 2;
        ldsm_x4(qa[kk*4+0], qa[kk*4+1], qa[kk*4+2], qa[kk*4+3], sbase + F_Q + offA);
    }

    float o_[16][4] = {};
    float m0 = -1e30f, m1 = -1e30f, l0 = 0.f, l1 = 0.f;

    for (int jt = 0; jt < 32; jt++) {
        const int st = jt & 1;
        if (jt < 31) {
            stage(jt + 1, st ^ 1);
            asm volatile("cp.async.commit_group;");
            asm volatile("cp.async.wait_group 1;");
        } else {
            asm volatile("cp.async.wait_group 0;");
        }
        __syncthreads();

        const uint32_t aK = sbase + st * F_STG;
        const uint32_t aV = aK + F_VOFF;

        // ---- scores for all 64 j: single-term fp16 ----
        float s_[8][4] = {};
        #pragma unroll
        for (int kk = 0; kk < 2; kk++) {
            #pragma unroll
            for (int ntp = 0; ntp < 4; ntp++) {
                uint32_t off = (uint32_t)((ntp * 16 + (mi >> 1) * 8 + row8) * 40
                                          + kk * 16 + (mi & 1) * 8) * 2;
                uint32_t bk[4];
                ldsm_x4(bk[0], bk[1], bk[2], bk[3], aK + off);
                mma_fp16(s_[2*ntp],   &qa[kk*4], &bk[0]);
                mma_fp16(s_[2*ntp+1], &qa[kk*4], &bk[2]);
            }
        }

        // ---- online softmax over 64 j (log2 domain) ----
        float ml0 = -1e30f, ml1 = -1e30f;
        #pragma unroll
        for (int nt = 0; nt < 8; nt++) {
            ml0 = fmaxf(ml0, fmaxf(s_[nt][0], s_[nt][1]));
            ml1 = fmaxf(ml1, fmaxf(s_[nt][2], s_[nt][3]));
        }
        ml0 = fmaxf(ml0, __shfl_xor_sync(0xffffffffu, ml0, 1));
        ml0 = fmaxf(ml0, __shfl_xor_sync(0xffffffffu, ml0, 2));
        ml1 = fmaxf(ml1, __shfl_xor_sync(0xffffffffu, ml1, 1));
        ml1 = fmaxf(ml1, __shfl_xor_sync(0xffffffffu, ml1, 2));
        const float mn0 = fmaxf(m0, ml0), mn1 = fmaxf(m1, ml1);
        const float sc0 = exp2f(m0 - mn0), sc1 = exp2f(m1 - mn1);
        m0 = mn0; m1 = mn1;

        float ls0 = 0.f, ls1 = 0.f;
        #pragma unroll
        for (int nt = 0; nt < 8; nt++) {
            s_[nt][0] = exp2f(s_[nt][0] - m0);
            s_[nt][1] = exp2f(s_[nt][1] - m0);
            s_[nt][2] = exp2f(s_[nt][2] - m1);
            s_[nt][3] = exp2f(s_[nt][3] - m1);
            ls0 += s_[nt][0] + s_[nt][1];
            ls1 += s_[nt][2] + s_[nt][3];
        }
        l0 = l0 * sc0 + ls0;
        l1 = l1 * sc1 + ls1;
        #pragma unroll
        for (int nt = 0; nt < 16; nt++) {
            o_[nt][0] *= sc0;  o_[nt][1] *= sc0;
            o_[nt][2] *= sc1;  o_[nt][3] *= sc1;
        }

        // ---- PV: O += P(fp16) V(fp16), single term, 4 k-steps ----
        #pragma unroll
        for (int ks = 0; ks < 4; ks++) {
            uint32_t pa[4];
            pa[0] = packh2(s_[2*ks][0],   s_[2*ks][1]);
            pa[1] = packh2(s_[2*ks][2],   s_[2*ks][3]);
            pa[2] = packh2(s_[2*ks+1][0], s_[2*ks+1][1]);
            pa[3] = packh2(s_[2*ks+1][2], s_[2*ks+1][3]);
            #pragma unroll
            for (int ntp = 0; ntp < 8; ntp++) {
                uint32_t off = (uint32_t)((ntp * 16 + (mi >> 1) * 8 + row8) * 72
                                          + ks * 16 + (mi & 1) * 8) * 2;
                uint32_t bv[4];
                ldsm_x4(bv[0], bv[1], bv[2], bv[3], aV + off);
                mma_fp16(o_[2*ntp],   pa, &bv[0]);
                mma_fp16(o_[2*ntp+1], pa, &bv[2]);
            }
        }
        __syncthreads();
    }

    // ---- epilogue: normalize, bounce through smem to [c][i], +gamma/x ----
    l0 += __shfl_xor_sync(0xffffffffu, l0, 1);
    l0 += __shfl_xor_sync(0xffffffffu, l0, 2);
    l1 += __shfl_xor_sync(0xffffffffu, l1, 1);
    l1 += __shfl_xor_sync(0xffffffffu, l1, 2);
    const float inv0 = 1.f / l0, inv1 = 1.f / l1;

    float* sO = (float*)smem;            // [c 128][i 128] pitch 132
    const int rA = wid * 16 + (lane >> 2), rB = rA + 8;
    #pragma unroll
    for (int nt = 0; nt < 16; nt++) {
        const int c = nt * 8 + (lane & 3) * 2;
        sO[c * 132 + rA]       = o_[nt][0] * inv0;
        sO[(c + 1) * 132 + rA] = o_[nt][1] * inv0;
        sO[c * 132 + rB]       = o_[nt][2] * inv1;
        sO[(c + 1) * 132 + rB] = o_[nt][3] * inv1;
    }
    __syncthreads();

    const float g = gamma[0];
    #pragma unroll
    for (int it = 0; it < 16; it++) {
        int u = tid + 256 * it;               // 0..4095
        int r = u >> 5, c4 = (u & 31) * 4;
        float4 v4 = *(float4*)&sO[r * 132 + c4];
        size_t go = (size_t)(c0 + r) * WW + i0 + c4;
        float4 xv = *(const float4*)(xb + go);
        v4.x = g * v4.x + xv.x;
        v4.y = g * v4.y + xv.y;
        v4.z = g * v4.z + xv.z;
        v4.w = g * v4.w + xv.w;
        *(float4*)(ob + go) = v4;
    }
}

// ---------------------------------------------------------------------------
extern "C" void kernel_launch(void* const* d_in, const int* in_sizes, int n_in,
                              void* d_out, int out_size)
{
    const float* x     = (const float*)d_in[0];
    const float* wq    = (const float*)d_in[1];
    const float* bq    = (const float*)d_in[2];
    const float* wk    = (const float*)d_in[3];
    const float* bk    = (const float*)d_in[4];
    const float* wv    = (const float*)d_in[5];
    const float* bv    = (const float*)d_in[6];
    const float* gamma = (const float*)d_in[7];
    float* out = (float*)d_out;

    __half *vh, *qt, *kt, *xt;
    __half *wqh, *wql, *wkh, *wkl, *wvh, *wvl;
    cudaGetSymbolAddress((void**)&vh, g_vh);
    cudaGetSymbolAddress((void**)&qt, g_qt);
    cudaGetSymbolAddress((void**)&kt, g_kt);
    cudaGetSymbolAddress((void**)&xt, g_xt);
    cudaGetSymbolAddress((void**)&wqh, g_wqh);
    cudaGetSymbolAddress((void**)&wql, g_wql);
    cudaGetSymbolAddress((void**)&wkh, g_wkh);
    cudaGetSymbolAddress((void**)&wkl, g_wkl);
    cudaGetSymbolAddress((void**)&wvh, g_wvh);
    cudaGetSymbolAddress((void**)&wvl, g_wvl);

    // 1. split weights (fp16 hi/lo)
    split_flat<<<CQ * CH / 256, 256>>>(wq, wqh, wql);
    split_flat<<<CQ * CH / 256, 256>>>(wk, wkh, wkl);
    split_flat<<<CH * CH / 256, 256>>>(wv, wvh, wvl);

    // 2. transpose x -> single fp16 x^T
    transpose_x<<<dim3(WW / 32, CH / 32, BATCH), 256>>>(x, xt);

    // 3. q/k projections (fp16 output; q pre-scaled by log2e)
    proj_qk<<<dim3(WW / 128, 2, BATCH), 256>>>(wqh, wql, wkh, wkl, bq, bk, xt, qt, kt);

    // 4. v projection (fp16 output)
    proj_v<<<dim3(WW / 128, CH / 128, BATCH), 256>>>(wvh, wvl, bv, xt, vh);

    // 5. fused attention (2 CTAs/SM)
    cudaFuncSetAttribute(fused_attn, cudaFuncAttributeMaxDynamicSharedMemorySize, F_SMEM);
    fused_attn<<<dim3(WW / 128, CH / 128, BATCH), 256, F_SMEM>>>(
        qt, kt, vh, x, gamma, out);
}

// round 11
// speedup vs baseline: 6.4731x; 1.0412x over previous
#include <cuda_runtime.h>
#include <cuda_bf16.h>
#include <cuda_fp16.h>
#include <cstdint>

// Problem constants
#define BATCH 16
#define CH    256
#define CQ    32
#define WW    2048

#define LOG2E 1.4426950408889634f

// ---------------------------------------------------------------------------
// Scratch (device globals: allocation-free per harness rules)
// ---------------------------------------------------------------------------
__device__ __half g_vh[(size_t)BATCH * CH * WW];                  // V fp16 [b][c][j]
__device__ __half g_qt[(size_t)BATCH * WW * CQ];                  // q^T fp16 [b][i][d] (pre-scaled log2e)
__device__ __half g_kt[(size_t)BATCH * WW * CQ];                  // k^T fp16
__device__ __half g_xt[(size_t)BATCH * WW * CH];                  // x^T fp16 [b][i][c]
__device__ __half g_wq[CQ * CH];                                  // weights single fp16
__device__ __half g_wk[CQ * CH];
__device__ __half g_wv[CH * CH];

// ---------------------------------------------------------------------------
// Helpers
// ---------------------------------------------------------------------------
__device__ __forceinline__ uint32_t smem_u32(const void* p) {
    uint32_t a;
    asm("{ .reg .u64 t; cvta.to.shared.u64 t, %1; cvt.u32.u64 %0, t; }" : "=r"(a) : "l"(p));
    return a;
}
__device__ __forceinline__ void ldsm_x4(uint32_t& r0, uint32_t& r1, uint32_t& r2, uint32_t& r3,
                                        uint32_t addr) {
    asm volatile("ldmatrix.sync.aligned.m8n8.x4.shared.b16 {%0,%1,%2,%3}, [%4];"
                 : "=r"(r0), "=r"(r1), "=r"(r2), "=r"(r3) : "r"(addr));
}
__device__ __forceinline__ void mma_fp16(float* c, const uint32_t* a, const uint32_t* b) {
    asm volatile(
        "mma.sync.aligned.m16n8k16.row.col.f32.f16.f16.f32 "
        "{%0,%1,%2,%3}, {%4,%5,%6,%7}, {%8,%9}, {%0,%1,%2,%3};"
        : "+f"(c[0]), "+f"(c[1]), "+f"(c[2]), "+f"(c[3])
        : "r"(a[0]), "r"(a[1]), "r"(a[2]), "r"(a[3]), "r"(b[0]), "r"(b[1]));
}
__device__ __forceinline__ void cp16(uint32_t dst, const void* src) {
    asm volatile("cp.async.ca.shared.global [%0], [%1], 16;" :: "r"(dst), "l"(src));
}
__device__ __forceinline__ uint32_t packh2(float x, float y) {
    __half2 t = __floats2half2_rn(x, y);
    return *(uint32_t*)&t;
}
__device__ __forceinline__ float ex2(float x) {
    float y;
    asm("ex2.approx.f32 %0, %1;" : "=f"(y) : "f"(x));
    return y;
}

// ---------------------------------------------------------------------------
// Convert fp32 -> single fp16 (weights)
// ---------------------------------------------------------------------------
__global__ __launch_bounds__(256)
void convert_flat(const float* __restrict__ s, __half* __restrict__ h)
{
    int i = blockIdx.x * 256 + threadIdx.x;
    h[i] = __float2half(s[i]);
}

// ---------------------------------------------------------------------------
// x [b][c][i] fp32 -> x^T [b][i][c] single fp16 (32x32 smem tiles)
// ---------------------------------------------------------------------------
__global__ __launch_bounds__(256)
void transpose_x(const float* __restrict__ X, __half* __restrict__ XT)
{
    __shared__ float t[32][33];
    const int b = blockIdx.z;
    const int i0 = blockIdx.x * 32, c0 = blockIdx.y * 32;
    const int tx = threadIdx.x & 31, ty = threadIdx.x >> 5;
    const float* xb = X + (size_t)b * CH * WW;
    #pragma unroll
    for (int r = 0; r < 4; r++)
        t[ty + r * 8][tx] = xb[(size_t)(c0 + ty + r * 8) * WW + i0 + tx];
    __syncthreads();
    __half* o = XT + (size_t)b * WW * CH;
    #pragma unroll
    for (int r = 0; r < 4; r++) {
        int i = ty + r * 8;
        o[(size_t)(i0 + i) * CH + c0 + tx] = __float2half(t[tx][i]);
    }
}

// ---------------------------------------------------------------------------
// Q/K projection (single-term fp16): qT[b][i][d] fp16
// Q output pre-scaled by log2e (softmax uses exp2).
// ---------------------------------------------------------------------------
__global__ __launch_bounds__(256)
void proj_qk(const __half* __restrict__ WQ, const __half* __restrict__ WK,
             const float* __restrict__ BQ, const float* __restrict__ BK_,
             const __half* __restrict__ XT,
             __half* __restrict__ QT, __half* __restrict__ KT)
{
    __shared__ __half sA[32][40], sB[128][40];
    __shared__ float sc[129][33];
    const int tid = threadIdx.x, wid = tid >> 5, lane = tid & 31;
    const int b = blockIdx.z;
    const int n0 = blockIdx.x * 128;
    const bool isK = blockIdx.y == 1;
    const __half* w = isK ? WK : WQ;
    const float* bias = isK ? BK_ : BQ;
    const float oscale = isK ? 1.0f : LOG2E;
    __half* OT = (isK ? KT : QT) + (size_t)b * WW * CQ;
    const __half* xg = XT + (size_t)b * WW * CH;

    const int mw = wid & 1, nw = wid >> 1;
    const int mi = lane >> 3, row8 = lane & 7;
    const uint32_t aA = smem_u32(sA), aB = smem_u32(sB);

    float acc[4][4] = {};

    for (int kc = 0; kc < 8; kc++) {
        const int k0 = kc * 32;
        if (tid < 128) {
            int r = tid >> 2, c8 = (tid & 3) * 8;
            *(uint4*)&sA[r][c8] = *(const uint4*)(w + (size_t)r * CH + k0 + c8);
        }
        #pragma unroll
        for (int i2 = 0; i2 < 2; i2++) {
            int u = tid + 256 * i2;
            int r = u >> 2, c8 = (u & 3) * 8;
            *(uint4*)&sB[r][c8] = *(const uint4*)(xg + (size_t)(n0 + r) * CH + k0 + c8);
        }
        __syncthreads();
        #pragma unroll
        for (int kk = 0; kk < 2; kk++) {
            const int ks = kk * 16;
            uint32_t bb[8];
            #pragma unroll
            for (int q = 0; q < 2; q++) {
                uint32_t off = (uint32_t)((nw * 32 + q * 16 + (mi >> 1) * 8 + row8) * 40
                                          + ks + (mi & 1) * 8) * 2;
                ldsm_x4(bb[q*4+0], bb[q*4+1], bb[q*4+2], bb[q*4+3], aB + off);
            }
            uint32_t a4[4];
            const uint32_t offA = (uint32_t)((mw * 16 + (mi & 1) * 8 + row8) * 40
                                             + ks + (mi >> 1) * 8) * 2;
            ldsm_x4(a4[0], a4[1], a4[2], a4[3], aA + offA);
            #pragma unroll
            for (int g = 0; g < 4; g++)
                mma_fp16(acc[g], a4, &bb[g * 2]);
        }
        __syncthreads();
    }
    const int m = mw * 16 + (lane >> 2);
    #pragma unroll
    for (int g = 0; g < 4; g++) {
        int n = nw * 32 + g * 8 + (lane & 3) * 2;
        sc[n][m]         = (acc[g][0] + bias[m]) * oscale;
        sc[n + 1][m]     = (acc[g][1] + bias[m]) * oscale;
        sc[n][m + 8]     = (acc[g][2] + bias[m + 8]) * oscale;
        sc[n + 1][m + 8] = (acc[g][3] + bias[m + 8]) * oscale;
    }
    __syncthreads();
    const int n = tid >> 1, half = (tid & 1) * 16;
    #pragma unroll
    for (int j = 0; j < 16; j += 2) {
        *(__half2*)&OT[(size_t)(n0 + n) * CQ + half + j] =
            __floats2half2_rn(sc[n][half + j], sc[n][half + j + 1]);
    }
}

// ---------------------------------------------------------------------------
// V projection (single-term fp16): v[b][o][i] = wv @ x + bv, fp16 out
// ---------------------------------------------------------------------------
__global__ __launch_bounds__(256)
void proj_v(const __half* __restrict__ WV, const float* __restrict__ BV,
            const __half* __restrict__ XT, __half* __restrict__ VH)
{
    __shared__ __half sA[128][40], sB[128][40];
    const int tid = threadIdx.x, wid = tid >> 5, lane = tid & 31;
    const int b = blockIdx.z, my = blockIdx.y;
    const int n0 = blockIdx.x * 128;
    const __half* xg = XT + (size_t)b * WW * CH;
    __half* vh = VH + (size_t)b * CH * WW;
    const int mw = wid & 1, nw = wid >> 1, mi = lane >> 3, row8 = lane & 7;
    const uint32_t aA = smem_u32(sA), aB = smem_u32(sB);

    float acc[4][4][4] = {};

    for (int kc = 0; kc < 8; kc++) {
        const int k0 = kc * 32;
        #pragma unroll
        for (int i2 = 0; i2 < 2; i2++) {
            int u = tid + 256 * i2;
            int r = u >> 2, c8 = (u & 3) * 8;
            *(uint4*)&sA[r][c8] = *(const uint4*)(WV + (size_t)(my * 128 + r) * CH + k0 + c8);
            *(uint4*)&sB[r][c8] = *(const uint4*)(xg + (size_t)(n0 + r) * CH + k0 + c8);
        }
        __syncthreads();
        #pragma unroll
        for (int kk = 0; kk < 2; kk++) {
            const int ks = kk * 16;
            uint32_t bb[8];
            #pragma unroll
            for (int q = 0; q < 2; q++) {
                uint32_t off = (uint32_t)((nw * 32 + q * 16 + (mi >> 1) * 8 + row8) * 40
                                          + ks + (mi & 1) * 8) * 2;
                ldsm_x4(bb[q*4+0], bb[q*4+1], bb[q*4+2], bb[q*4+3], aB + off);
            }
            uint32_t a[4][4];
            #pragma unroll
            for (int t = 0; t < 4; t++) {
                uint32_t off = (uint32_t)((mw * 64 + t * 16 + (mi & 1) * 8 + row8) * 40
                                          + ks + (mi >> 1) * 8) * 2;
                ldsm_x4(a[t][0], a[t][1], a[t][2], a[t][3], aA + off);
            }
            #pragma unroll
            for (int t = 0; t < 4; t++)
                #pragma unroll
                for (int g = 0; g < 4; g++)
                    mma_fp16(acc[t][g], a[t], &bb[g * 2]);
        }
        __syncthreads();
    }
    #pragma unroll
    for (int t = 0; t < 4; t++) {
        const int o = my * 128 + mw * 64 + t * 16 + (lane >> 2);
        const float b0 = BV[o], b8 = BV[o + 8];
        #pragma unroll
        for (int g = 0; g < 4; g++) {
            const int n = n0 + nw * 32 + g * 8 + (lane & 3) * 2;
            *(__half2*)&vh[(size_t)o * WW + n] =
                __floats2half2_rn(acc[t][g][0] + b0, acc[t][g][1] + b0);
            *(__half2*)&vh[(size_t)(o + 8) * WW + n] =
                __floats2half2_rn(acc[t][g][2] + b8, acc[t][g][3] + b8);
        }
    }
}

// ---------------------------------------------------------------------------
// Fused flash attention, all-fp16 single-term MMAs, softmax per 64-j tile,
// ex2.approx softmax, warp-uniform rescale skip.
// CTA = (i-tile 128, channel-half 128, batch). 8 warps; warp owns 16 i-rows.
// ---------------------------------------------------------------------------
#define F_VOFF  5120                 // K tile bytes (64 x pitch40 fp16)
#define F_STG   23552                // + V tile (128 x pitch72 fp16)
#define F_Q     47104                // 2 stages
#define F_SMEM  69632                // >= max(F_Q + 10240, sO 67584)

__global__ __launch_bounds__(256, 2)
void fused_attn(const __half* __restrict__ QT, const __half* __restrict__ KT,
                const __half* __restrict__ VH,
                const float* __restrict__ X, const float* __restrict__ gamma,
                float* __restrict__ OUT)
{
    extern __shared__ char smem[];
    const uint32_t sbase = smem_u32(smem);
    const int tid = threadIdx.x, wid = tid >> 5, lane = tid & 31;
    const int mi = lane >> 3, row8 = lane & 7;
    const int i0 = blockIdx.x * 128;
    const int c0 = blockIdx.y * 128;
    const int b  = blockIdx.z;

    const __half* qg = QT + (size_t)b * WW * CQ;
    const __half* kg = KT + (size_t)b * WW * CQ;
    const __half* vhg = VH + (size_t)b * CH * WW + (size_t)c0 * WW;
    const float* xb = X + (size_t)b * CH * WW;
    float* ob = OUT + (size_t)b * CH * WW;

    auto stage = [&](int jt, int st) {
        const int j0 = jt * 64;
        const uint32_t sb = sbase + st * F_STG;
        {
            int r = tid >> 2, c8 = (tid & 3) * 8;
            cp16(sb + (uint32_t)(r * 40 + c8) * 2, kg + (size_t)(j0 + r) * CQ + c8);
        }
        #pragma unroll
        for (int it = 0; it < 4; it++) {
            int u = tid + 256 * it;                      // 0..1023 = 128x8 chunks
            int r = u >> 3, c8 = (u & 7) * 8;
            cp16(sb + F_VOFF + (uint32_t)(r * 72 + c8) * 2, vhg + (size_t)r * WW + j0 + c8);
        }
    };

    stage(0, 0);
    asm volatile("cp.async.commit_group;");

    // load q tile (plain stores)
    #pragma unroll
    for (int it = 0; it < 2; it++) {
        int u = tid + 256 * it;
        int r = u >> 2, c8 = (u & 3) * 8;
        *(uint4*)(smem + F_Q + (uint32_t)(r * 40 + c8) * 2) =
            *(const uint4*)(qg + (size_t)(i0 + r) * CQ + c8);
    }
    __syncthreads();

    // cache q fragments (loop-invariant)
    uint32_t qa[8];
    #pragma unroll
    for (int kk = 0; kk < 2; kk++) {
        const uint32_t offA = (uint32_t)((wid * 16 + (mi & 1) * 8 + row8) * 40
                                         + kk * 16 + (mi >> 1) * 8) * 2;
        ldsm_x4(qa[kk*4+0], qa[kk*4+1], qa[kk*4+2], qa[kk*4+3], sbase + F_Q + offA);
    }

    float o_[16][4] = {};
    float m0 = -1e30f, m1 = -1e30f, l0 = 0.f, l1 = 0.f;

    for (int jt = 0; jt < 32; jt++) {
        const int st = jt & 1;
        if (jt < 31) {
            stage(jt + 1, st ^ 1);
            asm volatile("cp.async.commit_group;");
            asm volatile("cp.async.wait_group 1;");
        } else {
            asm volatile("cp.async.wait_group 0;");
        }
        __syncthreads();

        const uint32_t aK = sbase + st * F_STG;
        const uint32_t aV = aK + F_VOFF;

        // ---- scores for all 64 j: single-term fp16 ----
        float s_[8][4] = {};
        #pragma unroll
        for (int kk = 0; kk < 2; kk++) {
            #pragma unroll
            for (int ntp = 0; ntp < 4; ntp++) {
                uint32_t off = (uint32_t)((ntp * 16 + (mi >> 1) * 8 + row8) * 40
                                          + kk * 16 + (mi & 1) * 8) * 2;
                uint32_t bk[4];
                ldsm_x4(bk[0], bk[1], bk[2], bk[3], aK + off);
                mma_fp16(s_[2*ntp],   &qa[kk*4], &bk[0]);
                mma_fp16(s_[2*ntp+1], &qa[kk*4], &bk[2]);
            }
        }

        // ---- online softmax over 64 j (log2 domain, ex2.approx) ----
        float ml0 = -1e30f, ml1 = -1e30f;
        #pragma unroll
        for (int nt = 0; nt < 8; nt++) {
            ml0 = fmaxf(ml0, fmaxf(s_[nt][0], s_[nt][1]));
            ml1 = fmaxf(ml1, fmaxf(s_[nt][2], s_[nt][3]));
        }
        ml0 = fmaxf(ml0, __shfl_xor_sync(0xffffffffu, ml0, 1));
        ml0 = fmaxf(ml0, __shfl_xor_sync(0xffffffffu, ml0, 2));
        ml1 = fmaxf(ml1, __shfl_xor_sync(0xffffffffu, ml1, 1));
        ml1 = fmaxf(ml1, __shfl_xor_sync(0xffffffffu, ml1, 2));
        const float mn0 = fmaxf(m0, ml0), mn1 = fmaxf(m1, ml1);
        const bool nochg = __all_sync(0xffffffffu, (mn0 == m0) && (mn1 == m1));

        float ls0 = 0.f, ls1 = 0.f;
        #pragma unroll
        for (int nt = 0; nt < 8; nt++) {
            s_[nt][0] = ex2(s_[nt][0] - mn0);
            s_[nt][1] = ex2(s_[nt][1] - mn0);
            s_[nt][2] = ex2(s_[nt][2] - mn1);
            s_[nt][3] = ex2(s_[nt][3] - mn1);
            ls0 += s_[nt][0] + s_[nt][1];
            ls1 += s_[nt][2] + s_[nt][3];
        }

        if (nochg) {
            l0 += ls0;
            l1 += ls1;
        } else {
            const float sc0 = ex2(m0 - mn0), sc1 = ex2(m1 - mn1);
            l0 = l0 * sc0 + ls0;
            l1 = l1 * sc1 + ls1;
            #pragma unroll
            for (int nt = 0; nt < 16; nt++) {
                o_[nt][0] *= sc0;  o_[nt][1] *= sc0;
                o_[nt][2] *= sc1;  o_[nt][3] *= sc1;
            }
        }
        m0 = mn0; m1 = mn1;

        // ---- PV: O += P(fp16) V(fp16), single term, 4 k-steps ----
        #pragma unroll
        for (int ks = 0; ks < 4; ks++) {
            uint32_t pa[4];
            pa[0] = packh2(s_[2*ks][0],   s_[2*ks][1]);
            pa[1] = packh2(s_[2*ks][2],   s_[2*ks][3]);
            pa[2] = packh2(s_[2*ks+1][0], s_[2*ks+1][1]);
            pa[3] = packh2(s_[2*ks+1][2], s_[2*ks+1][3]);
            #pragma unroll
            for (int ntp = 0; ntp < 8; ntp++) {
                uint32_t off = (uint32_t)((ntp * 16 + (mi >> 1) * 8 + row8) * 72
                                          + ks * 16 + (mi & 1) * 8) * 2;
                uint32_t bv[4];
                ldsm_x4(bv[0], bv[1], bv[2], bv[3], aV + off);
                mma_fp16(o_[2*ntp],   pa, &bv[0]);
                mma_fp16(o_[2*ntp+1], pa, &bv[2]);
            }
        }
        __syncthreads();
    }

    // ---- epilogue: normalize, bounce through smem to [c][i], +gamma/x ----
    l0 += __shfl_xor_sync(0xffffffffu, l0, 1);
    l0 += __shfl_xor_sync(0xffffffffu, l0, 2);
    l1 += __shfl_xor_sync(0xffffffffu, l1, 1);
    l1 += __shfl_xor_sync(0xffffffffu, l1, 2);
    const float inv0 = 1.f / l0, inv1 = 1.f / l1;

    float* sO = (float*)smem;            // [c 128][i 128] pitch 132
    const int rA = wid * 16 + (lane >> 2), rB = rA + 8;
    #pragma unroll
    for (int nt = 0; nt < 16; nt++) {
        const int c = nt * 8 + (lane & 3) * 2;
        sO[c * 132 + rA]       = o_[nt][0] * inv0;
        sO[(c + 1) * 132 + rA] = o_[nt][1] * inv0;
        sO[c * 132 + rB]       = o_[nt][2] * inv1;
        sO[(c + 1) * 132 + rB] = o_[nt][3] * inv1;
    }
    __syncthreads();

    const float g = gamma[0];
    #pragma unroll
    for (int it = 0; it < 16; it++) {
        int u = tid + 256 * it;               // 0..4095
        int r = u >> 5, c4 = (u & 31) * 4;
        float4 v4 = *(float4*)&sO[r * 132 + c4];
        size_t go = (size_t)(c0 + r) * WW + i0 + c4;
        float4 xv = *(const float4*)(xb + go);
        v4.x = g * v4.x + xv.x;
        v4.y = g * v4.y + xv.y;
        v4.z = g * v4.z + xv.z;
        v4.w = g * v4.w + xv.w;
        *(float4*)(ob + go) = v4;
    }
}

// ---------------------------------------------------------------------------
extern "C" void kernel_launch(void* const* d_in, const int* in_sizes, int n_in,
                              void* d_out, int out_size)
{
    const float* x     = (const float*)d_in[0];
    const float* wq    = (const float*)d_in[1];
    const float* bq    = (const float*)d_in[2];
    const float* wk    = (const float*)d_in[3];
    const float* bk    = (const float*)d_in[4];
    const float* wv    = (const float*)d_in[5];
    const float* bv    = (const float*)d_in[6];
    const float* gamma = (const float*)d_in[7];
    float* out = (float*)d_out;

    __half *vh, *qt, *kt, *xt, *wqd, *wkd, *wvd;
    cudaGetSymbolAddress((void**)&vh, g_vh);
    cudaGetSymbolAddress((void**)&qt, g_qt);
    cudaGetSymbolAddress((void**)&kt, g_kt);
    cudaGetSymbolAddress((void**)&xt, g_xt);
    cudaGetSymbolAddress((void**)&wqd, g_wq);
    cudaGetSymbolAddress((void**)&wkd, g_wk);
    cudaGetSymbolAddress((void**)&wvd, g_wv);

    // 1. convert weights to fp16
    convert_flat<<<CQ * CH / 256, 256>>>(wq, wqd);
    convert_flat<<<CQ * CH / 256, 256>>>(wk, wkd);
    convert_flat<<<CH * CH / 256, 256>>>(wv, wvd);

    // 2. transpose x -> single fp16 x^T
    transpose_x<<<dim3(WW / 32, CH / 32, BATCH), 256>>>(x, xt);

    // 3. q/k projections (fp16 output; q pre-scaled by log2e)
    proj_qk<<<dim3(WW / 128, 2, BATCH), 256>>>(wqd, wkd, bq, bk, xt, qt, kt);

    // 4. v projection (fp16 output)
    proj_v<<<dim3(WW / 128, CH / 128, BATCH), 256>>>(wvd, bv, xt, vh);

    // 5. fused attention (2 CTAs/SM)
    cudaFuncSetAttribute(fused_attn, cudaFuncAttributeMaxDynamicSharedMemorySize, F_SMEM);
    fused_attn<<<dim3(WW / 128, CH / 128, BATCH), 256, F_SMEM>>>(
        qt, kt, vh, x, gamma, out);
}